// round 2
// baseline (speedup 1.0000x reference)
#include <cuda_runtime.h>
#include <cuda_bf16.h>
#include <math.h>

// Problem constants
#define LAYERS 2
#define D 512
#define H 8
#define DH 64
#define MFF 2048
#define O0 132
#define O1 3
#define BB 2
#define TT 2048
#define ROWS (BB*TT)          // 4096
#define EPS 1e-5f

// ---------------------------------------------------------------------------
// Scratch (device globals; no runtime allocation allowed)
// ---------------------------------------------------------------------------
__device__ float g_x  [ROWS * D];        // running residual stream
__device__ float g_h  [ROWS * D];        // LN output
__device__ float g_qkv[ROWS * 3 * H * DH];
__device__ float g_o  [ROWS * D];        // attention output (b,t,H*DH)
__device__ float g_mid[ROWS * MFF];      // FFN / regressor hidden
__device__ float g_cat[ROWS * (D + O0)];// concat buffer (max width 644)

// ---------------------------------------------------------------------------
// LayerNorm: one block per row, 128 threads, D=512
// ---------------------------------------------------------------------------
__global__ __launch_bounds__(128) void ln_kernel(const float* __restrict__ x,
                                                 const float* __restrict__ g,
                                                 const float* __restrict__ b,
                                                 float* __restrict__ out)
{
    int row = blockIdx.x;
    const float* xr = x + (size_t)row * D;
    __shared__ float red[128];
    int tid = threadIdx.x;

    float s = 0.f;
    #pragma unroll
    for (int i = tid; i < D; i += 128) s += xr[i];
    red[tid] = s; __syncthreads();
    for (int st = 64; st > 0; st >>= 1) {
        if (tid < st) red[tid] += red[tid + st];
        __syncthreads();
    }
    float mu = red[0] * (1.f / D);
    __syncthreads();

    float v = 0.f;
    #pragma unroll
    for (int i = tid; i < D; i += 128) { float d = xr[i] - mu; v += d * d; }
    red[tid] = v; __syncthreads();
    for (int st = 64; st > 0; st >>= 1) {
        if (tid < st) red[tid] += red[tid + st];
        __syncthreads();
    }
    float inv = rsqrtf(red[0] * (1.f / D) + EPS);

    float* orow = out + (size_t)row * D;
    #pragma unroll
    for (int i = tid; i < D; i += 128)
        orow[i] = (xr[i] - mu) * inv * g[i] + b[i];
}

// ---------------------------------------------------------------------------
// Generic SGEMM: C[M,N] = A[M,K] @ B[K,N]  (+bias)(+gelu)(+res)
// 128x128x8 tiles, 256 threads, 8x8 per-thread microtile.
// M is guaranteed a multiple of 128 (always 4096 here); N,K arbitrary.
// flags: 1 = add bias[n], 2 = exact GELU, 4 = add res[m*N+n]
// ---------------------------------------------------------------------------
#define BM 128
#define BN 128
#define BK 8

__global__ __launch_bounds__(256) void gemm_kernel(
    const float* __restrict__ A, const float* __restrict__ B,
    const float* __restrict__ bias, const float* __restrict__ res,
    float* __restrict__ C, int M, int N, int K, int flags)
{
    __shared__ float As[BK][BM];
    __shared__ float Bs[BK][BN + 4];

    int tid = threadIdx.x;
    int tx = tid & 15;          // 0..15 -> N direction
    int ty = tid >> 4;          // 0..15 -> M direction
    int brow = blockIdx.y;      // M tile
    int bcol = blockIdx.x;      // N tile

    int aRow = tid >> 1;            // 0..127
    int aCol = (tid & 1) * 4;       // 0 or 4
    int bRow = tid >> 5;            // 0..7
    int bCol = (tid & 31) * 4;      // 0..124

    const float* Ablk = A + (size_t)(brow * BM) * K;

    float acc[8][8];
    #pragma unroll
    for (int i = 0; i < 8; i++)
        #pragma unroll
        for (int j = 0; j < 8; j++) acc[i][j] = 0.f;

    for (int k0 = 0; k0 < K; k0 += BK) {
        #pragma unroll
        for (int i = 0; i < 4; i++) {
            int kk = aCol + i;
            int gk = k0 + kk;
            As[kk][aRow] = (gk < K) ? Ablk[(size_t)aRow * K + gk] : 0.f;
        }
        int gkB = k0 + bRow;
        #pragma unroll
        for (int i = 0; i < 4; i++) {
            int nn = bCol + i;
            int gn = bcol * BN + nn;
            Bs[bRow][nn] = (gkB < K && gn < N) ? B[(size_t)gkB * N + gn] : 0.f;
        }
        __syncthreads();

        #pragma unroll
        for (int kk = 0; kk < BK; kk++) {
            float ar[8], br[8];
            #pragma unroll
            for (int i = 0; i < 8; i++) ar[i] = As[kk][ty * 8 + i];
            #pragma unroll
            for (int j = 0; j < 8; j++) br[j] = Bs[kk][tx * 8 + j];
            #pragma unroll
            for (int i = 0; i < 8; i++)
                #pragma unroll
                for (int j = 0; j < 8; j++)
                    acc[i][j] = fmaf(ar[i], br[j], acc[i][j]);
        }
        __syncthreads();
    }

    #pragma unroll
    for (int i = 0; i < 8; i++) {
        int row = brow * BM + ty * 8 + i;
        #pragma unroll
        for (int j = 0; j < 8; j++) {
            int col = bcol * BN + tx * 8 + j;
            if (col < N) {
                float v = acc[i][j];
                if (flags & 1) v += bias[col];
                if (flags & 2) v = 0.5f * v * (1.f + erff(v * 0.70710678118654752f));
                if (flags & 4) v += res[(size_t)row * N + col];
                C[(size_t)row * N + col] = v;
            }
        }
    }
}

// ---------------------------------------------------------------------------
// Flash attention: grid (T/128, B*H), 128 threads; each thread = 1 query row.
// q/o live in registers; K,V 32x64 tiles in smem (score loop reads smem
// broadcast). mask is all-True in this problem -> omitted.
// ---------------------------------------------------------------------------
__global__ __launch_bounds__(128) void attn_kernel(const float* __restrict__ qkv,
                                                   float* __restrict__ out)
{
    const int bh = blockIdx.y;
    const int b  = bh / H;
    const int h  = bh % H;
    const int qi = blockIdx.x * 128 + threadIdx.x;  // < 2048 always
    const float scale = 0.125f;  // DH^-0.5

    __shared__ float Ks[32][64];
    __shared__ float Vs[32][64];

    float q[64];
    {
        const float* qp = qkv + (size_t)(b * TT + qi) * (3 * H * DH) + h * DH;
        #pragma unroll
        for (int d = 0; d < 64; d++) q[d] = qp[d];
    }

    float o[64];
    #pragma unroll
    for (int d = 0; d < 64; d++) o[d] = 0.f;
    float m = -1e30f, l = 0.f;

    for (int kb = 0; kb < TT / 32; kb++) {
        // cooperative load of K,V tiles (32 rows x 64 dims)
        {
            int base = threadIdx.x * 16;   // 128 threads * 16 = 2048 elements
            #pragma unroll
            for (int e = 0; e < 16; e++) {
                int idx = base + e;
                int j = idx >> 6, d = idx & 63;
                size_t src = (size_t)(b * TT + kb * 32 + j) * (3 * H * DH) + h * DH + d;
                Ks[j][d] = qkv[src + H * DH];
                Vs[j][d] = qkv[src + 2 * H * DH];
            }
        }
        __syncthreads();

        float sj[32];
        float tm = -1e30f;
        #pragma unroll
        for (int j = 0; j < 32; j++) {
            float s = 0.f;
            #pragma unroll
            for (int d = 0; d < 64; d++) s = fmaf(q[d], Ks[j][d], s);
            s *= scale;
            sj[j] = s;
            tm = fmaxf(tm, s);
        }
        float m_new = fmaxf(m, tm);
        float corr = __expf(m - m_new);
        l *= corr;
        #pragma unroll
        for (int d = 0; d < 64; d++) o[d] *= corr;
        #pragma unroll
        for (int j = 0; j < 32; j++) {
            float p = __expf(sj[j] - m_new);
            l += p;
            #pragma unroll
            for (int d = 0; d < 64; d++) o[d] = fmaf(p, Vs[j][d], o[d]);
        }
        m = m_new;
        __syncthreads();
    }

    float invl = 1.f / l;
    float* op = out + (size_t)(b * TT + qi) * (H * DH) + h * DH;
    #pragma unroll
    for (int d = 0; d < 64; d++) op[d] = o[d] * invl;
}

// ---------------------------------------------------------------------------
// concat: dst[r, :] = [a[r, :na], b2[r, :nb]]
// ---------------------------------------------------------------------------
__global__ void concat_kernel(float* __restrict__ dst,
                              const float* __restrict__ a, int na,
                              const float* __restrict__ b2, int nb, int rows)
{
    int w = na + nb;
    int total = rows * w;
    for (int idx = blockIdx.x * blockDim.x + threadIdx.x; idx < total;
         idx += gridDim.x * blockDim.x) {
        int r = idx / w, c = idx - r * w;
        dst[idx] = (c < na) ? a[(size_t)r * na + c] : b2[(size_t)r * nb + (c - na)];
    }
}

// ---------------------------------------------------------------------------
// launch
// ---------------------------------------------------------------------------
extern "C" void kernel_launch(void* const* d_in, const int* in_sizes, int n_in,
                              void* d_out, int out_size)
{
    (void)in_sizes; (void)n_in; (void)out_size;

    const float* in_x     = (const float*)d_in[0];
    const float* in_init0 = (const float*)d_in[1];
    const float* in_init1 = (const float*)d_in[2];
    // d_in[3] = mask: constant all-True for this problem -> unused
    const float* ln1_g = (const float*)d_in[4];
    const float* ln1_b = (const float*)d_in[5];
    const float* qkv_W = (const float*)d_in[6];
    const float* out_W = (const float*)d_in[7];
    const float* out_b = (const float*)d_in[8];
    const float* ln2_g = (const float*)d_in[9];
    const float* ln2_b = (const float*)d_in[10];
    const float* ff_W1 = (const float*)d_in[11];
    const float* ff_b1 = (const float*)d_in[12];
    const float* ff_W2 = (const float*)d_in[13];
    const float* ff_b2 = (const float*)d_in[14];
    const float* ln3_g = (const float*)d_in[15];
    const float* ln3_b = (const float*)d_in[16];
    const float* r0_W1 = (const float*)d_in[17];
    const float* r0_b1 = (const float*)d_in[18];
    const float* r0_W2 = (const float*)d_in[19];
    const float* r0_b2 = (const float*)d_in[20];
    const float* ln4_g = (const float*)d_in[21];
    const float* ln4_b = (const float*)d_in[22];
    const float* r1_W1 = (const float*)d_in[23];
    const float* r1_b1 = (const float*)d_in[24];
    const float* r1_W2 = (const float*)d_in[25];
    const float* r1_b2 = (const float*)d_in[26];

    float *px, *ph, *pqkv, *po, *pmid, *pcat;
    cudaGetSymbolAddress((void**)&px,   g_x);
    cudaGetSymbolAddress((void**)&ph,   g_h);
    cudaGetSymbolAddress((void**)&pqkv, g_qkv);
    cudaGetSymbolAddress((void**)&po,   g_o);
    cudaGetSymbolAddress((void**)&pmid, g_mid);
    cudaGetSymbolAddress((void**)&pcat, g_cat);

    float* y0 = (float*)d_out;                 // [ROWS, O0]
    float* y1 = (float*)d_out + ROWS * O0;     // [ROWS, O1]

    cudaMemcpyAsync(px, in_x,     (size_t)ROWS * D  * sizeof(float), cudaMemcpyDeviceToDevice, 0);
    cudaMemcpyAsync(y0, in_init0, (size_t)ROWS * O0 * sizeof(float), cudaMemcpyDeviceToDevice, 0);
    cudaMemcpyAsync(y1, in_init1, (size_t)ROWS * O1 * sizeof(float), cudaMemcpyDeviceToDevice, 0);

    const int NQKV = 3 * H * DH;   // 1536
    const int K0   = D + O0;       // 644
    const int K1   = D + O1;       // 515

    for (int l = 0; l < LAYERS; l++) {
        // --- attention block ---
        ln_kernel<<<ROWS, 128>>>(px, ln1_g + l * D, ln1_b + l * D, ph);
        gemm_kernel<<<dim3((NQKV + BN - 1) / BN, ROWS / BM), 256>>>(
            ph, qkv_W + (size_t)l * D * NQKV, nullptr, nullptr, pqkv,
            ROWS, NQKV, D, 0);
        attn_kernel<<<dim3(TT / 128, BB * H), 128>>>(pqkv, po);
        gemm_kernel<<<dim3((D + BN - 1) / BN, ROWS / BM), 256>>>(
            po, out_W + (size_t)l * D * D, out_b + l * D, px, px,
            ROWS, D, D, 1 | 4);

        // --- FFN block ---
        ln_kernel<<<ROWS, 128>>>(px, ln2_g + l * D, ln2_b + l * D, ph);
        gemm_kernel<<<dim3((MFF + BN - 1) / BN, ROWS / BM), 256>>>(
            ph, ff_W1 + (size_t)l * D * MFF, ff_b1 + l * MFF, nullptr, pmid,
            ROWS, MFF, D, 1 | 2);
        gemm_kernel<<<dim3((D + BN - 1) / BN, ROWS / BM), 256>>>(
            pmid, ff_W2 + (size_t)l * MFF * D, ff_b2 + l * D, px, px,
            ROWS, D, MFF, 1 | 4);

        // --- regressor 0 ---
        ln_kernel<<<ROWS, 128>>>(px, ln3_g + l * D, ln3_b + l * D, ph);
        concat_kernel<<<2048, 256>>>(pcat, ph, D, y0, O0, ROWS);
        gemm_kernel<<<dim3((MFF + BN - 1) / BN, ROWS / BM), 256>>>(
            pcat, r0_W1 + (size_t)l * K0 * MFF, r0_b1 + l * MFF, nullptr, pmid,
            ROWS, MFF, K0, 1 | 2);
        gemm_kernel<<<dim3((O0 + BN - 1) / BN, ROWS / BM), 256>>>(
            pmid, r0_W2 + (size_t)l * MFF * O0, r0_b2 + l * O0, y0, y0,
            ROWS, O0, MFF, 1 | 4);

        // --- regressor 1 ---
        ln_kernel<<<ROWS, 128>>>(px, ln4_g + l * D, ln4_b + l * D, ph);
        concat_kernel<<<2048, 256>>>(pcat, ph, D, y1, O1, ROWS);
        gemm_kernel<<<dim3((MFF + BN - 1) / BN, ROWS / BM), 256>>>(
            pcat, r1_W1 + (size_t)l * K1 * MFF, r1_b1 + l * MFF, nullptr, pmid,
            ROWS, MFF, K1, 1 | 2);
        gemm_kernel<<<dim3((O1 + BN - 1) / BN, ROWS / BM), 256>>>(
            pmid, r1_W2 + (size_t)l * MFF * O1, r1_b2 + l * O1, y1, y1,
            ROWS, O1, MFF, 1 | 4);
    }
}

// round 3
// speedup vs baseline: 1.4952x; 1.4952x over previous
#include <cuda_runtime.h>
#include <cuda_bf16.h>
#include <math.h>
#include <stdint.h>

// Problem constants
#define LAYERS 2
#define D 512
#define H 8
#define DH 64
#define MFF 2048
#define O0 132
#define O1 3
#define BB 2
#define TT 2048
#define ROWS (BB*TT)          // 4096
#define EPS 1e-5f

// ---------------------------------------------------------------------------
// Scratch (device globals; no runtime allocation allowed)
// ---------------------------------------------------------------------------
__device__ float g_x  [ROWS * D];
__device__ float g_h  [ROWS * D];
__device__ float g_qkv[ROWS * 3 * H * DH];
__device__ float g_o  [ROWS * D];
__device__ float g_mid[ROWS * MFF];
__device__ float g_cat[ROWS * (D + O0)];

// ---------------------------------------------------------------------------
// LayerNorm: one block per row, 128 threads, D=512
// ---------------------------------------------------------------------------
__global__ __launch_bounds__(128) void ln_kernel(const float* __restrict__ x,
                                                 const float* __restrict__ g,
                                                 const float* __restrict__ b,
                                                 float* __restrict__ out)
{
    int row = blockIdx.x;
    const float* xr = x + (size_t)row * D;
    __shared__ float red[128];
    int tid = threadIdx.x;

    float s = 0.f;
    #pragma unroll
    for (int i = tid; i < D; i += 128) s += xr[i];
    red[tid] = s; __syncthreads();
    for (int st = 64; st > 0; st >>= 1) {
        if (tid < st) red[tid] += red[tid + st];
        __syncthreads();
    }
    float mu = red[0] * (1.f / D);
    __syncthreads();

    float v = 0.f;
    #pragma unroll
    for (int i = tid; i < D; i += 128) { float d = xr[i] - mu; v += d * d; }
    red[tid] = v; __syncthreads();
    for (int st = 64; st > 0; st >>= 1) {
        if (tid < st) red[tid] += red[tid + st];
        __syncthreads();
    }
    float inv = rsqrtf(red[0] * (1.f / D) + EPS);

    float* orow = out + (size_t)row * D;
    #pragma unroll
    for (int i = tid; i < D; i += 128)
        orow[i] = (xr[i] - mu) * inv * g[i] + b[i];
}

// ---------------------------------------------------------------------------
// TF32 tensor-core GEMM: C[M,N] = A[M,K] @ B[K,N]  (+bias)(+gelu)(+res)
// Tiles: 128x128x16.  8 warps (2x4); warp tile 64x32; mma.m16n8k8.tf32.
// M multiple of 128 (always 4096); N,K arbitrary (zero-fill remainder).
// flags: 1 = add bias[n], 2 = exact GELU, 4 = add res[m*N+n]
// ---------------------------------------------------------------------------
#define BM 128
#define BN 128
#define BK 16

__device__ __forceinline__ uint32_t f2tf32(float f) {
    uint32_t u;
    asm("cvt.rna.tf32.f32 %0, %1;" : "=r"(u) : "f"(f));
    return u;
}

__global__ __launch_bounds__(256) void gemm_tc_kernel(
    const float* __restrict__ A, const float* __restrict__ B,
    const float* __restrict__ bias, const float* __restrict__ res,
    float* __restrict__ C, int M, int N, int K, int flags)
{
    __shared__ uint32_t As[BM][BK + 1];   // A[m][k], tf32 bits, stride 17
    __shared__ uint32_t Bs[BK][BN + 4];   // B[k][n], tf32 bits, stride 132

    const int tid  = threadIdx.x;
    const int lane = tid & 31;
    const int wid  = tid >> 5;           // 0..7
    const int wm   = wid >> 2;           // 0..1 -> m offset wm*64
    const int wn   = wid & 3;            // 0..3 -> n offset wn*32
    const int lr   = lane >> 2;          // 0..7
    const int lc   = lane & 3;           // 0..3

    const int m0 = blockIdx.y * BM;
    const int n0 = blockIdx.x * BN;

    // accumulators: 4 m-tiles x 4 n-tiles x 4 floats
    float acc[4][4][4];
    #pragma unroll
    for (int i = 0; i < 4; i++)
        #pragma unroll
        for (int j = 0; j < 4; j++)
            #pragma unroll
            for (int r = 0; r < 4; r++) acc[i][j][r] = 0.f;

    // A load mapping: thread t -> row t>>1, k-base (t&1)*8, 8 elems
    const int aRow = tid >> 1;
    const int aK   = (tid & 1) * 8;
    // B load mapping: thread t -> k t>>4, n-base (t&15)*8, 8 elems
    const int bK   = tid >> 4;
    const int bN   = (tid & 15) * 8;

    for (int k0 = 0; k0 < K; k0 += BK) {
        // --- load A tile (guarded, tf32-converted) ---
        {
            const float* ap = A + (size_t)(m0 + aRow) * K;
            #pragma unroll
            for (int i = 0; i < 8; i++) {
                int gk = k0 + aK + i;
                float v = (gk < K) ? ap[gk] : 0.f;
                As[aRow][aK + i] = f2tf32(v);
            }
        }
        // --- load B tile ---
        {
            int gk = k0 + bK;
            const float* bp = B + (size_t)gk * N;
            #pragma unroll
            for (int i = 0; i < 8; i++) {
                int gn = n0 + bN + i;
                float v = (gk < K && gn < N) ? bp[gn] : 0.f;
                Bs[bK][bN + i] = f2tf32(v);
            }
        }
        __syncthreads();

        #pragma unroll
        for (int ks = 0; ks < BK; ks += 8) {
            // A fragments
            uint32_t af[4][4];
            #pragma unroll
            for (int mi = 0; mi < 4; mi++) {
                int r = wm * 64 + mi * 16 + lr;
                af[mi][0] = As[r    ][ks + lc];
                af[mi][1] = As[r + 8][ks + lc];
                af[mi][2] = As[r    ][ks + 4 + lc];
                af[mi][3] = As[r + 8][ks + 4 + lc];
            }
            // B fragments
            uint32_t bf[4][2];
            #pragma unroll
            for (int ni = 0; ni < 4; ni++) {
                int c = wn * 32 + ni * 8 + lr;
                bf[ni][0] = Bs[ks + lc    ][c];
                bf[ni][1] = Bs[ks + 4 + lc][c];
            }
            #pragma unroll
            for (int mi = 0; mi < 4; mi++)
                #pragma unroll
                for (int ni = 0; ni < 4; ni++) {
                    asm volatile(
                        "mma.sync.aligned.m16n8k8.row.col.f32.tf32.tf32.f32 "
                        "{%0,%1,%2,%3}, {%4,%5,%6,%7}, {%8,%9}, {%0,%1,%2,%3};"
                        : "+f"(acc[mi][ni][0]), "+f"(acc[mi][ni][1]),
                          "+f"(acc[mi][ni][2]), "+f"(acc[mi][ni][3])
                        : "r"(af[mi][0]), "r"(af[mi][1]),
                          "r"(af[mi][2]), "r"(af[mi][3]),
                          "r"(bf[ni][0]), "r"(bf[ni][1]));
                }
        }
        __syncthreads();
    }

    // --- epilogue ---
    #pragma unroll
    for (int mi = 0; mi < 4; mi++) {
        #pragma unroll
        for (int ni = 0; ni < 4; ni++) {
            int row = m0 + wm * 64 + mi * 16 + lr;
            int col = n0 + wn * 32 + ni * 8 + lc * 2;
            #pragma unroll
            for (int r = 0; r < 4; r++) {
                int rr = row + (r >> 1) * 8;
                int cc = col + (r & 1);
                if (cc < N) {
                    float v = acc[mi][ni][r];
                    if (flags & 1) v += bias[cc];
                    if (flags & 2) v = 0.5f * v * (1.f + erff(v * 0.70710678118654752f));
                    if (flags & 4) v += res[(size_t)rr * N + cc];
                    C[(size_t)rr * N + cc] = v;
                }
            }
        }
    }
}

// ---------------------------------------------------------------------------
// Flash attention: grid (T/128, B*H), 128 threads; 1 thread = 1 query row.
// float4 smem tiles so each LDS.128 broadcast feeds 4 FMAs.
// mask is all-True in this problem -> omitted.
// ---------------------------------------------------------------------------
__global__ __launch_bounds__(128) void attn_kernel(const float* __restrict__ qkv,
                                                   float* __restrict__ out)
{
    const int bh = blockIdx.y;
    const int b  = bh / H;
    const int h  = bh % H;
    const int qi = blockIdx.x * 128 + threadIdx.x;
    const float scale = 0.125f;

    __shared__ float4 Ks[32][16];
    __shared__ float4 Vs[32][16];

    float4 q4[16];
    {
        const float4* qp = (const float4*)(qkv + (size_t)(b * TT + qi) * (3 * H * DH) + h * DH);
        #pragma unroll
        for (int d = 0; d < 16; d++) q4[d] = qp[d];
    }

    float4 o4[16];
    #pragma unroll
    for (int d = 0; d < 16; d++) o4[d] = make_float4(0.f, 0.f, 0.f, 0.f);
    float m = -1e30f, l = 0.f;

    for (int kb = 0; kb < TT / 32; kb++) {
        {
            int base = threadIdx.x * 4;     // 128 threads * 4 = 512 float4
            #pragma unroll
            for (int e = 0; e < 4; e++) {
                int idx = base + e;
                int j = idx >> 4, d = idx & 15;
                const float4* src = (const float4*)(qkv +
                    (size_t)(b * TT + kb * 32 + j) * (3 * H * DH) + h * DH);
                Ks[j][d] = src[d + (H * DH) / 4];
                Vs[j][d] = src[d + (2 * H * DH) / 4];
            }
        }
        __syncthreads();

        float sj[32];
        float tm = -1e30f;
        #pragma unroll
        for (int j = 0; j < 32; j++) {
            float s = 0.f;
            #pragma unroll
            for (int d = 0; d < 16; d++) {
                float4 k4 = Ks[j][d];
                s = fmaf(q4[d].x, k4.x, s);
                s = fmaf(q4[d].y, k4.y, s);
                s = fmaf(q4[d].z, k4.z, s);
                s = fmaf(q4[d].w, k4.w, s);
            }
            s *= scale;
            sj[j] = s;
            tm = fmaxf(tm, s);
        }
        float m_new = fmaxf(m, tm);
        float corr = __expf(m - m_new);
        l *= corr;
        #pragma unroll
        for (int d = 0; d < 16; d++) {
            o4[d].x *= corr; o4[d].y *= corr; o4[d].z *= corr; o4[d].w *= corr;
        }
        #pragma unroll
        for (int j = 0; j < 32; j++) {
            float p = __expf(sj[j] - m_new);
            l += p;
            #pragma unroll
            for (int d = 0; d < 16; d++) {
                float4 v4 = Vs[j][d];
                o4[d].x = fmaf(p, v4.x, o4[d].x);
                o4[d].y = fmaf(p, v4.y, o4[d].y);
                o4[d].z = fmaf(p, v4.z, o4[d].z);
                o4[d].w = fmaf(p, v4.w, o4[d].w);
            }
        }
        m = m_new;
        __syncthreads();
    }

    float invl = 1.f / l;
    float4* op = (float4*)(out + (size_t)(b * TT + qi) * (H * DH) + h * DH);
    #pragma unroll
    for (int d = 0; d < 16; d++) {
        float4 v = o4[d];
        v.x *= invl; v.y *= invl; v.z *= invl; v.w *= invl;
        op[d] = v;
    }
}

// ---------------------------------------------------------------------------
// concat: dst[r, :] = [a[r, :na], b2[r, :nb]]
// ---------------------------------------------------------------------------
__global__ void concat_kernel(float* __restrict__ dst,
                              const float* __restrict__ a, int na,
                              const float* __restrict__ b2, int nb, int rows)
{
    int w = na + nb;
    int total = rows * w;
    for (int idx = blockIdx.x * blockDim.x + threadIdx.x; idx < total;
         idx += gridDim.x * blockDim.x) {
        int r = idx / w, c = idx - r * w;
        dst[idx] = (c < na) ? a[(size_t)r * na + c] : b2[(size_t)r * nb + (c - na)];
    }
}

// ---------------------------------------------------------------------------
// launch
// ---------------------------------------------------------------------------
extern "C" void kernel_launch(void* const* d_in, const int* in_sizes, int n_in,
                              void* d_out, int out_size)
{
    (void)in_sizes; (void)n_in; (void)out_size;

    const float* in_x     = (const float*)d_in[0];
    const float* in_init0 = (const float*)d_in[1];
    const float* in_init1 = (const float*)d_in[2];
    // d_in[3] = mask: constant all-True for this problem -> unused
    const float* ln1_g = (const float*)d_in[4];
    const float* ln1_b = (const float*)d_in[5];
    const float* qkv_W = (const float*)d_in[6];
    const float* out_W = (const float*)d_in[7];
    const float* out_b = (const float*)d_in[8];
    const float* ln2_g = (const float*)d_in[9];
    const float* ln2_b = (const float*)d_in[10];
    const float* ff_W1 = (const float*)d_in[11];
    const float* ff_b1 = (const float*)d_in[12];
    const float* ff_W2 = (const float*)d_in[13];
    const float* ff_b2 = (const float*)d_in[14];
    const float* ln3_g = (const float*)d_in[15];
    const float* ln3_b = (const float*)d_in[16];
    const float* r0_W1 = (const float*)d_in[17];
    const float* r0_b1 = (const float*)d_in[18];
    const float* r0_W2 = (const float*)d_in[19];
    const float* r0_b2 = (const float*)d_in[20];
    const float* ln4_g = (const float*)d_in[21];
    const float* ln4_b = (const float*)d_in[22];
    const float* r1_W1 = (const float*)d_in[23];
    const float* r1_b1 = (const float*)d_in[24];
    const float* r1_W2 = (const float*)d_in[25];
    const float* r1_b2 = (const float*)d_in[26];

    float *px, *ph, *pqkv, *po, *pmid, *pcat;
    cudaGetSymbolAddress((void**)&px,   g_x);
    cudaGetSymbolAddress((void**)&ph,   g_h);
    cudaGetSymbolAddress((void**)&pqkv, g_qkv);
    cudaGetSymbolAddress((void**)&po,   g_o);
    cudaGetSymbolAddress((void**)&pmid, g_mid);
    cudaGetSymbolAddress((void**)&pcat, g_cat);

    float* y0 = (float*)d_out;                 // [ROWS, O0]
    float* y1 = (float*)d_out + ROWS * O0;     // [ROWS, O1]

    cudaMemcpyAsync(px, in_x,     (size_t)ROWS * D  * sizeof(float), cudaMemcpyDeviceToDevice, 0);
    cudaMemcpyAsync(y0, in_init0, (size_t)ROWS * O0 * sizeof(float), cudaMemcpyDeviceToDevice, 0);
    cudaMemcpyAsync(y1, in_init1, (size_t)ROWS * O1 * sizeof(float), cudaMemcpyDeviceToDevice, 0);

    const int NQKV = 3 * H * DH;   // 1536
    const int K0   = D + O0;       // 644
    const int K1   = D + O1;       // 515

    for (int l = 0; l < LAYERS; l++) {
        // --- attention block ---
        ln_kernel<<<ROWS, 128>>>(px, ln1_g + l * D, ln1_b + l * D, ph);
        gemm_tc_kernel<<<dim3((NQKV + BN - 1) / BN, ROWS / BM), 256>>>(
            ph, qkv_W + (size_t)l * D * NQKV, nullptr, nullptr, pqkv,
            ROWS, NQKV, D, 0);
        attn_kernel<<<dim3(TT / 128, BB * H), 128>>>(pqkv, po);
        gemm_tc_kernel<<<dim3((D + BN - 1) / BN, ROWS / BM), 256>>>(
            po, out_W + (size_t)l * D * D, out_b + l * D, px, px,
            ROWS, D, D, 1 | 4);

        // --- FFN block ---
        ln_kernel<<<ROWS, 128>>>(px, ln2_g + l * D, ln2_b + l * D, ph);
        gemm_tc_kernel<<<dim3((MFF + BN - 1) / BN, ROWS / BM), 256>>>(
            ph, ff_W1 + (size_t)l * D * MFF, ff_b1 + l * MFF, nullptr, pmid,
            ROWS, MFF, D, 1 | 2);
        gemm_tc_kernel<<<dim3((D + BN - 1) / BN, ROWS / BM), 256>>>(
            pmid, ff_W2 + (size_t)l * MFF * D, ff_b2 + l * D, px, px,
            ROWS, D, MFF, 1 | 4);

        // --- regressor 0 ---
        ln_kernel<<<ROWS, 128>>>(px, ln3_g + l * D, ln3_b + l * D, ph);
        concat_kernel<<<2048, 256>>>(pcat, ph, D, y0, O0, ROWS);
        gemm_tc_kernel<<<dim3((MFF + BN - 1) / BN, ROWS / BM), 256>>>(
            pcat, r0_W1 + (size_t)l * K0 * MFF, r0_b1 + l * MFF, nullptr, pmid,
            ROWS, MFF, K0, 1 | 2);
        gemm_tc_kernel<<<dim3((O0 + BN - 1) / BN, ROWS / BM), 256>>>(
            pmid, r0_W2 + (size_t)l * MFF * O0, r0_b2 + l * O0, y0, y0,
            ROWS, O0, MFF, 1 | 4);

        // --- regressor 1 ---
        ln_kernel<<<ROWS, 128>>>(px, ln4_g + l * D, ln4_b + l * D, ph);
        concat_kernel<<<2048, 256>>>(pcat, ph, D, y1, O1, ROWS);
        gemm_tc_kernel<<<dim3((MFF + BN - 1) / BN, ROWS / BM), 256>>>(
            pcat, r1_W1 + (size_t)l * K1 * MFF, r1_b1 + l * MFF, nullptr, pmid,
            ROWS, MFF, K1, 1 | 2);
        gemm_tc_kernel<<<dim3((O1 + BN - 1) / BN, ROWS / BM), 256>>>(
            pmid, r1_W2 + (size_t)l * MFF * O1, r1_b2 + l * O1, y1, y1,
            ROWS, O1, MFF, 1 | 4);
    }
}

// round 6
// speedup vs baseline: 2.6789x; 1.7917x over previous
#include <cuda_runtime.h>
#include <cuda_bf16.h>
#include <math.h>
#include <stdint.h>

// Problem constants
#define LAYERS 2
#define D 512
#define H 8
#define DH 64
#define MFF 2048
#define O0 132
#define O1 3
#define BB 2
#define TT 2048
#define ROWS (BB*TT)          // 4096
#define EPS 1e-5f

#define CAT1_STRIDE 516       // padded row stride for the K=515 concat (mod 4 == 0)

// ---------------------------------------------------------------------------
// Scratch (device globals; no runtime allocation allowed)
// ---------------------------------------------------------------------------
__device__ float g_x  [ROWS * D];
__device__ float g_h  [ROWS * D];
__device__ float g_qkv[ROWS * 3 * H * DH];
__device__ float g_o  [ROWS * D];
__device__ float g_mid[ROWS * MFF];
__device__ float g_cat[ROWS * (D + O0)];   // 644 wide; also holds 516-stride layout

// ---------------------------------------------------------------------------
// LayerNorm: one block per row, 128 threads, D=512
// ---------------------------------------------------------------------------
__global__ __launch_bounds__(128) void ln_kernel(const float* __restrict__ x,
                                                 const float* __restrict__ g,
                                                 const float* __restrict__ b,
                                                 float* __restrict__ out)
{
    int row = blockIdx.x;
    const float* xr = x + (size_t)row * D;
    __shared__ float red[128];
    int tid = threadIdx.x;

    float s = 0.f;
    #pragma unroll
    for (int i = tid; i < D; i += 128) s += xr[i];
    red[tid] = s; __syncthreads();
    for (int st = 64; st > 0; st >>= 1) {
        if (tid < st) red[tid] += red[tid + st];
        __syncthreads();
    }
    float mu = red[0] * (1.f / D);
    __syncthreads();

    float v = 0.f;
    #pragma unroll
    for (int i = tid; i < D; i += 128) { float d = xr[i] - mu; v += d * d; }
    red[tid] = v; __syncthreads();
    for (int st = 64; st > 0; st >>= 1) {
        if (tid < st) red[tid] += red[tid + st];
        __syncthreads();
    }
    float inv = rsqrtf(red[0] * (1.f / D) + EPS);

    float* orow = out + (size_t)row * D;
    #pragma unroll
    for (int i = tid; i < D; i += 128)
        orow[i] = (xr[i] - mu) * inv * g[i] + b[i];
}

// ---------------------------------------------------------------------------
// BF16 tensor-core GEMM with ldmatrix + double buffering.
// C[M,N] = A[M,K] @ B[K,N]  (+bias)(+gelu)(+res);  A row stride = lda (>= K,
// lda % 4 == 0 so float4 loads are 16B aligned).
// Tiles 128x128x32, 8 warps (2x4), warp tile 64x32, mma.m16n8k16.bf16.
// Smem padded rows: A 40 bf16 (80B), B 136 bf16 (272B) -> ldmatrix conflict-free.
// flags: 1 = add bias[n], 2 = exact GELU, 4 = add res[m*N+n]
// ---------------------------------------------------------------------------
#define BM 128
#define BN 128
#define BKT 32
#define ASTR 40
#define BSTR 136

__device__ __forceinline__ uint32_t bf2pack(float lo, float hi) {
    __nv_bfloat162 h = __floats2bfloat162_rn(lo, hi);
    return *reinterpret_cast<uint32_t*>(&h);
}

__global__ __launch_bounds__(256) void gemm_bf16_kernel(
    const float* __restrict__ A, const float* __restrict__ B,
    const float* __restrict__ bias, const float* __restrict__ res,
    float* __restrict__ C, int M, int N, int K, int lda, int flags)
{
    __shared__ __align__(16) uint16_t As[2][BM][ASTR];
    __shared__ __align__(16) uint16_t Bs[2][BKT][BSTR];

    const int tid  = threadIdx.x;
    const int lane = tid & 31;
    const int wid  = tid >> 5;
    const int wm   = wid >> 2;           // 0..1
    const int wn   = wid & 3;            // 0..3
    const int lr   = lane >> 2;          // 0..7
    const int lc   = lane & 3;           // 0..3

    const int m0 = blockIdx.y * BM;
    const int n0 = blockIdx.x * BN;

    // gmem load mappings
    const int aRow = tid >> 1;            // 0..127
    const int aK   = (tid & 1) * 16;      // 0 or 16
    const int bK   = tid >> 3;            // 0..31
    const int bN   = (tid & 7) * 16;      // 0..112

    // ldmatrix per-lane address components
    const int a_r  = (lane & 7) + ((lane >> 3) & 1) * 8;   // row within 16
    const int a_kc = (lane >> 4) * 8;                      // k chunk 0/8
    const int b_kr = (lane & 7) + ((lane >> 3) & 1) * 8;   // k within 16
    const int b_nc = (lane >> 4) * 8;                      // n chunk 0/8

    float acc[4][4][4];
    #pragma unroll
    for (int i = 0; i < 4; i++)
        #pragma unroll
        for (int j = 0; j < 4; j++)
            #pragma unroll
            for (int r = 0; r < 4; r++) acc[i][j][r] = 0.f;

    const int nkt = (K + BKT - 1) / BKT;

    float aReg[16], bReg[16];

    // ---- prologue: load tile 0 ----
    {
        const int k0 = 0;
        if (k0 + BKT <= K) {
            const float4* ap = (const float4*)(A + (size_t)(m0 + aRow) * lda + k0 + aK);
            #pragma unroll
            for (int i = 0; i < 4; i++) *(float4*)(aReg + i * 4) = ap[i];
        } else {
            const float* ap = A + (size_t)(m0 + aRow) * lda;
            #pragma unroll
            for (int i = 0; i < 16; i++) {
                int gk = k0 + aK + i;
                aReg[i] = (gk < K) ? ap[gk] : 0.f;
            }
        }
        int gk = k0 + bK;
        if (gk < K && n0 + BN <= N) {
            const float4* bp = (const float4*)(B + (size_t)gk * N + n0 + bN);
            #pragma unroll
            for (int i = 0; i < 4; i++) *(float4*)(bReg + i * 4) = bp[i];
        } else {
            #pragma unroll
            for (int i = 0; i < 16; i++) {
                int gn = n0 + bN + i;
                bReg[i] = (gk < K && gn < N) ? B[(size_t)gk * N + gn] : 0.f;
            }
        }
        // convert + store to buffer 0
        uint32_t pa[8], pb[8];
        #pragma unroll
        for (int i = 0; i < 8; i++) { pa[i] = bf2pack(aReg[2*i], aReg[2*i+1]);
                                      pb[i] = bf2pack(bReg[2*i], bReg[2*i+1]); }
        *(uint4*)&As[0][aRow][aK]     = make_uint4(pa[0],pa[1],pa[2],pa[3]);
        *(uint4*)&As[0][aRow][aK + 8] = make_uint4(pa[4],pa[5],pa[6],pa[7]);
        *(uint4*)&Bs[0][bK][bN]       = make_uint4(pb[0],pb[1],pb[2],pb[3]);
        *(uint4*)&Bs[0][bK][bN + 8]   = make_uint4(pb[4],pb[5],pb[6],pb[7]);
    }
    __syncthreads();

    for (int t = 0; t < nkt; t++) {
        // ---- issue gmem loads for next tile ----
        if (t + 1 < nkt) {
            const int k0 = (t + 1) * BKT;
            if (k0 + BKT <= K) {
                const float4* ap = (const float4*)(A + (size_t)(m0 + aRow) * lda + k0 + aK);
                #pragma unroll
                for (int i = 0; i < 4; i++) *(float4*)(aReg + i * 4) = ap[i];
            } else {
                const float* ap = A + (size_t)(m0 + aRow) * lda;
                #pragma unroll
                for (int i = 0; i < 16; i++) {
                    int gk = k0 + aK + i;
                    aReg[i] = (gk < K) ? ap[gk] : 0.f;
                }
            }
            int gk = k0 + bK;
            if (gk < K && n0 + BN <= N) {
                const float4* bp = (const float4*)(B + (size_t)gk * N + n0 + bN);
                #pragma unroll
                for (int i = 0; i < 4; i++) *(float4*)(bReg + i * 4) = bp[i];
            } else {
                #pragma unroll
                for (int i = 0; i < 16; i++) {
                    int gn = n0 + bN + i;
                    bReg[i] = (gk < K && gn < N) ? B[(size_t)gk * N + gn] : 0.f;
                }
            }
        }

        // ---- compute on buffer t&1 ----
        const int buf = t & 1;
        uint32_t aBase = (uint32_t)__cvta_generic_to_shared(&As[buf][0][0]);
        uint32_t bBase = (uint32_t)__cvta_generic_to_shared(&Bs[buf][0][0]);

        #pragma unroll
        for (int kk = 0; kk < BKT; kk += 16) {
            uint32_t af[4][4];
            #pragma unroll
            for (int mi = 0; mi < 4; mi++) {
                uint32_t addr = aBase +
                    ((wm * 64 + mi * 16 + a_r) * ASTR + kk + a_kc) * 2;
                asm volatile(
                    "ldmatrix.sync.aligned.m8n8.x4.shared.b16 {%0,%1,%2,%3}, [%4];"
                    : "=r"(af[mi][0]), "=r"(af[mi][1]),
                      "=r"(af[mi][2]), "=r"(af[mi][3]) : "r"(addr));
            }
            uint32_t bfp[2][4];
            #pragma unroll
            for (int pr = 0; pr < 2; pr++) {
                uint32_t addr = bBase +
                    ((kk + b_kr) * BSTR + wn * 32 + pr * 16 + b_nc) * 2;
                asm volatile(
                    "ldmatrix.sync.aligned.m8n8.x4.trans.shared.b16 {%0,%1,%2,%3}, [%4];"
                    : "=r"(bfp[pr][0]), "=r"(bfp[pr][1]),
                      "=r"(bfp[pr][2]), "=r"(bfp[pr][3]) : "r"(addr));
            }
            #pragma unroll
            for (int mi = 0; mi < 4; mi++)
                #pragma unroll
                for (int ni = 0; ni < 4; ni++) {
                    uint32_t b0 = bfp[ni >> 1][(ni & 1) * 2];
                    uint32_t b1 = bfp[ni >> 1][(ni & 1) * 2 + 1];
                    asm volatile(
                        "mma.sync.aligned.m16n8k16.row.col.f32.bf16.bf16.f32 "
                        "{%0,%1,%2,%3}, {%4,%5,%6,%7}, {%8,%9}, {%0,%1,%2,%3};"
                        : "+f"(acc[mi][ni][0]), "+f"(acc[mi][ni][1]),
                          "+f"(acc[mi][ni][2]), "+f"(acc[mi][ni][3])
                        : "r"(af[mi][0]), "r"(af[mi][1]),
                          "r"(af[mi][2]), "r"(af[mi][3]),
                          "r"(b0), "r"(b1));
                }
        }

        // ---- store next tile into other buffer ----
        if (t + 1 < nkt) {
            const int nb = (t + 1) & 1;
            uint32_t pa[8], pb[8];
            #pragma unroll
            for (int i = 0; i < 8; i++) { pa[i] = bf2pack(aReg[2*i], aReg[2*i+1]);
                                          pb[i] = bf2pack(bReg[2*i], bReg[2*i+1]); }
            __syncthreads();   // everyone done reading buffer nb from iter t-1
            *(uint4*)&As[nb][aRow][aK]     = make_uint4(pa[0],pa[1],pa[2],pa[3]);
            *(uint4*)&As[nb][aRow][aK + 8] = make_uint4(pa[4],pa[5],pa[6],pa[7]);
            *(uint4*)&Bs[nb][bK][bN]       = make_uint4(pb[0],pb[1],pb[2],pb[3]);
            *(uint4*)&Bs[nb][bK][bN + 8]   = make_uint4(pb[4],pb[5],pb[6],pb[7]);
            __syncthreads();
        }
    }

    // ---- epilogue ----
    #pragma unroll
    for (int mi = 0; mi < 4; mi++) {
        #pragma unroll
        for (int ni = 0; ni < 4; ni++) {
            int row = m0 + wm * 64 + mi * 16 + lr;
            int col = n0 + wn * 32 + ni * 8 + lc * 2;
            #pragma unroll
            for (int r = 0; r < 4; r++) {
                int rr = row + (r >> 1) * 8;
                int cc = col + (r & 1);
                if (cc < N) {
                    float v = acc[mi][ni][r];
                    if (flags & 1) v += bias[cc];
                    if (flags & 2) v = 0.5f * v * (1.f + erff(v * 0.70710678118654752f));
                    if (flags & 4) v += res[(size_t)rr * N + cc];
                    C[(size_t)rr * N + cc] = v;
                }
            }
        }
    }
}

// ---------------------------------------------------------------------------
// Flash attention: grid (T/128, B*H), 128 threads; 1 thread = 1 query row.
// float4 smem tiles so each LDS.128 broadcast feeds 4 FMAs.
// ---------------------------------------------------------------------------
__global__ __launch_bounds__(128) void attn_kernel(const float* __restrict__ qkv,
                                                   float* __restrict__ out)
{
    const int bh = blockIdx.y;
    const int b  = bh / H;
    const int h  = bh % H;
    const int qi = blockIdx.x * 128 + threadIdx.x;
    const float scale = 0.125f;

    __shared__ float4 Ks[32][16];
    __shared__ float4 Vs[32][16];

    float4 q4[16];
    {
        const float4* qp = (const float4*)(qkv + (size_t)(b * TT + qi) * (3 * H * DH) + h * DH);
        #pragma unroll
        for (int d = 0; d < 16; d++) q4[d] = qp[d];
    }

    float4 o4[16];
    #pragma unroll
    for (int d = 0; d < 16; d++) o4[d] = make_float4(0.f, 0.f, 0.f, 0.f);
    float m = -1e30f, l = 0.f;

    for (int kb = 0; kb < TT / 32; kb++) {
        {
            int base = threadIdx.x * 4;
            #pragma unroll
            for (int e = 0; e < 4; e++) {
                int idx = base + e;
                int j = idx >> 4, d = idx & 15;
                const float4* src = (const float4*)(qkv +
                    (size_t)(b * TT + kb * 32 + j) * (3 * H * DH) + h * DH);
                Ks[j][d] = src[d + (H * DH) / 4];
                Vs[j][d] = src[d + (2 * H * DH) / 4];
            }
        }
        __syncthreads();

        float sj[32];
        float tm = -1e30f;
        #pragma unroll
        for (int j = 0; j < 32; j++) {
            float s = 0.f;
            #pragma unroll
            for (int d = 0; d < 16; d++) {
                float4 k4 = Ks[j][d];
                s = fmaf(q4[d].x, k4.x, s);
                s = fmaf(q4[d].y, k4.y, s);
                s = fmaf(q4[d].z, k4.z, s);
                s = fmaf(q4[d].w, k4.w, s);
            }
            s *= scale;
            sj[j] = s;
            tm = fmaxf(tm, s);
        }
        float m_new = fmaxf(m, tm);
        float corr = __expf(m - m_new);
        l *= corr;
        #pragma unroll
        for (int d = 0; d < 16; d++) {
            o4[d].x *= corr; o4[d].y *= corr; o4[d].z *= corr; o4[d].w *= corr;
        }
        #pragma unroll
        for (int j = 0; j < 32; j++) {
            float p = __expf(sj[j] - m_new);
            l += p;
            #pragma unroll
            for (int d = 0; d < 16; d++) {
                float4 v4 = Vs[j][d];
                o4[d].x = fmaf(p, v4.x, o4[d].x);
                o4[d].y = fmaf(p, v4.y, o4[d].y);
                o4[d].z = fmaf(p, v4.z, o4[d].z);
                o4[d].w = fmaf(p, v4.w, o4[d].w);
            }
        }
        m = m_new;
        __syncthreads();
    }

    float invl = 1.f / l;
    float4* op = (float4*)(out + (size_t)(b * TT + qi) * (H * DH) + h * DH);
    #pragma unroll
    for (int d = 0; d < 16; d++) {
        float4 v = o4[d];
        v.x *= invl; v.y *= invl; v.z *= invl; v.w *= invl;
        op[d] = v;
    }
}

// ---------------------------------------------------------------------------
// concat: dst[r*dstr + c] = [a[r,:na], b2[r,:nb]]  (dstr >= na+nb)
// ---------------------------------------------------------------------------
__global__ void concat_kernel(float* __restrict__ dst,
                              const float* __restrict__ a, int na,
                              const float* __restrict__ b2, int nb, int rows,
                              int dstr)
{
    int w = na + nb;
    int total = rows * w;
    for (int idx = blockIdx.x * blockDim.x + threadIdx.x; idx < total;
         idx += gridDim.x * blockDim.x) {
        int r = idx / w, c = idx - r * w;
        dst[(size_t)r * dstr + c] =
            (c < na) ? a[(size_t)r * na + c] : b2[(size_t)r * nb + (c - na)];
    }
}

// ---------------------------------------------------------------------------
// launch
// ---------------------------------------------------------------------------
extern "C" void kernel_launch(void* const* d_in, const int* in_sizes, int n_in,
                              void* d_out, int out_size)
{
    (void)in_sizes; (void)n_in; (void)out_size;

    const float* in_x     = (const float*)d_in[0];
    const float* in_init0 = (const float*)d_in[1];
    const float* in_init1 = (const float*)d_in[2];
    // d_in[3] = mask: constant all-True for this problem -> unused
    const float* ln1_g = (const float*)d_in[4];
    const float* ln1_b = (const float*)d_in[5];
    const float* qkv_W = (const float*)d_in[6];
    const float* out_W = (const float*)d_in[7];
    const float* out_b = (const float*)d_in[8];
    const float* ln2_g = (const float*)d_in[9];
    const float* ln2_b = (const float*)d_in[10];
    const float* ff_W1 = (const float*)d_in[11];
    const float* ff_b1 = (const float*)d_in[12];
    const float* ff_W2 = (const float*)d_in[13];
    const float* ff_b2 = (const float*)d_in[14];
    const float* ln3_g = (const float*)d_in[15];
    const float* ln3_b = (const float*)d_in[16];
    const float* r0_W1 = (const float*)d_in[17];
    const float* r0_b1 = (const float*)d_in[18];
    const float* r0_W2 = (const float*)d_in[19];
    const float* r0_b2 = (const float*)d_in[20];
    const float* ln4_g = (const float*)d_in[21];
    const float* ln4_b = (const float*)d_in[22];
    const float* r1_W1 = (const float*)d_in[23];
    const float* r1_b1 = (const float*)d_in[24];
    const float* r1_W2 = (const float*)d_in[25];
    const float* r1_b2 = (const float*)d_in[26];

    float *px, *ph, *pqkv, *po, *pmid, *pcat;
    cudaGetSymbolAddress((void**)&px,   g_x);
    cudaGetSymbolAddress((void**)&ph,   g_h);
    cudaGetSymbolAddress((void**)&pqkv, g_qkv);
    cudaGetSymbolAddress((void**)&po,   g_o);
    cudaGetSymbolAddress((void**)&pmid, g_mid);
    cudaGetSymbolAddress((void**)&pcat, g_cat);

    float* y0 = (float*)d_out;                 // [ROWS, O0]
    float* y1 = (float*)d_out + ROWS * O0;     // [ROWS, O1]

    cudaMemcpyAsync(px, in_x,     (size_t)ROWS * D  * sizeof(float), cudaMemcpyDeviceToDevice, 0);
    cudaMemcpyAsync(y0, in_init0, (size_t)ROWS * O0 * sizeof(float), cudaMemcpyDeviceToDevice, 0);
    cudaMemcpyAsync(y1, in_init1, (size_t)ROWS * O1 * sizeof(float), cudaMemcpyDeviceToDevice, 0);

    const int NQKV = 3 * H * DH;   // 1536
    const int K0   = D + O0;       // 644 (mod 4 == 0)
    const int K1   = D + O1;       // 515 (mod 4 == 3 -> padded stride)

    for (int l = 0; l < LAYERS; l++) {
        // --- attention block ---
        ln_kernel<<<ROWS, 128>>>(px, ln1_g + l * D, ln1_b + l * D, ph);
        gemm_bf16_kernel<<<dim3((NQKV + BN - 1) / BN, ROWS / BM), 256>>>(
            ph, qkv_W + (size_t)l * D * NQKV, nullptr, nullptr, pqkv,
            ROWS, NQKV, D, D, 0);
        attn_kernel<<<dim3(TT / 128, BB * H), 128>>>(pqkv, po);
        gemm_bf16_kernel<<<dim3((D + BN - 1) / BN, ROWS / BM), 256>>>(
            po, out_W + (size_t)l * D * D, out_b + l * D, px, px,
            ROWS, D, D, D, 1 | 4);

        // --- FFN block ---
        ln_kernel<<<ROWS, 128>>>(px, ln2_g + l * D, ln2_b + l * D, ph);
        gemm_bf16_kernel<<<dim3((MFF + BN - 1) / BN, ROWS / BM), 256>>>(
            ph, ff_W1 + (size_t)l * D * MFF, ff_b1 + l * MFF, nullptr, pmid,
            ROWS, MFF, D, D, 1 | 2);
        gemm_bf16_kernel<<<dim3((D + BN - 1) / BN, ROWS / BM), 256>>>(
            pmid, ff_W2 + (size_t)l * MFF * D, ff_b2 + l * D, px, px,
            ROWS, D, MFF, MFF, 1 | 4);

        // --- regressor 0 ---
        ln_kernel<<<ROWS, 128>>>(px, ln3_g + l * D, ln3_b + l * D, ph);
        concat_kernel<<<2048, 256>>>(pcat, ph, D, y0, O0, ROWS, K0);
        gemm_bf16_kernel<<<dim3((MFF + BN - 1) / BN, ROWS / BM), 256>>>(
            pcat, r0_W1 + (size_t)l * K0 * MFF, r0_b1 + l * MFF, nullptr, pmid,
            ROWS, MFF, K0, K0, 1 | 2);
        gemm_bf16_kernel<<<dim3((O0 + BN - 1) / BN, ROWS / BM), 256>>>(
            pmid, r0_W2 + (size_t)l * MFF * O0, r0_b2 + l * O0, y0, y0,
            ROWS, O0, MFF, MFF, 1 | 4);

        // --- regressor 1 (A padded to stride 516 for 16B-aligned float4) ---
        ln_kernel<<<ROWS, 128>>>(px, ln4_g + l * D, ln4_b + l * D, ph);
        concat_kernel<<<2048, 256>>>(pcat, ph, D, y1, O1, ROWS, CAT1_STRIDE);
        gemm_bf16_kernel<<<dim3((MFF + BN - 1) / BN, ROWS / BM), 256>>>(
            pcat, r1_W1 + (size_t)l * K1 * MFF, r1_b1 + l * MFF, nullptr, pmid,
            ROWS, MFF, K1, CAT1_STRIDE, 1 | 2);
        gemm_bf16_kernel<<<dim3((O1 + BN - 1) / BN, ROWS / BM), 256>>>(
            pmid, r1_W2 + (size_t)l * MFF * O1, r1_b2 + l * O1, y1, y1,
            ROWS, O1, MFF, MFF, 1 | 4);
    }
}

// round 8
// speedup vs baseline: 2.9667x; 1.1074x over previous
#include <cuda_runtime.h>
#include <cuda_bf16.h>
#include <math.h>
#include <stdint.h>

// Problem constants
#define LAYERS 2
#define D 512
#define H 8
#define DH 64
#define MFF 2048
#define O0 132
#define O1 3
#define BB 2
#define TT 2048
#define ROWS (BB*TT)          // 4096
#define EPS 1e-5f

#define NQKV 1536
#define K0c 644               // D+O0
#define K1c 515               // D+O1
#define LDC0 648              // cat0 stride (mod 8 == 0)
#define LDC1 520              // cat1 stride (mod 8 == 0)
#define LDW02 136             // r0_W2 padded N stride
#define LDW12 8               // r1_W2 padded N stride

// ---------------------------------------------------------------------------
// Scratch (device globals; no runtime allocation allowed)
// ---------------------------------------------------------------------------
__device__ float g_x  [ROWS * D];          // residual stream (fp32)
__device__ float g_qkv[ROWS * 3 * H * DH]; // attention input (fp32)

__device__ __nv_bfloat16 gb_h  [ROWS * D];
__device__ __nv_bfloat16 gb_o  [ROWS * D];
__device__ __nv_bfloat16 gb_mid[ROWS * MFF];
__device__ __nv_bfloat16 gb_cat[ROWS * LDC0];

__device__ __nv_bfloat16 gb_wqkv[LAYERS * D * NQKV];
__device__ __nv_bfloat16 gb_wout[LAYERS * D * D];
__device__ __nv_bfloat16 gb_wff1[LAYERS * D * MFF];
__device__ __nv_bfloat16 gb_wff2[LAYERS * MFF * D];
__device__ __nv_bfloat16 gb_wr01[LAYERS * K0c * MFF];
__device__ __nv_bfloat16 gb_wr02[LAYERS * MFF * LDW02];
__device__ __nv_bfloat16 gb_wr11[LAYERS * K1c * MFF];
__device__ __nv_bfloat16 gb_wr12[LAYERS * MFF * LDW12];

__device__ __forceinline__ uint32_t bf2pack(float lo, float hi) {
    __nv_bfloat162 h = __floats2bfloat162_rn(lo, hi);
    return *reinterpret_cast<uint32_t*>(&h);
}

// ---------------------------------------------------------------------------
// Weight fp32 -> bf16 with padded/zeroed N stride
// ---------------------------------------------------------------------------
__global__ void wconv_kernel(const float* __restrict__ src,
                             __nv_bfloat16* __restrict__ dst,
                             int rows, int N, int ldb)
{
    int half = ldb >> 1;
    int total = rows * half;
    for (int idx = blockIdx.x * blockDim.x + threadIdx.x; idx < total;
         idx += gridDim.x * blockDim.x) {
        int r = idx / half;
        int c = (idx - r * half) * 2;
        float v0 = (c     < N) ? src[(size_t)r * N + c]     : 0.f;
        float v1 = (c + 1 < N) ? src[(size_t)r * N + c + 1] : 0.f;
        reinterpret_cast<uint32_t*>(dst)[(size_t)r * half + (c >> 1)] = bf2pack(v0, v1);
    }
}

// ---------------------------------------------------------------------------
// LayerNorm: one block per row, 128 threads, D=512; bf16 output
// ---------------------------------------------------------------------------
__global__ __launch_bounds__(128) void ln_kernel(const float* __restrict__ x,
                                                 const float* __restrict__ g,
                                                 const float* __restrict__ b,
                                                 __nv_bfloat16* __restrict__ out)
{
    int row = blockIdx.x;
    int tid = threadIdx.x;
    const float4 xv = *(const float4*)(x + (size_t)row * D + tid * 4);
    __shared__ float red[128];

    red[tid] = xv.x + xv.y + xv.z + xv.w;
    __syncthreads();
    for (int st = 64; st > 0; st >>= 1) {
        if (tid < st) red[tid] += red[tid + st];
        __syncthreads();
    }
    float mu = red[0] * (1.f / D);
    __syncthreads();

    float d0 = xv.x - mu, d1 = xv.y - mu, d2 = xv.z - mu, d3 = xv.w - mu;
    red[tid] = d0*d0 + d1*d1 + d2*d2 + d3*d3;
    __syncthreads();
    for (int st = 64; st > 0; st >>= 1) {
        if (tid < st) red[tid] += red[tid + st];
        __syncthreads();
    }
    float inv = rsqrtf(red[0] * (1.f / D) + EPS);

    const float4 g4 = *(const float4*)(g + tid * 4);
    const float4 b4 = *(const float4*)(b + tid * 4);
    float o0 = d0 * inv * g4.x + b4.x;
    float o1 = d1 * inv * g4.y + b4.y;
    float o2 = d2 * inv * g4.z + b4.z;
    float o3 = d3 * inv * g4.w + b4.w;
    uint2 u; u.x = bf2pack(o0, o1); u.y = bf2pack(o2, o3);
    reinterpret_cast<uint2*>(out + (size_t)row * D)[tid] = u;
}

// ---------------------------------------------------------------------------
// BF16 tensor-core GEMM, cp.async 2-stage pipeline.
// C = A[M,K]@B[K,N] (+bias)(+gelu)(+res). A bf16 (stride lda, lda%8==0,
// cols [K,lda) zero), B bf16 (stride ldb, ldb%8==0, cols [N,ldb) zero).
// Outputs: Cf fp32 (stride N) and/or Cb bf16 (stride ldcb), either may be null.
// flags: 1 = +bias[n], 2 = exact GELU, 4 = +res[m*N+n] (fp32)
// ---------------------------------------------------------------------------
#define BM 128
#define BN 128
#define BKT 32
#define ASTR 40
#define BSTR 136
#define A_ST_BYTES (BM*ASTR*2)
#define B_ST_BYTES (BKT*BSTR*2)

__global__ __launch_bounds__(256) void gemm_bf16_kernel(
    const __nv_bfloat16* __restrict__ A, const __nv_bfloat16* __restrict__ B,
    const float* __restrict__ bias, const float* __restrict__ res,
    float* __restrict__ Cf, __nv_bfloat16* __restrict__ Cb,
    int M, int N, int K, int lda, int ldb, int ldcb, int flags)
{
    __shared__ __align__(16) uint16_t As[2][BM][ASTR];
    __shared__ __align__(16) uint16_t Bs[2][BKT][BSTR];

    const int tid  = threadIdx.x;
    const int lane = tid & 31;
    const int wid  = tid >> 5;
    const int wm   = wid >> 2;           // 0..1
    const int wn   = wid & 3;            // 0..3
    const int lr   = lane >> 2;          // 0..7
    const int lc   = lane & 3;           // 0..3

    const int m0 = blockIdx.y * BM;
    const int n0 = blockIdx.x * BN;

    const int a_r  = (lane & 7) + ((lane >> 3) & 1) * 8;
    const int a_kc = (lane >> 4) * 8;
    const int b_kr = (lane & 7) + ((lane >> 3) & 1) * 8;
    const int b_nc = (lane >> 4) * 8;

    const uint32_t aBase = (uint32_t)__cvta_generic_to_shared(&As[0][0][0]);
    const uint32_t bBase = (uint32_t)__cvta_generic_to_shared(&Bs[0][0][0]);

    float acc[4][4][4];
    #pragma unroll
    for (int i = 0; i < 4; i++)
        #pragma unroll
        for (int j = 0; j < 4; j++)
            #pragma unroll
            for (int r = 0; r < 4; r++) acc[i][j][r] = 0.f;

    const int nkt = (K + BKT - 1) / BKT;

    // cp.async tile loaders. A guarded by lda (pad cols are zeros); byte counts
    // land in {0,16} since lda%8==0. B guarded by K and ldb (pad cols zero).
    auto load_tile = [&](int t, int buf) {
        const int k0 = t * BKT;
        #pragma unroll
        for (int i = 0; i < 2; i++) {
            int c   = tid + i * 256;        // 0..511
            int row = c >> 2;
            int col = (c & 3) * 8;
            int gk  = k0 + col;
            int avail = lda - gk;
            int bytes = (avail <= 0) ? 0 : (avail >= 8 ? 16 : avail * 2);
            const __nv_bfloat16* src = bytes ? (A + (size_t)(m0 + row) * lda + gk) : A;
            uint32_t dst = aBase + buf * A_ST_BYTES + (row * ASTR + col) * 2;
            asm volatile("cp.async.cg.shared.global [%0], [%1], 16, %2;"
                         :: "r"(dst), "l"(src), "r"(bytes));
        }
        #pragma unroll
        for (int i = 0; i < 2; i++) {
            int c   = tid + i * 256;
            int row = c >> 4;               // 0..31
            int col = (c & 15) * 8;         // 0..120
            int gk  = k0 + row;
            int gn  = n0 + col;
            int bytes = (gk < K && gn + 8 <= ldb) ? 16 : 0;
            const __nv_bfloat16* src = bytes ? (B + (size_t)gk * ldb + gn) : B;
            uint32_t dst = bBase + buf * B_ST_BYTES + (row * BSTR + col) * 2;
            asm volatile("cp.async.cg.shared.global [%0], [%1], 16, %2;"
                         :: "r"(dst), "l"(src), "r"(bytes));
        }
        asm volatile("cp.async.commit_group;");
    };

    load_tile(0, 0);

    for (int t = 0; t < nkt; t++) {
        asm volatile("cp.async.wait_group 0;");
        __syncthreads();
        if (t + 1 < nkt) load_tile(t + 1, (t + 1) & 1);

        const int buf = t & 1;
        const uint32_t aB = aBase + buf * A_ST_BYTES;
        const uint32_t bB = bBase + buf * B_ST_BYTES;

        #pragma unroll
        for (int kk = 0; kk < BKT; kk += 16) {
            uint32_t af[4][4];
            #pragma unroll
            for (int mi = 0; mi < 4; mi++) {
                uint32_t addr = aB + ((wm * 64 + mi * 16 + a_r) * ASTR + kk + a_kc) * 2;
                asm volatile(
                    "ldmatrix.sync.aligned.m8n8.x4.shared.b16 {%0,%1,%2,%3}, [%4];"
                    : "=r"(af[mi][0]), "=r"(af[mi][1]),
                      "=r"(af[mi][2]), "=r"(af[mi][3]) : "r"(addr));
            }
            uint32_t bfp[2][4];
            #pragma unroll
            for (int pr = 0; pr < 2; pr++) {
                uint32_t addr = bB + ((kk + b_kr) * BSTR + wn * 32 + pr * 16 + b_nc) * 2;
                asm volatile(
                    "ldmatrix.sync.aligned.m8n8.x4.trans.shared.b16 {%0,%1,%2,%3}, [%4];"
                    : "=r"(bfp[pr][0]), "=r"(bfp[pr][1]),
                      "=r"(bfp[pr][2]), "=r"(bfp[pr][3]) : "r"(addr));
            }
            #pragma unroll
            for (int mi = 0; mi < 4; mi++)
                #pragma unroll
                for (int ni = 0; ni < 4; ni++) {
                    uint32_t b0 = bfp[ni >> 1][(ni & 1) * 2];
                    uint32_t b1 = bfp[ni >> 1][(ni & 1) * 2 + 1];
                    asm volatile(
                        "mma.sync.aligned.m16n8k16.row.col.f32.bf16.bf16.f32 "
                        "{%0,%1,%2,%3}, {%4,%5,%6,%7}, {%8,%9}, {%0,%1,%2,%3};"
                        : "+f"(acc[mi][ni][0]), "+f"(acc[mi][ni][1]),
                          "+f"(acc[mi][ni][2]), "+f"(acc[mi][ni][3])
                        : "r"(af[mi][0]), "r"(af[mi][1]),
                          "r"(af[mi][2]), "r"(af[mi][3]),
                          "r"(b0), "r"(b1));
                }
        }
        __syncthreads();
    }

    // ---- epilogue ----
    #pragma unroll
    for (int mi = 0; mi < 4; mi++) {
        #pragma unroll
        for (int ni = 0; ni < 4; ni++) {
            int row = m0 + wm * 64 + mi * 16 + lr;
            int col = n0 + wn * 32 + ni * 8 + lc * 2;
            float v[4];
            #pragma unroll
            for (int r = 0; r < 4; r++) {
                int rr = row + (r >> 1) * 8;
                int cc = col + (r & 1);
                float x = acc[mi][ni][r];
                if (cc < N) {
                    if (flags & 1) x += bias[cc];
                    if (flags & 2) x = 0.5f * x * (1.f + erff(x * 0.70710678118654752f));
                    if (flags & 4) x += res[(size_t)rr * N + cc];
                    if (Cf) Cf[(size_t)rr * N + cc] = x;
                }
                v[r] = x;
            }
            if (Cb && col + 2 <= N) {
                reinterpret_cast<uint32_t*>(Cb)[((size_t)row * ldcb + col) >> 1]       = bf2pack(v[0], v[1]);
                reinterpret_cast<uint32_t*>(Cb)[((size_t)(row + 8) * ldcb + col) >> 1] = bf2pack(v[2], v[3]);
            }
        }
    }
}

// ---------------------------------------------------------------------------
// Flash attention (fp32 math, fp32 qkv in, bf16 out): grid (T/128, B*H),
// 128 threads; 1 thread = 1 query row.
// ---------------------------------------------------------------------------
__global__ __launch_bounds__(128) void attn_kernel(const float* __restrict__ qkv,
                                                   __nv_bfloat16* __restrict__ out)
{
    const int bh = blockIdx.y;
    const int b  = bh / H;
    const int h  = bh % H;
    const int qi = blockIdx.x * 128 + threadIdx.x;
    const float scale = 0.125f;

    __shared__ float4 Ks[32][16];
    __shared__ float4 Vs[32][16];

    float4 q4[16];
    {
        const float4* qp = (const float4*)(qkv + (size_t)(b * TT + qi) * (3 * H * DH) + h * DH);
        #pragma unroll
        for (int d = 0; d < 16; d++) q4[d] = qp[d];
    }

    float4 o4[16];
    #pragma unroll
    for (int d = 0; d < 16; d++) o4[d] = make_float4(0.f, 0.f, 0.f, 0.f);
    float m = -1e30f, l = 0.f;

    for (int kb = 0; kb < TT / 32; kb++) {
        {
            int base = threadIdx.x * 4;
            #pragma unroll
            for (int e = 0; e < 4; e++) {
                int idx = base + e;
                int j = idx >> 4, d = idx & 15;
                const float4* src = (const float4*)(qkv +
                    (size_t)(b * TT + kb * 32 + j) * (3 * H * DH) + h * DH);
                Ks[j][d] = src[d + (H * DH) / 4];
                Vs[j][d] = src[d + (2 * H * DH) / 4];
            }
        }
        __syncthreads();

        float sj[32];
        float tm = -1e30f;
        #pragma unroll
        for (int j = 0; j < 32; j++) {
            float s = 0.f;
            #pragma unroll
            for (int d = 0; d < 16; d++) {
                float4 k4 = Ks[j][d];
                s = fmaf(q4[d].x, k4.x, s);
                s = fmaf(q4[d].y, k4.y, s);
                s = fmaf(q4[d].z, k4.z, s);
                s = fmaf(q4[d].w, k4.w, s);
            }
            s *= scale;
            sj[j] = s;
            tm = fmaxf(tm, s);
        }
        float m_new = fmaxf(m, tm);
        float corr = __expf(m - m_new);
        l *= corr;
        #pragma unroll
        for (int d = 0; d < 16; d++) {
            o4[d].x *= corr; o4[d].y *= corr; o4[d].z *= corr; o4[d].w *= corr;
        }
        #pragma unroll
        for (int j = 0; j < 32; j++) {
            float p = __expf(sj[j] - m_new);
            l += p;
            #pragma unroll
            for (int d = 0; d < 16; d++) {
                float4 v4 = Vs[j][d];
                o4[d].x = fmaf(p, v4.x, o4[d].x);
                o4[d].y = fmaf(p, v4.y, o4[d].y);
                o4[d].z = fmaf(p, v4.z, o4[d].z);
                o4[d].w = fmaf(p, v4.w, o4[d].w);
            }
        }
        m = m_new;
        __syncthreads();
    }

    float invl = 1.f / l;
    __nv_bfloat16* op = out + (size_t)(b * TT + qi) * (H * DH) + h * DH;
    #pragma unroll
    for (int d = 0; d < 16; d += 2) {
        float4 va = o4[d], vb = o4[d + 1];
        uint4 u;
        u.x = bf2pack(va.x * invl, va.y * invl);
        u.y = bf2pack(va.z * invl, va.w * invl);
        u.z = bf2pack(vb.x * invl, vb.y * invl);
        u.w = bf2pack(vb.z * invl, vb.w * invl);
        reinterpret_cast<uint4*>(op)[d >> 1] = u;
    }
}

// ---------------------------------------------------------------------------
// concat into bf16: dst[r*dstr + c] = [h_bf[r,:512], (bf16)y[r,:nb], 0-pad]
// ---------------------------------------------------------------------------
__global__ void concat_kernel(__nv_bfloat16* __restrict__ dst,
                              const __nv_bfloat16* __restrict__ a,
                              const float* __restrict__ y, int nb, int rows,
                              int dstr)
{
    int total = rows * dstr;
    for (int idx = blockIdx.x * blockDim.x + threadIdx.x; idx < total;
         idx += gridDim.x * blockDim.x) {
        int r = idx / dstr, c = idx - r * dstr;
        __nv_bfloat16 v;
        if (c < D)            v = a[(size_t)r * D + c];
        else if (c < D + nb)  v = __float2bfloat16(y[(size_t)r * nb + (c - D)]);
        else                  v = __float2bfloat16(0.f);
        dst[idx] = v;
    }
}

// ---------------------------------------------------------------------------
// launch
// ---------------------------------------------------------------------------
extern "C" void kernel_launch(void* const* d_in, const int* in_sizes, int n_in,
                              void* d_out, int out_size)
{
    (void)in_sizes; (void)n_in; (void)out_size;

    const float* in_x     = (const float*)d_in[0];
    const float* in_init0 = (const float*)d_in[1];
    const float* in_init1 = (const float*)d_in[2];
    // d_in[3] = mask: constant all-True -> unused
    const float* ln1_g = (const float*)d_in[4];
    const float* ln1_b = (const float*)d_in[5];
    const float* qkv_W = (const float*)d_in[6];
    const float* out_W = (const float*)d_in[7];
    const float* out_b = (const float*)d_in[8];
    const float* ln2_g = (const float*)d_in[9];
    const float* ln2_b = (const float*)d_in[10];
    const float* ff_W1 = (const float*)d_in[11];
    const float* ff_b1 = (const float*)d_in[12];
    const float* ff_W2 = (const float*)d_in[13];
    const float* ff_b2 = (const float*)d_in[14];
    const float* ln3_g = (const float*)d_in[15];
    const float* ln3_b = (const float*)d_in[16];
    const float* r0_W1 = (const float*)d_in[17];
    const float* r0_b1 = (const float*)d_in[18];
    const float* r0_W2 = (const float*)d_in[19];
    const float* r0_b2 = (const float*)d_in[20];
    const float* ln4_g = (const float*)d_in[21];
    const float* ln4_b = (const float*)d_in[22];
    const float* r1_W1 = (const float*)d_in[23];
    const float* r1_b1 = (const float*)d_in[24];
    const float* r1_W2 = (const float*)d_in[25];
    const float* r1_b2 = (const float*)d_in[26];

    float *px, *pqkv;
    __nv_bfloat16 *ph, *po, *pmid, *pcat;
    __nv_bfloat16 *wqkv, *wout, *wff1, *wff2, *wr01, *wr02, *wr11, *wr12;
    cudaGetSymbolAddress((void**)&px,   g_x);
    cudaGetSymbolAddress((void**)&pqkv, g_qkv);
    cudaGetSymbolAddress((void**)&ph,   gb_h);
    cudaGetSymbolAddress((void**)&po,   gb_o);
    cudaGetSymbolAddress((void**)&pmid, gb_mid);
    cudaGetSymbolAddress((void**)&pcat, gb_cat);
    cudaGetSymbolAddress((void**)&wqkv, gb_wqkv);
    cudaGetSymbolAddress((void**)&wout, gb_wout);
    cudaGetSymbolAddress((void**)&wff1, gb_wff1);
    cudaGetSymbolAddress((void**)&wff2, gb_wff2);
    cudaGetSymbolAddress((void**)&wr01, gb_wr01);
    cudaGetSymbolAddress((void**)&wr02, gb_wr02);
    cudaGetSymbolAddress((void**)&wr11, gb_wr11);
    cudaGetSymbolAddress((void**)&wr12, gb_wr12);

    float* y0 = (float*)d_out;                 // [ROWS, O0]
    float* y1 = (float*)d_out + ROWS * O0;     // [ROWS, O1]

    cudaMemcpyAsync(px, in_x,     (size_t)ROWS * D  * sizeof(float), cudaMemcpyDeviceToDevice, 0);
    cudaMemcpyAsync(y0, in_init0, (size_t)ROWS * O0 * sizeof(float), cudaMemcpyDeviceToDevice, 0);
    cudaMemcpyAsync(y1, in_init1, (size_t)ROWS * O1 * sizeof(float), cudaMemcpyDeviceToDevice, 0);

    // ---- weight conversion (fp32 -> padded bf16) ----
    wconv_kernel<<<1024, 256>>>(qkv_W, wqkv, LAYERS * D,   NQKV, NQKV);
    wconv_kernel<<<1024, 256>>>(out_W, wout, LAYERS * D,   D,    D);
    wconv_kernel<<<1024, 256>>>(ff_W1, wff1, LAYERS * D,   MFF,  MFF);
    wconv_kernel<<<1024, 256>>>(ff_W2, wff2, LAYERS * MFF, D,    D);
    wconv_kernel<<<1024, 256>>>(r0_W1, wr01, LAYERS * K0c, MFF,  MFF);
    wconv_kernel<<<1024, 256>>>(r0_W2, wr02, LAYERS * MFF, O0,   LDW02);
    wconv_kernel<<<1024, 256>>>(r1_W1, wr11, LAYERS * K1c, MFF,  MFF);
    wconv_kernel<<<1024, 256>>>(r1_W2, wr12, LAYERS * MFF, O1,   LDW12);

    for (int l = 0; l < LAYERS; l++) {
        // --- attention block ---
        ln_kernel<<<ROWS, 128>>>(px, ln1_g + l * D, ln1_b + l * D, ph);
        gemm_bf16_kernel<<<dim3(NQKV / BN, ROWS / BM), 256>>>(
            ph, wqkv + (size_t)l * D * NQKV, nullptr, nullptr, pqkv, nullptr,
            ROWS, NQKV, D, D, NQKV, 0, 0);
        attn_kernel<<<dim3(TT / 128, BB * H), 128>>>(pqkv, po);
        gemm_bf16_kernel<<<dim3(D / BN, ROWS / BM), 256>>>(
            po, wout + (size_t)l * D * D, out_b + l * D, px, px, nullptr,
            ROWS, D, D, D, D, 0, 1 | 4);

        // --- FFN block ---
        ln_kernel<<<ROWS, 128>>>(px, ln2_g + l * D, ln2_b + l * D, ph);
        gemm_bf16_kernel<<<dim3(MFF / BN, ROWS / BM), 256>>>(
            ph, wff1 + (size_t)l * D * MFF, ff_b1 + l * MFF, nullptr, nullptr, pmid,
            ROWS, MFF, D, D, MFF, MFF, 1 | 2);
        gemm_bf16_kernel<<<dim3(D / BN, ROWS / BM), 256>>>(
            pmid, wff2 + (size_t)l * MFF * D, ff_b2 + l * D, px, px, nullptr,
            ROWS, D, MFF, MFF, D, 0, 1 | 4);

        // --- regressor 0 ---
        ln_kernel<<<ROWS, 128>>>(px, ln3_g + l * D, ln3_b + l * D, ph);
        concat_kernel<<<2048, 256>>>(pcat, ph, y0, O0, ROWS, LDC0);
        gemm_bf16_kernel<<<dim3(MFF / BN, ROWS / BM), 256>>>(
            pcat, wr01 + (size_t)l * K0c * MFF, r0_b1 + l * MFF, nullptr, nullptr, pmid,
            ROWS, MFF, K0c, LDC0, MFF, MFF, 1 | 2);
        gemm_bf16_kernel<<<dim3((O0 + BN - 1) / BN, ROWS / BM), 256>>>(
            pmid, wr02 + (size_t)l * MFF * LDW02, r0_b2 + l * O0, y0, y0, nullptr,
            ROWS, O0, MFF, MFF, LDW02, 0, 1 | 4);

        // --- regressor 1 ---
        ln_kernel<<<ROWS, 128>>>(px, ln4_g + l * D, ln4_b + l * D, ph);
        concat_kernel<<<2048, 256>>>(pcat, ph, y1, O1, ROWS, LDC1);
        gemm_bf16_kernel<<<dim3(MFF / BN, ROWS / BM), 256>>>(
            pcat, wr11 + (size_t)l * K1c * MFF, r1_b1 + l * MFF, nullptr, nullptr, pmid,
            ROWS, MFF, K1c, LDC1, MFF, MFF, 1 | 2);
        gemm_bf16_kernel<<<dim3((O1 + BN - 1) / BN, ROWS / BM), 256>>>(
            pmid, wr12 + (size_t)l * MFF * LDW12, r1_b2 + l * O1, y1, y1, nullptr,
            ROWS, O1, MFF, MFF, LDW12, 0, 1 | 4);
    }
}

// round 9
// speedup vs baseline: 6.0899x; 2.0528x over previous
#include <cuda_runtime.h>
#include <cuda_bf16.h>
#include <math.h>
#include <stdint.h>

// Problem constants
#define LAYERS 2
#define D 512
#define H 8
#define DH 64
#define MFF 2048
#define O0 132
#define O1 3
#define BB 2
#define TT 2048
#define ROWS (BB*TT)          // 4096
#define EPS 1e-5f

#define NQKV 1536
#define K0c 644               // D+O0
#define K1c 515               // D+O1
#define LDC0 648              // cat0 stride (mod 8 == 0)
#define LDC1 520              // cat1 stride (mod 8 == 0)
#define LDW02 136             // r0_W2 padded N stride
#define LDW12 8               // r1_W2 padded N stride

// ---------------------------------------------------------------------------
// Scratch (device globals; no runtime allocation allowed)
// ---------------------------------------------------------------------------
__device__ float g_x  [ROWS * D];          // residual stream (fp32)

__device__ __nv_bfloat16 gb_qkv[ROWS * NQKV];
__device__ __nv_bfloat16 gb_h  [ROWS * D];
__device__ __nv_bfloat16 gb_o  [ROWS * D];
__device__ __nv_bfloat16 gb_mid[ROWS * MFF];
__device__ __nv_bfloat16 gb_cat[ROWS * LDC0];

__device__ __nv_bfloat16 gb_wqkv[LAYERS * D * NQKV];
__device__ __nv_bfloat16 gb_wout[LAYERS * D * D];
__device__ __nv_bfloat16 gb_wff1[LAYERS * D * MFF];
__device__ __nv_bfloat16 gb_wff2[LAYERS * MFF * D];
__device__ __nv_bfloat16 gb_wr01[LAYERS * K0c * MFF];
__device__ __nv_bfloat16 gb_wr02[LAYERS * MFF * LDW02];
__device__ __nv_bfloat16 gb_wr11[LAYERS * K1c * MFF];
__device__ __nv_bfloat16 gb_wr12[LAYERS * MFF * LDW12];

__device__ __forceinline__ uint32_t bf2pack(float lo, float hi) {
    __nv_bfloat162 h = __floats2bfloat162_rn(lo, hi);
    return *reinterpret_cast<uint32_t*>(&h);
}

__device__ __forceinline__ float ex2f(float x) {
    float y;
    asm("ex2.approx.f32 %0, %1;" : "=f"(y) : "f"(x));
    return y;
}

#define MMA_BF16(acc, a, b0v, b1v)                                          \
    asm volatile(                                                           \
        "mma.sync.aligned.m16n8k16.row.col.f32.bf16.bf16.f32 "              \
        "{%0,%1,%2,%3}, {%4,%5,%6,%7}, {%8,%9}, {%0,%1,%2,%3};"             \
        : "+f"((acc)[0]), "+f"((acc)[1]), "+f"((acc)[2]), "+f"((acc)[3])    \
        : "r"((a)[0]), "r"((a)[1]), "r"((a)[2]), "r"((a)[3]),               \
          "r"(b0v), "r"(b1v))

// ---------------------------------------------------------------------------
// Weight fp32 -> bf16 with padded/zeroed N stride
// ---------------------------------------------------------------------------
__global__ void wconv_kernel(const float* __restrict__ src,
                             __nv_bfloat16* __restrict__ dst,
                             int rows, int N, int ldb)
{
    int half = ldb >> 1;
    int total = rows * half;
    for (int idx = blockIdx.x * blockDim.x + threadIdx.x; idx < total;
         idx += gridDim.x * blockDim.x) {
        int r = idx / half;
        int c = (idx - r * half) * 2;
        float v0 = (c     < N) ? src[(size_t)r * N + c]     : 0.f;
        float v1 = (c + 1 < N) ? src[(size_t)r * N + c + 1] : 0.f;
        reinterpret_cast<uint32_t*>(dst)[(size_t)r * half + (c >> 1)] = bf2pack(v0, v1);
    }
}

// ---------------------------------------------------------------------------
// LayerNorm: one block per row, 128 threads, D=512; bf16 output
// ---------------------------------------------------------------------------
__global__ __launch_bounds__(128) void ln_kernel(const float* __restrict__ x,
                                                 const float* __restrict__ g,
                                                 const float* __restrict__ b,
                                                 __nv_bfloat16* __restrict__ out)
{
    int row = blockIdx.x;
    int tid = threadIdx.x;
    const float4 xv = *(const float4*)(x + (size_t)row * D + tid * 4);
    __shared__ float red[128];

    red[tid] = xv.x + xv.y + xv.z + xv.w;
    __syncthreads();
    for (int st = 64; st > 0; st >>= 1) {
        if (tid < st) red[tid] += red[tid + st];
        __syncthreads();
    }
    float mu = red[0] * (1.f / D);
    __syncthreads();

    float d0 = xv.x - mu, d1 = xv.y - mu, d2 = xv.z - mu, d3 = xv.w - mu;
    red[tid] = d0*d0 + d1*d1 + d2*d2 + d3*d3;
    __syncthreads();
    for (int st = 64; st > 0; st >>= 1) {
        if (tid < st) red[tid] += red[tid + st];
        __syncthreads();
    }
    float inv = rsqrtf(red[0] * (1.f / D) + EPS);

    const float4 g4 = *(const float4*)(g + tid * 4);
    const float4 b4 = *(const float4*)(b + tid * 4);
    float o0 = d0 * inv * g4.x + b4.x;
    float o1 = d1 * inv * g4.y + b4.y;
    float o2 = d2 * inv * g4.z + b4.z;
    float o3 = d3 * inv * g4.w + b4.w;
    uint2 u; u.x = bf2pack(o0, o1); u.y = bf2pack(o2, o3);
    reinterpret_cast<uint2*>(out + (size_t)row * D)[tid] = u;
}

// ---------------------------------------------------------------------------
// BF16 tensor-core GEMM, cp.async 2-stage pipeline.  (verified in Round 8)
// ---------------------------------------------------------------------------
#define BM 128
#define BN 128
#define BKT 32
#define ASTR 40
#define BSTR 136
#define A_ST_BYTES (BM*ASTR*2)
#define B_ST_BYTES (BKT*BSTR*2)

__global__ __launch_bounds__(256) void gemm_bf16_kernel(
    const __nv_bfloat16* __restrict__ A, const __nv_bfloat16* __restrict__ B,
    const float* __restrict__ bias, const float* __restrict__ res,
    float* __restrict__ Cf, __nv_bfloat16* __restrict__ Cb,
    int M, int N, int K, int lda, int ldb, int ldcb, int flags)
{
    __shared__ __align__(16) uint16_t As[2][BM][ASTR];
    __shared__ __align__(16) uint16_t Bs[2][BKT][BSTR];

    const int tid  = threadIdx.x;
    const int lane = tid & 31;
    const int wid  = tid >> 5;
    const int wm   = wid >> 2;
    const int wn   = wid & 3;
    const int lr   = lane >> 2;
    const int lc   = lane & 3;

    const int m0 = blockIdx.y * BM;
    const int n0 = blockIdx.x * BN;

    const int a_r  = (lane & 7) + ((lane >> 3) & 1) * 8;
    const int a_kc = (lane >> 4) * 8;
    const int b_kr = (lane & 7) + ((lane >> 3) & 1) * 8;
    const int b_nc = (lane >> 4) * 8;

    const uint32_t aBase = (uint32_t)__cvta_generic_to_shared(&As[0][0][0]);
    const uint32_t bBase = (uint32_t)__cvta_generic_to_shared(&Bs[0][0][0]);

    float acc[4][4][4];
    #pragma unroll
    for (int i = 0; i < 4; i++)
        #pragma unroll
        for (int j = 0; j < 4; j++)
            #pragma unroll
            for (int r = 0; r < 4; r++) acc[i][j][r] = 0.f;

    const int nkt = (K + BKT - 1) / BKT;

    auto load_tile = [&](int t, int buf) {
        const int k0 = t * BKT;
        #pragma unroll
        for (int i = 0; i < 2; i++) {
            int c   = tid + i * 256;
            int row = c >> 2;
            int col = (c & 3) * 8;
            int gk  = k0 + col;
            int avail = lda - gk;
            int bytes = (avail <= 0) ? 0 : (avail >= 8 ? 16 : avail * 2);
            const __nv_bfloat16* src = bytes ? (A + (size_t)(m0 + row) * lda + gk) : A;
            uint32_t dst = aBase + buf * A_ST_BYTES + (row * ASTR + col) * 2;
            asm volatile("cp.async.cg.shared.global [%0], [%1], 16, %2;"
                         :: "r"(dst), "l"(src), "r"(bytes));
        }
        #pragma unroll
        for (int i = 0; i < 2; i++) {
            int c   = tid + i * 256;
            int row = c >> 4;
            int col = (c & 15) * 8;
            int gk  = k0 + row;
            int gn  = n0 + col;
            int bytes = (gk < K && gn + 8 <= ldb) ? 16 : 0;
            const __nv_bfloat16* src = bytes ? (B + (size_t)gk * ldb + gn) : B;
            uint32_t dst = bBase + buf * B_ST_BYTES + (row * BSTR + col) * 2;
            asm volatile("cp.async.cg.shared.global [%0], [%1], 16, %2;"
                         :: "r"(dst), "l"(src), "r"(bytes));
        }
        asm volatile("cp.async.commit_group;");
    };

    load_tile(0, 0);

    for (int t = 0; t < nkt; t++) {
        asm volatile("cp.async.wait_group 0;");
        __syncthreads();
        if (t + 1 < nkt) load_tile(t + 1, (t + 1) & 1);

        const int buf = t & 1;
        const uint32_t aB = aBase + buf * A_ST_BYTES;
        const uint32_t bB = bBase + buf * B_ST_BYTES;

        #pragma unroll
        for (int kk = 0; kk < BKT; kk += 16) {
            uint32_t af[4][4];
            #pragma unroll
            for (int mi = 0; mi < 4; mi++) {
                uint32_t addr = aB + ((wm * 64 + mi * 16 + a_r) * ASTR + kk + a_kc) * 2;
                asm volatile(
                    "ldmatrix.sync.aligned.m8n8.x4.shared.b16 {%0,%1,%2,%3}, [%4];"
                    : "=r"(af[mi][0]), "=r"(af[mi][1]),
                      "=r"(af[mi][2]), "=r"(af[mi][3]) : "r"(addr));
            }
            uint32_t bfp[2][4];
            #pragma unroll
            for (int pr = 0; pr < 2; pr++) {
                uint32_t addr = bB + ((kk + b_kr) * BSTR + wn * 32 + pr * 16 + b_nc) * 2;
                asm volatile(
                    "ldmatrix.sync.aligned.m8n8.x4.trans.shared.b16 {%0,%1,%2,%3}, [%4];"
                    : "=r"(bfp[pr][0]), "=r"(bfp[pr][1]),
                      "=r"(bfp[pr][2]), "=r"(bfp[pr][3]) : "r"(addr));
            }
            #pragma unroll
            for (int mi = 0; mi < 4; mi++)
                #pragma unroll
                for (int ni = 0; ni < 4; ni++) {
                    uint32_t b0 = bfp[ni >> 1][(ni & 1) * 2];
                    uint32_t b1 = bfp[ni >> 1][(ni & 1) * 2 + 1];
                    MMA_BF16(acc[mi][ni], af[mi], b0, b1);
                }
        }
        __syncthreads();
    }

    #pragma unroll
    for (int mi = 0; mi < 4; mi++) {
        #pragma unroll
        for (int ni = 0; ni < 4; ni++) {
            int row = m0 + wm * 64 + mi * 16 + lr;
            int col = n0 + wn * 32 + ni * 8 + lc * 2;
            float v[4];
            #pragma unroll
            for (int r = 0; r < 4; r++) {
                int rr = row + (r >> 1) * 8;
                int cc = col + (r & 1);
                float x = acc[mi][ni][r];
                if (cc < N) {
                    if (flags & 1) x += bias[cc];
                    if (flags & 2) x = 0.5f * x * (1.f + erff(x * 0.70710678118654752f));
                    if (flags & 4) x += res[(size_t)rr * N + cc];
                    if (Cf) Cf[(size_t)rr * N + cc] = x;
                }
                v[r] = x;
            }
            if (Cb && col + 2 <= N) {
                reinterpret_cast<uint32_t*>(Cb)[((size_t)row * ldcb + col) >> 1]       = bf2pack(v[0], v[1]);
                reinterpret_cast<uint32_t*>(Cb)[((size_t)(row + 8) * ldcb + col) >> 1] = bf2pack(v[2], v[3]);
            }
        }
    }
}

// ---------------------------------------------------------------------------
// Tensor-core flash attention (bf16 in/out, fp32 accum, exp2-domain softmax).
// grid (T/128, B*H), 256 threads (8 warps x 16 query rows). KV tiles of 64
// keys double-buffered in smem (stride 72 -> ldmatrix conflict-free).
// ---------------------------------------------------------------------------
#define KSTR 72
#define KV_ST_BYTES (64*KSTR*2)

__global__ __launch_bounds__(256) void attn_kernel(
    const __nv_bfloat16* __restrict__ qkv, __nv_bfloat16* __restrict__ out)
{
    __shared__ __align__(16) uint16_t Ks[2][64][KSTR];
    __shared__ __align__(16) uint16_t Vs[2][64][KSTR];

    const int tid  = threadIdx.x;
    const int lane = tid & 31;
    const int w    = tid >> 5;
    const int gid  = lane >> 2;        // 0..7
    const int tq   = lane & 3;         // 0..3
    const int qb   = blockIdx.x * 128;
    const int b    = blockIdx.y >> 3;  // H == 8
    const int h    = blockIdx.y & 7;

    // Q fragments straight from gmem (bf16 qkv, row stride NQKV)
    uint32_t qf[4][4];
    {
        const uint16_t* q0 = (const uint16_t*)qkv +
            (size_t)(b * TT + qb + w * 16 + gid) * NQKV + h * DH;
        const uint16_t* q1 = q0 + (size_t)8 * NQKV;
        #pragma unroll
        for (int ks = 0; ks < 4; ks++) {
            qf[ks][0] = *(const uint32_t*)(q0 + ks * 16 + tq * 2);
            qf[ks][1] = *(const uint32_t*)(q1 + ks * 16 + tq * 2);
            qf[ks][2] = *(const uint32_t*)(q0 + ks * 16 + 8 + tq * 2);
            qf[ks][3] = *(const uint32_t*)(q1 + ks * 16 + 8 + tq * 2);
        }
    }

    const uint32_t kBase = (uint32_t)__cvta_generic_to_shared(&Ks[0][0][0]);
    const uint32_t vBase = (uint32_t)__cvta_generic_to_shared(&Vs[0][0][0]);

    float oacc[8][4];
    #pragma unroll
    for (int i = 0; i < 8; i++)
        #pragma unroll
        for (int j = 0; j < 4; j++) oacc[i][j] = 0.f;
    float m0 = -1e30f, m1 = -1e30f, l0 = 0.f, l1 = 0.f;

    auto load_kv = [&](int t, int buf) {
        #pragma unroll
        for (int i = 0; i < 2; i++) {
            int idx = tid + i * 256;        // 0..511
            int row = idx >> 3;             // 0..63
            int ch  = (idx & 7) * 8;        // 0..56
            const uint16_t* src = (const uint16_t*)qkv +
                (size_t)(b * TT + t * 64 + row) * NQKV + h * DH + ch;
            uint32_t kd = kBase + buf * KV_ST_BYTES + (row * KSTR + ch) * 2;
            uint32_t vd = vBase + buf * KV_ST_BYTES + (row * KSTR + ch) * 2;
            asm volatile("cp.async.cg.shared.global [%0], [%1], 16;"
                         :: "r"(kd), "l"(src + 512) : "memory");
            asm volatile("cp.async.cg.shared.global [%0], [%1], 16;"
                         :: "r"(vd), "l"(src + 1024) : "memory");
        }
        asm volatile("cp.async.commit_group;");
    };

    load_kv(0, 0);

    const float sc = 0.125f * 1.4426950408889634f;  // scale * log2(e)

    for (int t = 0; t < TT / 64; t++) {
        asm volatile("cp.async.wait_group 0;");
        __syncthreads();
        if (t + 1 < TT / 64) load_kv(t + 1, (t + 1) & 1);

        const uint32_t kB = kBase + (t & 1) * KV_ST_BYTES;
        const uint32_t vB = vBase + (t & 1) * KV_ST_BYTES;

        // ---- S = Q @ K^T ----
        float sacc[8][4];
        #pragma unroll
        for (int i = 0; i < 8; i++)
            #pragma unroll
            for (int j = 0; j < 4; j++) sacc[i][j] = 0.f;

        #pragma unroll
        for (int np = 0; np < 4; np++) {
            #pragma unroll
            for (int ks = 0; ks < 4; ks++) {
                uint32_t kb[4];
                uint32_t addr = kB +
                    ((np * 16 + (lane & 7) + ((lane >> 4) & 1) * 8) * KSTR +
                     ks * 16 + ((lane >> 3) & 1) * 8) * 2;
                asm volatile(
                    "ldmatrix.sync.aligned.m8n8.x4.shared.b16 {%0,%1,%2,%3}, [%4];"
                    : "=r"(kb[0]), "=r"(kb[1]), "=r"(kb[2]), "=r"(kb[3]) : "r"(addr));
                MMA_BF16(sacc[np * 2],     qf[ks], kb[0], kb[1]);
                MMA_BF16(sacc[np * 2 + 1], qf[ks], kb[2], kb[3]);
            }
        }

        // ---- online softmax (log2 domain) ----
        float mx0 = -1e30f, mx1 = -1e30f;
        #pragma unroll
        for (int ni = 0; ni < 8; ni++) {
            sacc[ni][0] *= sc; sacc[ni][1] *= sc;
            sacc[ni][2] *= sc; sacc[ni][3] *= sc;
            mx0 = fmaxf(mx0, fmaxf(sacc[ni][0], sacc[ni][1]));
            mx1 = fmaxf(mx1, fmaxf(sacc[ni][2], sacc[ni][3]));
        }
        mx0 = fmaxf(mx0, __shfl_xor_sync(0xffffffff, mx0, 1));
        mx0 = fmaxf(mx0, __shfl_xor_sync(0xffffffff, mx0, 2));
        mx1 = fmaxf(mx1, __shfl_xor_sync(0xffffffff, mx1, 1));
        mx1 = fmaxf(mx1, __shfl_xor_sync(0xffffffff, mx1, 2));

        float m0n = fmaxf(m0, mx0), m1n = fmaxf(m1, mx1);
        float c0 = ex2f(m0 - m0n), c1 = ex2f(m1 - m1n);
        float s0 = 0.f, s1 = 0.f;
        #pragma unroll
        for (int ni = 0; ni < 8; ni++) {
            float p0 = ex2f(sacc[ni][0] - m0n);
            float p1 = ex2f(sacc[ni][1] - m0n);
            float p2 = ex2f(sacc[ni][2] - m1n);
            float p3 = ex2f(sacc[ni][3] - m1n);
            sacc[ni][0] = p0; sacc[ni][1] = p1;
            sacc[ni][2] = p2; sacc[ni][3] = p3;
            s0 += p0 + p1; s1 += p2 + p3;
        }
        s0 += __shfl_xor_sync(0xffffffff, s0, 1);
        s0 += __shfl_xor_sync(0xffffffff, s0, 2);
        s1 += __shfl_xor_sync(0xffffffff, s1, 1);
        s1 += __shfl_xor_sync(0xffffffff, s1, 2);
        l0 = l0 * c0 + s0;
        l1 = l1 * c1 + s1;
        m0 = m0n; m1 = m1n;
        #pragma unroll
        for (int nj = 0; nj < 8; nj++) {
            oacc[nj][0] *= c0; oacc[nj][1] *= c0;
            oacc[nj][2] *= c1; oacc[nj][3] *= c1;
        }

        // ---- P fragments (S-accumulator -> A fragment) ----
        uint32_t aP[4][4];
        #pragma unroll
        for (int ks = 0; ks < 4; ks++) {
            aP[ks][0] = bf2pack(sacc[2*ks][0],     sacc[2*ks][1]);
            aP[ks][1] = bf2pack(sacc[2*ks][2],     sacc[2*ks][3]);
            aP[ks][2] = bf2pack(sacc[2*ks + 1][0], sacc[2*ks + 1][1]);
            aP[ks][3] = bf2pack(sacc[2*ks + 1][2], sacc[2*ks + 1][3]);
        }

        // ---- O += P @ V ----
        #pragma unroll
        for (int np = 0; np < 4; np++) {
            #pragma unroll
            for (int ks = 0; ks < 4; ks++) {
                uint32_t vb[4];
                uint32_t addr = vB +
                    ((ks * 16 + (lane & 7) + ((lane >> 3) & 1) * 8) * KSTR +
                     np * 16 + ((lane >> 4) & 1) * 8) * 2;
                asm volatile(
                    "ldmatrix.sync.aligned.m8n8.x4.trans.shared.b16 {%0,%1,%2,%3}, [%4];"
                    : "=r"(vb[0]), "=r"(vb[1]), "=r"(vb[2]), "=r"(vb[3]) : "r"(addr));
                MMA_BF16(oacc[np * 2],     aP[ks], vb[0], vb[1]);
                MMA_BF16(oacc[np * 2 + 1], aP[ks], vb[2], vb[3]);
            }
        }
    }

    // ---- write O (bf16, row stride D) ----
    float i0 = 1.f / l0, i1 = 1.f / l1;
    uint16_t* o0 = (uint16_t*)out + (size_t)(b * TT + qb + w * 16 + gid) * D + h * DH;
    uint16_t* o1 = o0 + (size_t)8 * D;
    #pragma unroll
    for (int nj = 0; nj < 8; nj++) {
        *(uint32_t*)(o0 + nj * 8 + tq * 2) = bf2pack(oacc[nj][0] * i0, oacc[nj][1] * i0);
        *(uint32_t*)(o1 + nj * 8 + tq * 2) = bf2pack(oacc[nj][2] * i1, oacc[nj][3] * i1);
    }
}

// ---------------------------------------------------------------------------
// concat into bf16: dst[r*dstr + c] = [h_bf[r,:512], (bf16)y[r,:nb], 0-pad]
// ---------------------------------------------------------------------------
__global__ void concat_kernel(__nv_bfloat16* __restrict__ dst,
                              const __nv_bfloat16* __restrict__ a,
                              const float* __restrict__ y, int nb, int rows,
                              int dstr)
{
    int total = rows * dstr;
    for (int idx = blockIdx.x * blockDim.x + threadIdx.x; idx < total;
         idx += gridDim.x * blockDim.x) {
        int r = idx / dstr, c = idx - r * dstr;
        __nv_bfloat16 v;
        if (c < D)            v = a[(size_t)r * D + c];
        else if (c < D + nb)  v = __float2bfloat16(y[(size_t)r * nb + (c - D)]);
        else                  v = __float2bfloat16(0.f);
        dst[idx] = v;
    }
}

// ---------------------------------------------------------------------------
// launch
// ---------------------------------------------------------------------------
extern "C" void kernel_launch(void* const* d_in, const int* in_sizes, int n_in,
                              void* d_out, int out_size)
{
    (void)in_sizes; (void)n_in; (void)out_size;

    const float* in_x     = (const float*)d_in[0];
    const float* in_init0 = (const float*)d_in[1];
    const float* in_init1 = (const float*)d_in[2];
    // d_in[3] = mask: constant all-True -> unused
    const float* ln1_g = (const float*)d_in[4];
    const float* ln1_b = (const float*)d_in[5];
    const float* qkv_W = (const float*)d_in[6];
    const float* out_W = (const float*)d_in[7];
    const float* out_b = (const float*)d_in[8];
    const float* ln2_g = (const float*)d_in[9];
    const float* ln2_b = (const float*)d_in[10];
    const float* ff_W1 = (const float*)d_in[11];
    const float* ff_b1 = (const float*)d_in[12];
    const float* ff_W2 = (const float*)d_in[13];
    const float* ff_b2 = (const float*)d_in[14];
    const float* ln3_g = (const float*)d_in[15];
    const float* ln3_b = (const float*)d_in[16];
    const float* r0_W1 = (const float*)d_in[17];
    const float* r0_b1 = (const float*)d_in[18];
    const float* r0_W2 = (const float*)d_in[19];
    const float* r0_b2 = (const float*)d_in[20];
    const float* ln4_g = (const float*)d_in[21];
    const float* ln4_b = (const float*)d_in[22];
    const float* r1_W1 = (const float*)d_in[23];
    const float* r1_b1 = (const float*)d_in[24];
    const float* r1_W2 = (const float*)d_in[25];
    const float* r1_b2 = (const float*)d_in[26];

    float *px;
    __nv_bfloat16 *pqkv, *ph, *po, *pmid, *pcat;
    __nv_bfloat16 *wqkv, *wout, *wff1, *wff2, *wr01, *wr02, *wr11, *wr12;
    cudaGetSymbolAddress((void**)&px,   g_x);
    cudaGetSymbolAddress((void**)&pqkv, gb_qkv);
    cudaGetSymbolAddress((void**)&ph,   gb_h);
    cudaGetSymbolAddress((void**)&po,   gb_o);
    cudaGetSymbolAddress((void**)&pmid, gb_mid);
    cudaGetSymbolAddress((void**)&pcat, gb_cat);
    cudaGetSymbolAddress((void**)&wqkv, gb_wqkv);
    cudaGetSymbolAddress((void**)&wout, gb_wout);
    cudaGetSymbolAddress((void**)&wff1, gb_wff1);
    cudaGetSymbolAddress((void**)&wff2, gb_wff2);
    cudaGetSymbolAddress((void**)&wr01, gb_wr01);
    cudaGetSymbolAddress((void**)&wr02, gb_wr02);
    cudaGetSymbolAddress((void**)&wr11, gb_wr11);
    cudaGetSymbolAddress((void**)&wr12, gb_wr12);

    float* y0 = (float*)d_out;                 // [ROWS, O0]
    float* y1 = (float*)d_out + ROWS * O0;     // [ROWS, O1]

    cudaMemcpyAsync(px, in_x,     (size_t)ROWS * D  * sizeof(float), cudaMemcpyDeviceToDevice, 0);
    cudaMemcpyAsync(y0, in_init0, (size_t)ROWS * O0 * sizeof(float), cudaMemcpyDeviceToDevice, 0);
    cudaMemcpyAsync(y1, in_init1, (size_t)ROWS * O1 * sizeof(float), cudaMemcpyDeviceToDevice, 0);

    // ---- weight conversion (fp32 -> padded bf16) ----
    wconv_kernel<<<1024, 256>>>(qkv_W, wqkv, LAYERS * D,   NQKV, NQKV);
    wconv_kernel<<<1024, 256>>>(out_W, wout, LAYERS * D,   D,    D);
    wconv_kernel<<<1024, 256>>>(ff_W1, wff1, LAYERS * D,   MFF,  MFF);
    wconv_kernel<<<1024, 256>>>(ff_W2, wff2, LAYERS * MFF, D,    D);
    wconv_kernel<<<1024, 256>>>(r0_W1, wr01, LAYERS * K0c, MFF,  MFF);
    wconv_kernel<<<1024, 256>>>(r0_W2, wr02, LAYERS * MFF, O0,   LDW02);
    wconv_kernel<<<1024, 256>>>(r1_W1, wr11, LAYERS * K1c, MFF,  MFF);
    wconv_kernel<<<1024, 256>>>(r1_W2, wr12, LAYERS * MFF, O1,   LDW12);

    for (int l = 0; l < LAYERS; l++) {
        // --- attention block ---
        ln_kernel<<<ROWS, 128>>>(px, ln1_g + l * D, ln1_b + l * D, ph);
        gemm_bf16_kernel<<<dim3(NQKV / BN, ROWS / BM), 256>>>(
            ph, wqkv + (size_t)l * D * NQKV, nullptr, nullptr, nullptr, pqkv,
            ROWS, NQKV, D, D, NQKV, NQKV, 0);
        attn_kernel<<<dim3(TT / 128, BB * H), 256>>>(pqkv, po);
        gemm_bf16_kernel<<<dim3(D / BN, ROWS / BM), 256>>>(
            po, wout + (size_t)l * D * D, out_b + l * D, px, px, nullptr,
            ROWS, D, D, D, D, 0, 1 | 4);

        // --- FFN block ---
        ln_kernel<<<ROWS, 128>>>(px, ln2_g + l * D, ln2_b + l * D, ph);
        gemm_bf16_kernel<<<dim3(MFF / BN, ROWS / BM), 256>>>(
            ph, wff1 + (size_t)l * D * MFF, ff_b1 + l * MFF, nullptr, nullptr, pmid,
            ROWS, MFF, D, D, MFF, MFF, 1 | 2);
        gemm_bf16_kernel<<<dim3(D / BN, ROWS / BM), 256>>>(
            pmid, wff2 + (size_t)l * MFF * D, ff_b2 + l * D, px, px, nullptr,
            ROWS, D, MFF, MFF, D, 0, 1 | 4);

        // --- regressor 0 ---
        ln_kernel<<<ROWS, 128>>>(px, ln3_g + l * D, ln3_b + l * D, ph);
        concat_kernel<<<2048, 256>>>(pcat, ph, y0, O0, ROWS, LDC0);
        gemm_bf16_kernel<<<dim3(MFF / BN, ROWS / BM), 256>>>(
            pcat, wr01 + (size_t)l * K0c * MFF, r0_b1 + l * MFF, nullptr, nullptr, pmid,
            ROWS, MFF, K0c, LDC0, MFF, MFF, 1 | 2);
        gemm_bf16_kernel<<<dim3((O0 + BN - 1) / BN, ROWS / BM), 256>>>(
            pmid, wr02 + (size_t)l * MFF * LDW02, r0_b2 + l * O0, y0, y0, nullptr,
            ROWS, O0, MFF, MFF, LDW02, 0, 1 | 4);

        // --- regressor 1 ---
        ln_kernel<<<ROWS, 128>>>(px, ln4_g + l * D, ln4_b + l * D, ph);
        concat_kernel<<<2048, 256>>>(pcat, ph, y1, O1, ROWS, LDC1);
        gemm_bf16_kernel<<<dim3(MFF / BN, ROWS / BM), 256>>>(
            pcat, wr11 + (size_t)l * K1c * MFF, r1_b1 + l * MFF, nullptr, nullptr, pmid,
            ROWS, MFF, K1c, LDC1, MFF, MFF, 1 | 2);
        gemm_bf16_kernel<<<dim3((O1 + BN - 1) / BN, ROWS / BM), 256>>>(
            pmid, wr12 + (size_t)l * MFF * LDW12, r1_b2 + l * O1, y1, y1, nullptr,
            ROWS, O1, MFF, MFF, LDW12, 0, 1 | 4);
    }
}

// round 12
// speedup vs baseline: 6.8913x; 1.1316x over previous
#include <cuda_runtime.h>
#include <cuda_bf16.h>
#include <math.h>
#include <stdint.h>

// Problem constants
#define LAYERS 2
#define D 512
#define H 8
#define DH 64
#define MFF 2048
#define O0 132
#define O1 3
#define BB 2
#define TT 2048
#define ROWS (BB*TT)          // 4096
#define EPS 1e-5f

#define NQKV 1536
#define K0c 644               // D+O0
#define K1c 515               // D+O1
#define LDC0 648              // cat0 stride (mod 8 == 0)
#define LDC1 520              // cat1 stride (mod 8 == 0)
#define LDW02 136             // r0_W2 padded N stride

// ---------------------------------------------------------------------------
// Scratch (device globals; no runtime allocation allowed)
// ---------------------------------------------------------------------------
__device__ float g_x  [ROWS * D];          // residual stream (fp32)

__device__ __nv_bfloat16 gb_qkv[ROWS * NQKV];
__device__ __nv_bfloat16 gb_h  [ROWS * D];
__device__ __nv_bfloat16 gb_o  [ROWS * D];
__device__ __nv_bfloat16 gb_mid[ROWS * MFF];
__device__ __nv_bfloat16 gb_cat[ROWS * LDC0];

__device__ __nv_bfloat16 gb_wqkv[LAYERS * D * NQKV];
__device__ __nv_bfloat16 gb_wout[LAYERS * D * D];
__device__ __nv_bfloat16 gb_wff1[LAYERS * D * MFF];
__device__ __nv_bfloat16 gb_wff2[LAYERS * MFF * D];
__device__ __nv_bfloat16 gb_wr01[LAYERS * K0c * MFF];
__device__ __nv_bfloat16 gb_wr02[LAYERS * MFF * LDW02];
__device__ __nv_bfloat16 gb_wr11[LAYERS * K1c * MFF];

__device__ __forceinline__ uint32_t bf2pack(float lo, float hi) {
    __nv_bfloat162 h = __floats2bfloat162_rn(lo, hi);
    return *reinterpret_cast<uint32_t*>(&h);
}

__device__ __forceinline__ float2 bfunpack(uint32_t u) {
    __nv_bfloat162 h = *reinterpret_cast<__nv_bfloat162*>(&u);
    return __bfloat1622float2(h);
}

__device__ __forceinline__ float ex2f(float x) {
    float y;
    asm("ex2.approx.f32 %0, %1;" : "=f"(y) : "f"(x));
    return y;
}

#define MMA_BF16(acc, a, b0v, b1v)                                          \
    asm volatile(                                                           \
        "mma.sync.aligned.m16n8k16.row.col.f32.bf16.bf16.f32 "              \
        "{%0,%1,%2,%3}, {%4,%5,%6,%7}, {%8,%9}, {%0,%1,%2,%3};"             \
        : "+f"((acc)[0]), "+f"((acc)[1]), "+f"((acc)[2]), "+f"((acc)[3])    \
        : "r"((a)[0]), "r"((a)[1]), "r"((a)[2]), "r"((a)[3]),               \
          "r"(b0v), "r"(b1v))

// ---------------------------------------------------------------------------
// Weight fp32 -> bf16 with padded/zeroed N stride (fast path when no pad)
// ---------------------------------------------------------------------------
__global__ void wconv_kernel(const float* __restrict__ src,
                             __nv_bfloat16* __restrict__ dst,
                             int rows, int N, int ldb)
{
    if (N == ldb && (N & 7) == 0) {
        // vectorized copy-convert: 8 values per thread-iteration
        int total8 = rows * (N >> 3);
        for (int idx = blockIdx.x * blockDim.x + threadIdx.x; idx < total8;
             idx += gridDim.x * blockDim.x) {
            const float4* s = (const float4*)(src + (size_t)idx * 8);
            float4 a = s[0], b2 = s[1];
            uint4 u;
            u.x = bf2pack(a.x, a.y);   u.y = bf2pack(a.z, a.w);
            u.z = bf2pack(b2.x, b2.y); u.w = bf2pack(b2.z, b2.w);
            reinterpret_cast<uint4*>(dst)[idx] = u;
        }
        return;
    }
    int half = ldb >> 1;
    int total = rows * half;
    for (int idx = blockIdx.x * blockDim.x + threadIdx.x; idx < total;
         idx += gridDim.x * blockDim.x) {
        int r = idx / half;
        int c = (idx - r * half) * 2;
        float v0 = (c     < N) ? src[(size_t)r * N + c]     : 0.f;
        float v1 = (c + 1 < N) ? src[(size_t)r * N + c + 1] : 0.f;
        reinterpret_cast<uint32_t*>(dst)[(size_t)r * half + (c >> 1)] = bf2pack(v0, v1);
    }
}

// ---------------------------------------------------------------------------
// LayerNorm: one block per row, 128 threads, D=512; bf16 output
// ---------------------------------------------------------------------------
__global__ __launch_bounds__(128) void ln_kernel(const float* __restrict__ x,
                                                 const float* __restrict__ g,
                                                 const float* __restrict__ b,
                                                 __nv_bfloat16* __restrict__ out)
{
    int row = blockIdx.x;
    int tid = threadIdx.x;
    const float4 xv = *(const float4*)(x + (size_t)row * D + tid * 4);
    __shared__ float red[128];

    red[tid] = xv.x + xv.y + xv.z + xv.w;
    __syncthreads();
    for (int st = 64; st > 0; st >>= 1) {
        if (tid < st) red[tid] += red[tid + st];
        __syncthreads();
    }
    float mu = red[0] * (1.f / D);
    __syncthreads();

    float d0 = xv.x - mu, d1 = xv.y - mu, d2 = xv.z - mu, d3 = xv.w - mu;
    red[tid] = d0*d0 + d1*d1 + d2*d2 + d3*d3;
    __syncthreads();
    for (int st = 64; st > 0; st >>= 1) {
        if (tid < st) red[tid] += red[tid + st];
        __syncthreads();
    }
    float inv = rsqrtf(red[0] * (1.f / D) + EPS);

    const float4 g4 = *(const float4*)(g + tid * 4);
    const float4 b4 = *(const float4*)(b + tid * 4);
    float o0 = d0 * inv * g4.x + b4.x;
    float o1 = d1 * inv * g4.y + b4.y;
    float o2 = d2 * inv * g4.z + b4.z;
    float o3 = d3 * inv * g4.w + b4.w;
    uint2 u; u.x = bf2pack(o0, o1); u.y = bf2pack(o2, o3);
    reinterpret_cast<uint2*>(out + (size_t)row * D)[tid] = u;
}

// ---------------------------------------------------------------------------
// BF16 tensor-core GEMM, 4-stage cp.async pipeline (prefetch distance 3).
// Dynamic smem: 4 stages x (A 10240B + B 8704B) = 75776 B.
// ---------------------------------------------------------------------------
#define BM 128
#define BN 128
#define BKT 32
#define ASTR 40
#define BSTR 136
#define STAGE_BYTES (BM*ASTR*2 + BKT*BSTR*2)   // 18944
#define A_PART (BM*ASTR*2)                     // 10240
#define NSTAGE 4
#define GEMM_SMEM (NSTAGE*STAGE_BYTES)         // 75776

__global__ __launch_bounds__(256) void gemm_bf16_kernel(
    const __nv_bfloat16* __restrict__ A, const __nv_bfloat16* __restrict__ B,
    const float* __restrict__ bias, const float* __restrict__ res,
    float* __restrict__ Cf, __nv_bfloat16* __restrict__ Cb,
    int M, int N, int K, int lda, int ldb, int ldcb, int flags)
{
    extern __shared__ __align__(16) uint16_t smem_dyn[];
    const uint32_t sBase = (uint32_t)__cvta_generic_to_shared(smem_dyn);

    const int tid  = threadIdx.x;
    const int lane = tid & 31;
    const int wid  = tid >> 5;
    const int wm   = wid >> 2;
    const int wn   = wid & 3;
    const int lr   = lane >> 2;
    const int lc   = lane & 3;

    const int m0 = blockIdx.y * BM;
    const int n0 = blockIdx.x * BN;

    const int a_r  = (lane & 7) + ((lane >> 3) & 1) * 8;
    const int a_kc = (lane >> 4) * 8;
    const int b_kr = (lane & 7) + ((lane >> 3) & 1) * 8;
    const int b_nc = (lane >> 4) * 8;

    float acc[4][4][4];
    #pragma unroll
    for (int i = 0; i < 4; i++)
        #pragma unroll
        for (int j = 0; j < 4; j++)
            #pragma unroll
            for (int r = 0; r < 4; r++) acc[i][j][r] = 0.f;

    const int nkt = (K + BKT - 1) / BKT;

    auto load_tile = [&](int t, int stage) {
        const int k0 = t * BKT;
        const uint32_t sA = sBase + stage * STAGE_BYTES;
        const uint32_t sB = sA + A_PART;
        #pragma unroll
        for (int i = 0; i < 2; i++) {
            int c   = tid + i * 256;
            int row = c >> 2;
            int col = (c & 3) * 8;
            int gk  = k0 + col;
            int avail = lda - gk;
            int bytes = (avail <= 0) ? 0 : (avail >= 8 ? 16 : avail * 2);
            const __nv_bfloat16* src = bytes ? (A + (size_t)(m0 + row) * lda + gk) : A;
            uint32_t dst = sA + (row * ASTR + col) * 2;
            asm volatile("cp.async.cg.shared.global [%0], [%1], 16, %2;"
                         :: "r"(dst), "l"(src), "r"(bytes));
        }
        #pragma unroll
        for (int i = 0; i < 2; i++) {
            int c   = tid + i * 256;
            int row = c >> 4;
            int col = (c & 15) * 8;
            int gk  = k0 + row;
            int gn  = n0 + col;
            int bytes = (gk < K && gn + 8 <= ldb) ? 16 : 0;
            const __nv_bfloat16* src = bytes ? (B + (size_t)gk * ldb + gn) : B;
            uint32_t dst = sB + (row * BSTR + col) * 2;
            asm volatile("cp.async.cg.shared.global [%0], [%1], 16, %2;"
                         :: "r"(dst), "l"(src), "r"(bytes));
        }
        asm volatile("cp.async.commit_group;");
    };

    // prologue: stages 0..2
    #pragma unroll
    for (int s = 0; s < NSTAGE - 1; s++) {
        if (s < nkt) load_tile(s, s);
        else asm volatile("cp.async.commit_group;");
    }

    for (int t = 0; t < nkt; t++) {
        asm volatile("cp.async.wait_group %0;" :: "n"(NSTAGE - 2));
        __syncthreads();
        if (t + NSTAGE - 1 < nkt) load_tile(t + NSTAGE - 1, (t + NSTAGE - 1) & (NSTAGE - 1));
        else asm volatile("cp.async.commit_group;");

        const uint32_t aB = sBase + (t & (NSTAGE - 1)) * STAGE_BYTES;
        const uint32_t bB = aB + A_PART;

        #pragma unroll
        for (int kk = 0; kk < BKT; kk += 16) {
            uint32_t af[4][4];
            #pragma unroll
            for (int mi = 0; mi < 4; mi++) {
                uint32_t addr = aB + ((wm * 64 + mi * 16 + a_r) * ASTR + kk + a_kc) * 2;
                asm volatile(
                    "ldmatrix.sync.aligned.m8n8.x4.shared.b16 {%0,%1,%2,%3}, [%4];"
                    : "=r"(af[mi][0]), "=r"(af[mi][1]),
                      "=r"(af[mi][2]), "=r"(af[mi][3]) : "r"(addr));
            }
            uint32_t bfp[2][4];
            #pragma unroll
            for (int pr = 0; pr < 2; pr++) {
                uint32_t addr = bB + ((kk + b_kr) * BSTR + wn * 32 + pr * 16 + b_nc) * 2;
                asm volatile(
                    "ldmatrix.sync.aligned.m8n8.x4.trans.shared.b16 {%0,%1,%2,%3}, [%4];"
                    : "=r"(bfp[pr][0]), "=r"(bfp[pr][1]),
                      "=r"(bfp[pr][2]), "=r"(bfp[pr][3]) : "r"(addr));
            }
            #pragma unroll
            for (int mi = 0; mi < 4; mi++)
                #pragma unroll
                for (int ni = 0; ni < 4; ni++) {
                    uint32_t b0 = bfp[ni >> 1][(ni & 1) * 2];
                    uint32_t b1 = bfp[ni >> 1][(ni & 1) * 2 + 1];
                    MMA_BF16(acc[mi][ni], af[mi], b0, b1);
                }
        }
        __syncthreads();
    }

    #pragma unroll
    for (int mi = 0; mi < 4; mi++) {
        #pragma unroll
        for (int ni = 0; ni < 4; ni++) {
            int row = m0 + wm * 64 + mi * 16 + lr;
            int col = n0 + wn * 32 + ni * 8 + lc * 2;
            float v[4];
            #pragma unroll
            for (int r = 0; r < 4; r++) {
                int rr = row + (r >> 1) * 8;
                int cc = col + (r & 1);
                float x = acc[mi][ni][r];
                if (cc < N) {
                    if (flags & 1) x += bias[cc];
                    if (flags & 2) x = 0.5f * x * (1.f + erff(x * 0.70710678118654752f));
                    if (flags & 4) x += res[(size_t)rr * N + cc];
                    if (Cf) Cf[(size_t)rr * N + cc] = x;
                }
                v[r] = x;
            }
            if (Cb && col + 2 <= N) {
                reinterpret_cast<uint32_t*>(Cb)[((size_t)row * ldcb + col) >> 1]       = bf2pack(v[0], v[1]);
                reinterpret_cast<uint32_t*>(Cb)[((size_t)(row + 8) * ldcb + col) >> 1] = bf2pack(v[2], v[3]);
            }
        }
    }
}

// ---------------------------------------------------------------------------
// rowdot3: y[r,0..2] += A[r,:] @ W[:,0..2] + bias   (N=3, K=2048, memory-bound)
// grid 128 x 256 threads; warp per 4 rows; W staged in smem as [3][2048] bf16.
// ---------------------------------------------------------------------------
__global__ __launch_bounds__(256) void rowdot3_kernel(
    const __nv_bfloat16* __restrict__ A, const float* __restrict__ W,
    const float* __restrict__ bias, float* __restrict__ y)
{
    __shared__ uint16_t Ws[3][MFF];
    const int tid  = threadIdx.x;
    const int lane = tid & 31;
    const int w    = tid >> 5;

    for (int i = tid; i < 3 * MFF; i += 256) {
        int c = i / MFF, k = i - c * MFF;
        __nv_bfloat16 hv = __float2bfloat16(W[(size_t)k * O1 + c]);
        Ws[c][k] = *reinterpret_cast<const uint16_t*>(&hv);
    }
    __syncthreads();

    const float b0 = bias[0], b1 = bias[1], b2 = bias[2];
    #pragma unroll
    for (int r = 0; r < 4; r++) {
        int row = blockIdx.x * 32 + w * 4 + r;
        const uint4* arow = (const uint4*)(A + (size_t)row * MFF);
        float a0 = 0.f, a1 = 0.f, a2 = 0.f;
        #pragma unroll
        for (int i = 0; i < MFF / 8 / 32; i++) {   // 8 iters
            int idx = lane + i * 32;
            uint4 av = arow[idx];
            uint4 w0 = ((const uint4*)Ws[0])[idx];
            uint4 w1 = ((const uint4*)Ws[1])[idx];
            uint4 w2 = ((const uint4*)Ws[2])[idx];
            const uint32_t* ap = (const uint32_t*)&av;
            const uint32_t* p0 = (const uint32_t*)&w0;
            const uint32_t* p1 = (const uint32_t*)&w1;
            const uint32_t* p2 = (const uint32_t*)&w2;
            #pragma unroll
            for (int j = 0; j < 4; j++) {
                float2 a = bfunpack(ap[j]);
                float2 f0 = bfunpack(p0[j]);
                float2 f1 = bfunpack(p1[j]);
                float2 f2 = bfunpack(p2[j]);
                a0 = fmaf(a.x, f0.x, fmaf(a.y, f0.y, a0));
                a1 = fmaf(a.x, f1.x, fmaf(a.y, f1.y, a1));
                a2 = fmaf(a.x, f2.x, fmaf(a.y, f2.y, a2));
            }
        }
        #pragma unroll
        for (int off = 16; off > 0; off >>= 1) {
            a0 += __shfl_xor_sync(0xffffffff, a0, off);
            a1 += __shfl_xor_sync(0xffffffff, a1, off);
            a2 += __shfl_xor_sync(0xffffffff, a2, off);
        }
        if (lane == 0) {
            float* yr = y + (size_t)row * O1;
            yr[0] += a0 + b0;
            yr[1] += a1 + b1;
            yr[2] += a2 + b2;
        }
    }
}

// ---------------------------------------------------------------------------
// Tensor-core flash attention (verified Round 9)
// ---------------------------------------------------------------------------
#define KSTR 72
#define KV_ST_BYTES (64*KSTR*2)

__global__ __launch_bounds__(256) void attn_kernel(
    const __nv_bfloat16* __restrict__ qkv, __nv_bfloat16* __restrict__ out)
{
    __shared__ __align__(16) uint16_t Ks[2][64][KSTR];
    __shared__ __align__(16) uint16_t Vs[2][64][KSTR];

    const int tid  = threadIdx.x;
    const int lane = tid & 31;
    const int w    = tid >> 5;
    const int gid  = lane >> 2;
    const int tq   = lane & 3;
    const int qb   = blockIdx.x * 128;
    const int b    = blockIdx.y >> 3;
    const int h    = blockIdx.y & 7;

    uint32_t qf[4][4];
    {
        const uint16_t* q0 = (const uint16_t*)qkv +
            (size_t)(b * TT + qb + w * 16 + gid) * NQKV + h * DH;
        const uint16_t* q1 = q0 + (size_t)8 * NQKV;
        #pragma unroll
        for (int ks = 0; ks < 4; ks++) {
            qf[ks][0] = *(const uint32_t*)(q0 + ks * 16 + tq * 2);
            qf[ks][1] = *(const uint32_t*)(q1 + ks * 16 + tq * 2);
            qf[ks][2] = *(const uint32_t*)(q0 + ks * 16 + 8 + tq * 2);
            qf[ks][3] = *(const uint32_t*)(q1 + ks * 16 + 8 + tq * 2);
        }
    }

    const uint32_t kBase = (uint32_t)__cvta_generic_to_shared(&Ks[0][0][0]);
    const uint32_t vBase = (uint32_t)__cvta_generic_to_shared(&Vs[0][0][0]);

    float oacc[8][4];
    #pragma unroll
    for (int i = 0; i < 8; i++)
        #pragma unroll
        for (int j = 0; j < 4; j++) oacc[i][j] = 0.f;
    float m0 = -1e30f, m1 = -1e30f, l0 = 0.f, l1 = 0.f;

    auto load_kv = [&](int t, int buf) {
        #pragma unroll
        for (int i = 0; i < 2; i++) {
            int idx = tid + i * 256;
            int row = idx >> 3;
            int ch  = (idx & 7) * 8;
            const uint16_t* src = (const uint16_t*)qkv +
                (size_t)(b * TT + t * 64 + row) * NQKV + h * DH + ch;
            uint32_t kd = kBase + buf * KV_ST_BYTES + (row * KSTR + ch) * 2;
            uint32_t vd = vBase + buf * KV_ST_BYTES + (row * KSTR + ch) * 2;
            asm volatile("cp.async.cg.shared.global [%0], [%1], 16;"
                         :: "r"(kd), "l"(src + 512) : "memory");
            asm volatile("cp.async.cg.shared.global [%0], [%1], 16;"
                         :: "r"(vd), "l"(src + 1024) : "memory");
        }
        asm volatile("cp.async.commit_group;");
    };

    load_kv(0, 0);

    const float sc = 0.125f * 1.4426950408889634f;

    for (int t = 0; t < TT / 64; t++) {
        asm volatile("cp.async.wait_group 0;");
        __syncthreads();
        if (t + 1 < TT / 64) load_kv(t + 1, (t + 1) & 1);

        const uint32_t kB = kBase + (t & 1) * KV_ST_BYTES;
        const uint32_t vB = vBase + (t & 1) * KV_ST_BYTES;

        float sacc[8][4];
        #pragma unroll
        for (int i = 0; i < 8; i++)
            #pragma unroll
            for (int j = 0; j < 4; j++) sacc[i][j] = 0.f;

        #pragma unroll
        for (int np = 0; np < 4; np++) {
            #pragma unroll
            for (int ks = 0; ks < 4; ks++) {
                uint32_t kb[4];
                uint32_t addr = kB +
                    ((np * 16 + (lane & 7) + ((lane >> 4) & 1) * 8) * KSTR +
                     ks * 16 + ((lane >> 3) & 1) * 8) * 2;
                asm volatile(
                    "ldmatrix.sync.aligned.m8n8.x4.shared.b16 {%0,%1,%2,%3}, [%4];"
                    : "=r"(kb[0]), "=r"(kb[1]), "=r"(kb[2]), "=r"(kb[3]) : "r"(addr));
                MMA_BF16(sacc[np * 2],     qf[ks], kb[0], kb[1]);
                MMA_BF16(sacc[np * 2 + 1], qf[ks], kb[2], kb[3]);
            }
        }

        float mx0 = -1e30f, mx1 = -1e30f;
        #pragma unroll
        for (int ni = 0; ni < 8; ni++) {
            sacc[ni][0] *= sc; sacc[ni][1] *= sc;
            sacc[ni][2] *= sc; sacc[ni][3] *= sc;
            mx0 = fmaxf(mx0, fmaxf(sacc[ni][0], sacc[ni][1]));
            mx1 = fmaxf(mx1, fmaxf(sacc[ni][2], sacc[ni][3]));
        }
        mx0 = fmaxf(mx0, __shfl_xor_sync(0xffffffff, mx0, 1));
        mx0 = fmaxf(mx0, __shfl_xor_sync(0xffffffff, mx0, 2));
        mx1 = fmaxf(mx1, __shfl_xor_sync(0xffffffff, mx1, 1));
        mx1 = fmaxf(mx1, __shfl_xor_sync(0xffffffff, mx1, 2));

        float m0n = fmaxf(m0, mx0), m1n = fmaxf(m1, mx1);
        float c0 = ex2f(m0 - m0n), c1 = ex2f(m1 - m1n);
        float s0 = 0.f, s1 = 0.f;
        #pragma unroll
        for (int ni = 0; ni < 8; ni++) {
            float p0 = ex2f(sacc[ni][0] - m0n);
            float p1 = ex2f(sacc[ni][1] - m0n);
            float p2 = ex2f(sacc[ni][2] - m1n);
            float p3 = ex2f(sacc[ni][3] - m1n);
            sacc[ni][0] = p0; sacc[ni][1] = p1;
            sacc[ni][2] = p2; sacc[ni][3] = p3;
            s0 += p0 + p1; s1 += p2 + p3;
        }
        s0 += __shfl_xor_sync(0xffffffff, s0, 1);
        s0 += __shfl_xor_sync(0xffffffff, s0, 2);
        s1 += __shfl_xor_sync(0xffffffff, s1, 1);
        s1 += __shfl_xor_sync(0xffffffff, s1, 2);
        l0 = l0 * c0 + s0;
        l1 = l1 * c1 + s1;
        m0 = m0n; m1 = m1n;
        #pragma unroll
        for (int nj = 0; nj < 8; nj++) {
            oacc[nj][0] *= c0; oacc[nj][1] *= c0;
            oacc[nj][2] *= c1; oacc[nj][3] *= c1;
        }

        uint32_t aP[4][4];
        #pragma unroll
        for (int ks = 0; ks < 4; ks++) {
            aP[ks][0] = bf2pack(sacc[2*ks][0],     sacc[2*ks][1]);
            aP[ks][1] = bf2pack(sacc[2*ks][2],     sacc[2*ks][3]);
            aP[ks][2] = bf2pack(sacc[2*ks + 1][0], sacc[2*ks + 1][1]);
            aP[ks][3] = bf2pack(sacc[2*ks + 1][2], sacc[2*ks + 1][3]);
        }

        #pragma unroll
        for (int np = 0; np < 4; np++) {
            #pragma unroll
            for (int ks = 0; ks < 4; ks++) {
                uint32_t vb[4];
                uint32_t addr = vB +
                    ((ks * 16 + (lane & 7) + ((lane >> 3) & 1) * 8) * KSTR +
                     np * 16 + ((lane >> 4) & 1) * 8) * 2;
                asm volatile(
                    "ldmatrix.sync.aligned.m8n8.x4.trans.shared.b16 {%0,%1,%2,%3}, [%4];"
                    : "=r"(vb[0]), "=r"(vb[1]), "=r"(vb[2]), "=r"(vb[3]) : "r"(addr));
                MMA_BF16(oacc[np * 2],     aP[ks], vb[0], vb[1]);
                MMA_BF16(oacc[np * 2 + 1], aP[ks], vb[2], vb[3]);
            }
        }
    }

    float i0 = 1.f / l0, i1 = 1.f / l1;
    uint16_t* o0 = (uint16_t*)out + (size_t)(b * TT + qb + w * 16 + gid) * D + h * DH;
    uint16_t* o1 = o0 + (size_t)8 * D;
    #pragma unroll
    for (int nj = 0; nj < 8; nj++) {
        *(uint32_t*)(o0 + nj * 8 + tq * 2) = bf2pack(oacc[nj][0] * i0, oacc[nj][1] * i0);
        *(uint32_t*)(o1 + nj * 8 + tq * 2) = bf2pack(oacc[nj][2] * i1, oacc[nj][3] * i1);
    }
}

// ---------------------------------------------------------------------------
// concat into bf16: dst[r*dstr + c] = [h_bf[r,:512], (bf16)y[r,:nb], 0-pad]
// ---------------------------------------------------------------------------
__global__ void concat_kernel(__nv_bfloat16* __restrict__ dst,
                              const __nv_bfloat16* __restrict__ a,
                              const float* __restrict__ y, int nb, int rows,
                              int dstr)
{
    int total = rows * dstr;
    for (int idx = blockIdx.x * blockDim.x + threadIdx.x; idx < total;
         idx += gridDim.x * blockDim.x) {
        int r = idx / dstr, c = idx - r * dstr;
        __nv_bfloat16 v;
        if (c < D)            v = a[(size_t)r * D + c];
        else if (c < D + nb)  v = __float2bfloat16(y[(size_t)r * nb + (c - D)]);
        else                  v = __float2bfloat16(0.f);
        dst[idx] = v;
    }
}

// ---------------------------------------------------------------------------
// launch
// ---------------------------------------------------------------------------
extern "C" void kernel_launch(void* const* d_in, const int* in_sizes, int n_in,
                              void* d_out, int out_size)
{
    (void)in_sizes; (void)n_in; (void)out_size;

    const float* in_x     = (const float*)d_in[0];
    const float* in_init0 = (const float*)d_in[1];
    const float* in_init1 = (const float*)d_in[2];
    // d_in[3] = mask: constant all-True -> unused
    const float* ln1_g = (const float*)d_in[4];
    const float* ln1_b = (const float*)d_in[5];
    const float* qkv_W = (const float*)d_in[6];
    const float* out_W = (const float*)d_in[7];
    const float* out_b = (const float*)d_in[8];
    const float* ln2_g = (const float*)d_in[9];
    const float* ln2_b = (const float*)d_in[10];
    const float* ff_W1 = (const float*)d_in[11];
    const float* ff_b1 = (const float*)d_in[12];
    const float* ff_W2 = (const float*)d_in[13];
    const float* ff_b2 = (const float*)d_in[14];
    const float* ln3_g = (const float*)d_in[15];
    const float* ln3_b = (const float*)d_in[16];
    const float* r0_W1 = (const float*)d_in[17];
    const float* r0_b1 = (const float*)d_in[18];
    const float* r0_W2 = (const float*)d_in[19];
    const float* r0_b2 = (const float*)d_in[20];
    const float* ln4_g = (const float*)d_in[21];
    const float* ln4_b = (const float*)d_in[22];
    const float* r1_W1 = (const float*)d_in[23];
    const float* r1_b1 = (const float*)d_in[24];
    const float* r1_W2 = (const float*)d_in[25];
    const float* r1_b2 = (const float*)d_in[26];

    static bool attr_done = false;
    if (!attr_done) {
        cudaFuncSetAttribute(gemm_bf16_kernel,
                             cudaFuncAttributeMaxDynamicSharedMemorySize, GEMM_SMEM);
        attr_done = true;
    }

    float *px;
    __nv_bfloat16 *pqkv, *ph, *po, *pmid, *pcat;
    __nv_bfloat16 *wqkv, *wout, *wff1, *wff2, *wr01, *wr02, *wr11;
    cudaGetSymbolAddress((void**)&px,   g_x);
    cudaGetSymbolAddress((void**)&pqkv, gb_qkv);
    cudaGetSymbolAddress((void**)&ph,   gb_h);
    cudaGetSymbolAddress((void**)&po,   gb_o);
    cudaGetSymbolAddress((void**)&pmid, gb_mid);
    cudaGetSymbolAddress((void**)&pcat, gb_cat);
    cudaGetSymbolAddress((void**)&wqkv, gb_wqkv);
    cudaGetSymbolAddress((void**)&wout, gb_wout);
    cudaGetSymbolAddress((void**)&wff1, gb_wff1);
    cudaGetSymbolAddress((void**)&wff2, gb_wff2);
    cudaGetSymbolAddress((void**)&wr01, gb_wr01);
    cudaGetSymbolAddress((void**)&wr02, gb_wr02);
    cudaGetSymbolAddress((void**)&wr11, gb_wr11);

    float* y0 = (float*)d_out;                 // [ROWS, O0]
    float* y1 = (float*)d_out + ROWS * O0;     // [ROWS, O1]

    cudaMemcpyAsync(px, in_x,     (size_t)ROWS * D  * sizeof(float), cudaMemcpyDeviceToDevice, 0);
    cudaMemcpyAsync(y0, in_init0, (size_t)ROWS * O0 * sizeof(float), cudaMemcpyDeviceToDevice, 0);
    cudaMemcpyAsync(y1, in_init1, (size_t)ROWS * O1 * sizeof(float), cudaMemcpyDeviceToDevice, 0);

    // ---- weight conversion (fp32 -> padded bf16) ----
    wconv_kernel<<<1024, 256>>>(qkv_W, wqkv, LAYERS * D,   NQKV, NQKV);
    wconv_kernel<<<1024, 256>>>(out_W, wout, LAYERS * D,   D,    D);
    wconv_kernel<<<1024, 256>>>(ff_W1, wff1, LAYERS * D,   MFF,  MFF);
    wconv_kernel<<<1024, 256>>>(ff_W2, wff2, LAYERS * MFF, D,    D);
    wconv_kernel<<<1024, 256>>>(r0_W1, wr01, LAYERS * K0c, MFF,  MFF);
    wconv_kernel<<<1024, 256>>>(r0_W2, wr02, LAYERS * MFF, O0,   LDW02);
    wconv_kernel<<<1024, 256>>>(r1_W1, wr11, LAYERS * K1c, MFF,  MFF);

    for (int l = 0; l < LAYERS; l++) {
        // --- attention block ---
        ln_kernel<<<ROWS, 128>>>(px, ln1_g + l * D, ln1_b + l * D, ph);
        gemm_bf16_kernel<<<dim3(NQKV / BN, ROWS / BM), 256, GEMM_SMEM>>>(
            ph, wqkv + (size_t)l * D * NQKV, nullptr, nullptr, nullptr, pqkv,
            ROWS, NQKV, D, D, NQKV, NQKV, 0);
        attn_kernel<<<dim3(TT / 128, BB * H), 256>>>(pqkv, po);
        gemm_bf16_kernel<<<dim3(D / BN, ROWS / BM), 256, GEMM_SMEM>>>(
            po, wout + (size_t)l * D * D, out_b + l * D, px, px, nullptr,
            ROWS, D, D, D, D, 0, 1 | 4);

        // --- FFN block ---
        ln_kernel<<<ROWS, 128>>>(px, ln2_g + l * D, ln2_b + l * D, ph);
        gemm_bf16_kernel<<<dim3(MFF / BN, ROWS / BM), 256, GEMM_SMEM>>>(
            ph, wff1 + (size_t)l * D * MFF, ff_b1 + l * MFF, nullptr, nullptr, pmid,
            ROWS, MFF, D, D, MFF, MFF, 1 | 2);
        gemm_bf16_kernel<<<dim3(D / BN, ROWS / BM), 256, GEMM_SMEM>>>(
            pmid, wff2 + (size_t)l * MFF * D, ff_b2 + l * D, px, px, nullptr,
            ROWS, D, MFF, MFF, D, 0, 1 | 4);

        // --- regressor 0 ---
        ln_kernel<<<ROWS, 128>>>(px, ln3_g + l * D, ln3_b + l * D, ph);
        concat_kernel<<<2048, 256>>>(pcat, ph, y0, O0, ROWS, LDC0);
        gemm_bf16_kernel<<<dim3(MFF / BN, ROWS / BM), 256, GEMM_SMEM>>>(
            pcat, wr01 + (size_t)l * K0c * MFF, r0_b1 + l * MFF, nullptr, nullptr, pmid,
            ROWS, MFF, K0c, LDC0, MFF, MFF, 1 | 2);
        gemm_bf16_kernel<<<dim3((O0 + BN - 1) / BN, ROWS / BM), 256, GEMM_SMEM>>>(
            pmid, wr02 + (size_t)l * MFF * LDW02, r0_b2 + l * O0, y0, y0, nullptr,
            ROWS, O0, MFF, MFF, LDW02, 0, 1 | 4);

        // --- regressor 1 ---
        ln_kernel<<<ROWS, 128>>>(px, ln4_g + l * D, ln4_b + l * D, ph);
        concat_kernel<<<2048, 256>>>(pcat, ph, y1, O1, ROWS, LDC1);
        gemm_bf16_kernel<<<dim3(MFF / BN, ROWS / BM), 256, GEMM_SMEM>>>(
            pcat, wr11 + (size_t)l * K1c * MFF, r1_b1 + l * MFF, nullptr, nullptr, pmid,
            ROWS, MFF, K1c, LDC1, MFF, MFF, 1 | 2);
        rowdot3_kernel<<<128, 256>>>(pmid, r1_W2 + (size_t)l * MFF * O1,
                                     r1_b2 + l * O1, y1);
    }
}

// round 13
// speedup vs baseline: 7.1544x; 1.0382x over previous
#include <cuda_runtime.h>
#include <cuda_bf16.h>
#include <math.h>
#include <stdint.h>

// Problem constants
#define LAYERS 2
#define D 512
#define H 8
#define DH 64
#define MFF 2048
#define O0 132
#define O1 3
#define BB 2
#define TT 2048
#define ROWS (BB*TT)          // 4096
#define EPS 1e-5f

#define NQKV 1536
#define K0c 644               // D+O0
#define K1c 515               // D+O1
#define LDC0 648              // cat0 stride (mod 8 == 0)
#define LDC1 520              // cat1 stride (mod 8 == 0)
#define LDW02 136             // r0_W2 padded N stride

// ---------------------------------------------------------------------------
// Scratch (device globals; no runtime allocation allowed)
// ---------------------------------------------------------------------------
__device__ float g_x  [ROWS * D];          // residual stream (fp32)

__device__ __nv_bfloat16 gb_qkv[ROWS * NQKV];
__device__ __nv_bfloat16 gb_h  [ROWS * D];
__device__ __nv_bfloat16 gb_o  [ROWS * D];
__device__ __nv_bfloat16 gb_mid[ROWS * MFF];
__device__ __nv_bfloat16 gb_cat[ROWS * LDC0];

__device__ __nv_bfloat16 gb_wqkv[LAYERS * D * NQKV];
__device__ __nv_bfloat16 gb_wout[LAYERS * D * D];
__device__ __nv_bfloat16 gb_wff1[LAYERS * D * MFF];
__device__ __nv_bfloat16 gb_wff2[LAYERS * MFF * D];
__device__ __nv_bfloat16 gb_wr01[LAYERS * K0c * MFF];
__device__ __nv_bfloat16 gb_wr02[LAYERS * MFF * LDW02];
__device__ __nv_bfloat16 gb_wr11[LAYERS * K1c * MFF];

__device__ __forceinline__ uint32_t bf2pack(float lo, float hi) {
    __nv_bfloat162 h = __floats2bfloat162_rn(lo, hi);
    return *reinterpret_cast<uint32_t*>(&h);
}

__device__ __forceinline__ float2 bfunpack(uint32_t u) {
    __nv_bfloat162 h = *reinterpret_cast<__nv_bfloat162*>(&u);
    return __bfloat1622float2(h);
}

__device__ __forceinline__ float ex2f(float x) {
    float y;
    asm("ex2.approx.f32 %0, %1;" : "=f"(y) : "f"(x));
    return y;
}

#define MMA_BF16(acc, a, b0v, b1v)                                          \
    asm volatile(                                                           \
        "mma.sync.aligned.m16n8k16.row.col.f32.bf16.bf16.f32 "              \
        "{%0,%1,%2,%3}, {%4,%5,%6,%7}, {%8,%9}, {%0,%1,%2,%3};"             \
        : "+f"((acc)[0]), "+f"((acc)[1]), "+f"((acc)[2]), "+f"((acc)[3])    \
        : "r"((a)[0]), "r"((a)[1]), "r"((a)[2]), "r"((a)[3]),               \
          "r"(b0v), "r"(b1v))

// ---------------------------------------------------------------------------
// Weight fp32 -> bf16 with padded/zeroed N stride (fast path when no pad)
// ---------------------------------------------------------------------------
__global__ void wconv_kernel(const float* __restrict__ src,
                             __nv_bfloat16* __restrict__ dst,
                             int rows, int N, int ldb)
{
    if (N == ldb && (N & 7) == 0) {
        int total8 = rows * (N >> 3);
        for (int idx = blockIdx.x * blockDim.x + threadIdx.x; idx < total8;
             idx += gridDim.x * blockDim.x) {
            const float4* s = (const float4*)(src + (size_t)idx * 8);
            float4 a = s[0], b2 = s[1];
            uint4 u;
            u.x = bf2pack(a.x, a.y);   u.y = bf2pack(a.z, a.w);
            u.z = bf2pack(b2.x, b2.y); u.w = bf2pack(b2.z, b2.w);
            reinterpret_cast<uint4*>(dst)[idx] = u;
        }
        return;
    }
    int half = ldb >> 1;
    int total = rows * half;
    for (int idx = blockIdx.x * blockDim.x + threadIdx.x; idx < total;
         idx += gridDim.x * blockDim.x) {
        int r = idx / half;
        int c = (idx - r * half) * 2;
        float v0 = (c     < N) ? src[(size_t)r * N + c]     : 0.f;
        float v1 = (c + 1 < N) ? src[(size_t)r * N + c + 1] : 0.f;
        reinterpret_cast<uint32_t*>(dst)[(size_t)r * half + (c >> 1)] = bf2pack(v0, v1);
    }
}

// ---------------------------------------------------------------------------
// LayerNorm: warp per row (4 rows/block), D=512; bf16 output with stride ldo.
// ---------------------------------------------------------------------------
__global__ __launch_bounds__(128) void ln_kernel(const float* __restrict__ x,
                                                 const float* __restrict__ g,
                                                 const float* __restrict__ b,
                                                 __nv_bfloat16* __restrict__ out,
                                                 int ldo)
{
    const int row  = blockIdx.x * 4 + (threadIdx.x >> 5);
    const int lane = threadIdx.x & 31;
    const float4* xr = (const float4*)(x + (size_t)row * D);

    float4 v[4];
    float s = 0.f;
    #pragma unroll
    for (int i = 0; i < 4; i++) {
        v[i] = xr[lane + 32 * i];
        s += v[i].x + v[i].y + v[i].z + v[i].w;
    }
    #pragma unroll
    for (int off = 16; off > 0; off >>= 1)
        s += __shfl_xor_sync(0xffffffff, s, off);
    float mu = s * (1.f / D);

    float var = 0.f;
    #pragma unroll
    for (int i = 0; i < 4; i++) {
        v[i].x -= mu; v[i].y -= mu; v[i].z -= mu; v[i].w -= mu;
        var += v[i].x*v[i].x + v[i].y*v[i].y + v[i].z*v[i].z + v[i].w*v[i].w;
    }
    #pragma unroll
    for (int off = 16; off > 0; off >>= 1)
        var += __shfl_xor_sync(0xffffffff, var, off);
    float inv = rsqrtf(var * (1.f / D) + EPS);

    uint16_t* orow = (uint16_t*)out + (size_t)row * ldo;
    #pragma unroll
    for (int i = 0; i < 4; i++) {
        int e = (lane + 32 * i) * 4;
        const float4 g4 = *(const float4*)(g + e);
        const float4 b4 = *(const float4*)(b + e);
        float o0 = v[i].x * inv * g4.x + b4.x;
        float o1 = v[i].y * inv * g4.y + b4.y;
        float o2 = v[i].z * inv * g4.z + b4.z;
        float o3 = v[i].w * inv * g4.w + b4.w;
        uint2 u; u.x = bf2pack(o0, o1); u.y = bf2pack(o2, o3);
        *(uint2*)(orow + e) = u;
    }
}

// ---------------------------------------------------------------------------
// concat_y: fill columns [D, dstr) of dst with (bf16)y[:, 0:nb] then zero pad
// ---------------------------------------------------------------------------
__global__ void concat_y_kernel(__nv_bfloat16* __restrict__ dst,
                                const float* __restrict__ y, int nb, int rows,
                                int dstr)
{
    int w = dstr - D;
    int total = rows * w;
    for (int idx = blockIdx.x * blockDim.x + threadIdx.x; idx < total;
         idx += gridDim.x * blockDim.x) {
        int r = idx / w, c = idx - r * w;
        dst[(size_t)r * dstr + D + c] =
            (c < nb) ? __float2bfloat16(y[(size_t)r * nb + c])
                     : __float2bfloat16(0.f);
    }
}

// ---------------------------------------------------------------------------
// BF16 tensor-core GEMM, 4-stage cp.async pipeline, 2 CTAs/SM.
// ---------------------------------------------------------------------------
#define BM 128
#define BN 128
#define BKT 32
#define ASTR 40
#define BSTR 136
#define STAGE_BYTES (BM*ASTR*2 + BKT*BSTR*2)   // 18944
#define A_PART (BM*ASTR*2)                     // 10240
#define NSTAGE 4
#define GEMM_SMEM (NSTAGE*STAGE_BYTES)         // 75776

__global__ __launch_bounds__(256, 2) void gemm_bf16_kernel(
    const __nv_bfloat16* __restrict__ A, const __nv_bfloat16* __restrict__ B,
    const float* __restrict__ bias, const float* __restrict__ res,
    float* __restrict__ Cf, __nv_bfloat16* __restrict__ Cb,
    int M, int N, int K, int lda, int ldb, int ldcb, int flags)
{
    extern __shared__ __align__(16) uint16_t smem_dyn[];
    const uint32_t sBase = (uint32_t)__cvta_generic_to_shared(smem_dyn);

    const int tid  = threadIdx.x;
    const int lane = tid & 31;
    const int wid  = tid >> 5;
    const int wm   = wid >> 2;
    const int wn   = wid & 3;
    const int lr   = lane >> 2;
    const int lc   = lane & 3;

    const int m0 = blockIdx.y * BM;
    const int n0 = blockIdx.x * BN;

    const int a_r  = (lane & 7) + ((lane >> 3) & 1) * 8;
    const int a_kc = (lane >> 4) * 8;
    const int b_kr = (lane & 7) + ((lane >> 3) & 1) * 8;
    const int b_nc = (lane >> 4) * 8;

    float acc[4][4][4];
    #pragma unroll
    for (int i = 0; i < 4; i++)
        #pragma unroll
        for (int j = 0; j < 4; j++)
            #pragma unroll
            for (int r = 0; r < 4; r++) acc[i][j][r] = 0.f;

    const int nkt = (K + BKT - 1) / BKT;

    auto load_tile = [&](int t, int stage) {
        const int k0 = t * BKT;
        const uint32_t sA = sBase + stage * STAGE_BYTES;
        const uint32_t sB = sA + A_PART;
        #pragma unroll
        for (int i = 0; i < 2; i++) {
            int c   = tid + i * 256;
            int row = c >> 2;
            int col = (c & 3) * 8;
            int gk  = k0 + col;
            int avail = lda - gk;
            int bytes = (avail <= 0) ? 0 : (avail >= 8 ? 16 : avail * 2);
            const __nv_bfloat16* src = bytes ? (A + (size_t)(m0 + row) * lda + gk) : A;
            uint32_t dst = sA + (row * ASTR + col) * 2;
            asm volatile("cp.async.cg.shared.global [%0], [%1], 16, %2;"
                         :: "r"(dst), "l"(src), "r"(bytes));
        }
        #pragma unroll
        for (int i = 0; i < 2; i++) {
            int c   = tid + i * 256;
            int row = c >> 4;
            int col = (c & 15) * 8;
            int gk  = k0 + row;
            int gn  = n0 + col;
            int bytes = (gk < K && gn + 8 <= ldb) ? 16 : 0;
            const __nv_bfloat16* src = bytes ? (B + (size_t)gk * ldb + gn) : B;
            uint32_t dst = sB + (row * BSTR + col) * 2;
            asm volatile("cp.async.cg.shared.global [%0], [%1], 16, %2;"
                         :: "r"(dst), "l"(src), "r"(bytes));
        }
        asm volatile("cp.async.commit_group;");
    };

    // prologue: stages 0..2
    #pragma unroll
    for (int s = 0; s < NSTAGE - 1; s++) {
        if (s < nkt) load_tile(s, s);
        else asm volatile("cp.async.commit_group;");
    }

    for (int t = 0; t < nkt; t++) {
        asm volatile("cp.async.wait_group %0;" :: "n"(NSTAGE - 2));
        __syncthreads();
        if (t + NSTAGE - 1 < nkt) load_tile(t + NSTAGE - 1, (t + NSTAGE - 1) & (NSTAGE - 1));
        else asm volatile("cp.async.commit_group;");

        const uint32_t aB = sBase + (t & (NSTAGE - 1)) * STAGE_BYTES;
        const uint32_t bB = aB + A_PART;

        #pragma unroll
        for (int kk = 0; kk < BKT; kk += 16) {
            uint32_t af[4][4];
            #pragma unroll
            for (int mi = 0; mi < 4; mi++) {
                uint32_t addr = aB + ((wm * 64 + mi * 16 + a_r) * ASTR + kk + a_kc) * 2;
                asm volatile(
                    "ldmatrix.sync.aligned.m8n8.x4.shared.b16 {%0,%1,%2,%3}, [%4];"
                    : "=r"(af[mi][0]), "=r"(af[mi][1]),
                      "=r"(af[mi][2]), "=r"(af[mi][3]) : "r"(addr));
            }
            uint32_t bfp[2][4];
            #pragma unroll
            for (int pr = 0; pr < 2; pr++) {
                uint32_t addr = bB + ((kk + b_kr) * BSTR + wn * 32 + pr * 16 + b_nc) * 2;
                asm volatile(
                    "ldmatrix.sync.aligned.m8n8.x4.trans.shared.b16 {%0,%1,%2,%3}, [%4];"
                    : "=r"(bfp[pr][0]), "=r"(bfp[pr][1]),
                      "=r"(bfp[pr][2]), "=r"(bfp[pr][3]) : "r"(addr));
            }
            #pragma unroll
            for (int mi = 0; mi < 4; mi++)
                #pragma unroll
                for (int ni = 0; ni < 4; ni++) {
                    uint32_t b0 = bfp[ni >> 1][(ni & 1) * 2];
                    uint32_t b1 = bfp[ni >> 1][(ni & 1) * 2 + 1];
                    MMA_BF16(acc[mi][ni], af[mi], b0, b1);
                }
        }
        __syncthreads();
    }

    #pragma unroll
    for (int mi = 0; mi < 4; mi++) {
        #pragma unroll
        for (int ni = 0; ni < 4; ni++) {
            int row = m0 + wm * 64 + mi * 16 + lr;
            int col = n0 + wn * 32 + ni * 8 + lc * 2;
            float v[4];
            #pragma unroll
            for (int r = 0; r < 4; r++) {
                int rr = row + (r >> 1) * 8;
                int cc = col + (r & 1);
                float x = acc[mi][ni][r];
                if (cc < N) {
                    if (flags & 1) x += bias[cc];
                    if (flags & 2) x = 0.5f * x * (1.f + erff(x * 0.70710678118654752f));
                    if (flags & 4) x += res[(size_t)rr * N + cc];
                    if (Cf) Cf[(size_t)rr * N + cc] = x;
                }
                v[r] = x;
            }
            if (Cb && col + 2 <= N) {
                reinterpret_cast<uint32_t*>(Cb)[((size_t)row * ldcb + col) >> 1]       = bf2pack(v[0], v[1]);
                reinterpret_cast<uint32_t*>(Cb)[((size_t)(row + 8) * ldcb + col) >> 1] = bf2pack(v[2], v[3]);
            }
        }
    }
}

// ---------------------------------------------------------------------------
// rowdot3: y[r,0..2] += A[r,:] @ W[:,0..2] + bias   (N=3, K=2048, memory-bound)
// ---------------------------------------------------------------------------
__global__ __launch_bounds__(256) void rowdot3_kernel(
    const __nv_bfloat16* __restrict__ A, const float* __restrict__ W,
    const float* __restrict__ bias, float* __restrict__ y)
{
    __shared__ uint16_t Ws[3][MFF];
    const int tid  = threadIdx.x;
    const int lane = tid & 31;
    const int w    = tid >> 5;

    for (int i = tid; i < 3 * MFF; i += 256) {
        int c = i / MFF, k = i - c * MFF;
        __nv_bfloat16 hv = __float2bfloat16(W[(size_t)k * O1 + c]);
        Ws[c][k] = *reinterpret_cast<const uint16_t*>(&hv);
    }
    __syncthreads();

    const float b0 = bias[0], b1 = bias[1], b2 = bias[2];
    #pragma unroll
    for (int r = 0; r < 4; r++) {
        int row = blockIdx.x * 32 + w * 4 + r;
        const uint4* arow = (const uint4*)(A + (size_t)row * MFF);
        float a0 = 0.f, a1 = 0.f, a2 = 0.f;
        #pragma unroll
        for (int i = 0; i < MFF / 8 / 32; i++) {
            int idx = lane + i * 32;
            uint4 av = arow[idx];
            uint4 w0 = ((const uint4*)Ws[0])[idx];
            uint4 w1 = ((const uint4*)Ws[1])[idx];
            uint4 w2 = ((const uint4*)Ws[2])[idx];
            const uint32_t* ap = (const uint32_t*)&av;
            const uint32_t* p0 = (const uint32_t*)&w0;
            const uint32_t* p1 = (const uint32_t*)&w1;
            const uint32_t* p2 = (const uint32_t*)&w2;
            #pragma unroll
            for (int j = 0; j < 4; j++) {
                float2 a = bfunpack(ap[j]);
                float2 f0 = bfunpack(p0[j]);
                float2 f1 = bfunpack(p1[j]);
                float2 f2 = bfunpack(p2[j]);
                a0 = fmaf(a.x, f0.x, fmaf(a.y, f0.y, a0));
                a1 = fmaf(a.x, f1.x, fmaf(a.y, f1.y, a1));
                a2 = fmaf(a.x, f2.x, fmaf(a.y, f2.y, a2));
            }
        }
        #pragma unroll
        for (int off = 16; off > 0; off >>= 1) {
            a0 += __shfl_xor_sync(0xffffffff, a0, off);
            a1 += __shfl_xor_sync(0xffffffff, a1, off);
            a2 += __shfl_xor_sync(0xffffffff, a2, off);
        }
        if (lane == 0) {
            float* yr = y + (size_t)row * O1;
            yr[0] += a0 + b0;
            yr[1] += a1 + b1;
            yr[2] += a2 + b2;
        }
    }
}

// ---------------------------------------------------------------------------
// Tensor-core flash attention (verified Round 9)
// ---------------------------------------------------------------------------
#define KSTR 72
#define KV_ST_BYTES (64*KSTR*2)

__global__ __launch_bounds__(256) void attn_kernel(
    const __nv_bfloat16* __restrict__ qkv, __nv_bfloat16* __restrict__ out)
{
    __shared__ __align__(16) uint16_t Ks[2][64][KSTR];
    __shared__ __align__(16) uint16_t Vs[2][64][KSTR];

    const int tid  = threadIdx.x;
    const int lane = tid & 31;
    const int w    = tid >> 5;
    const int gid  = lane >> 2;
    const int tq   = lane & 3;
    const int qb   = blockIdx.x * 128;
    const int b    = blockIdx.y >> 3;
    const int h    = blockIdx.y & 7;

    uint32_t qf[4][4];
    {
        const uint16_t* q0 = (const uint16_t*)qkv +
            (size_t)(b * TT + qb + w * 16 + gid) * NQKV + h * DH;
        const uint16_t* q1 = q0 + (size_t)8 * NQKV;
        #pragma unroll
        for (int ks = 0; ks < 4; ks++) {
            qf[ks][0] = *(const uint32_t*)(q0 + ks * 16 + tq * 2);
            qf[ks][1] = *(const uint32_t*)(q1 + ks * 16 + tq * 2);
            qf[ks][2] = *(const uint32_t*)(q0 + ks * 16 + 8 + tq * 2);
            qf[ks][3] = *(const uint32_t*)(q1 + ks * 16 + 8 + tq * 2);
        }
    }

    const uint32_t kBase = (uint32_t)__cvta_generic_to_shared(&Ks[0][0][0]);
    const uint32_t vBase = (uint32_t)__cvta_generic_to_shared(&Vs[0][0][0]);

    float oacc[8][4];
    #pragma unroll
    for (int i = 0; i < 8; i++)
        #pragma unroll
        for (int j = 0; j < 4; j++) oacc[i][j] = 0.f;
    float m0 = -1e30f, m1 = -1e30f, l0 = 0.f, l1 = 0.f;

    auto load_kv = [&](int t, int buf) {
        #pragma unroll
        for (int i = 0; i < 2; i++) {
            int idx = tid + i * 256;
            int row = idx >> 3;
            int ch  = (idx & 7) * 8;
            const uint16_t* src = (const uint16_t*)qkv +
                (size_t)(b * TT + t * 64 + row) * NQKV + h * DH + ch;
            uint32_t kd = kBase + buf * KV_ST_BYTES + (row * KSTR + ch) * 2;
            uint32_t vd = vBase + buf * KV_ST_BYTES + (row * KSTR + ch) * 2;
            asm volatile("cp.async.cg.shared.global [%0], [%1], 16;"
                         :: "r"(kd), "l"(src + 512) : "memory");
            asm volatile("cp.async.cg.shared.global [%0], [%1], 16;"
                         :: "r"(vd), "l"(src + 1024) : "memory");
        }
        asm volatile("cp.async.commit_group;");
    };

    load_kv(0, 0);

    const float sc = 0.125f * 1.4426950408889634f;

    for (int t = 0; t < TT / 64; t++) {
        asm volatile("cp.async.wait_group 0;");
        __syncthreads();
        if (t + 1 < TT / 64) load_kv(t + 1, (t + 1) & 1);

        const uint32_t kB = kBase + (t & 1) * KV_ST_BYTES;
        const uint32_t vB = vBase + (t & 1) * KV_ST_BYTES;

        float sacc[8][4];
        #pragma unroll
        for (int i = 0; i < 8; i++)
            #pragma unroll
            for (int j = 0; j < 4; j++) sacc[i][j] = 0.f;

        #pragma unroll
        for (int np = 0; np < 4; np++) {
            #pragma unroll
            for (int ks = 0; ks < 4; ks++) {
                uint32_t kb[4];
                uint32_t addr = kB +
                    ((np * 16 + (lane & 7) + ((lane >> 4) & 1) * 8) * KSTR +
                     ks * 16 + ((lane >> 3) & 1) * 8) * 2;
                asm volatile(
                    "ldmatrix.sync.aligned.m8n8.x4.shared.b16 {%0,%1,%2,%3}, [%4];"
                    : "=r"(kb[0]), "=r"(kb[1]), "=r"(kb[2]), "=r"(kb[3]) : "r"(addr));
                MMA_BF16(sacc[np * 2],     qf[ks], kb[0], kb[1]);
                MMA_BF16(sacc[np * 2 + 1], qf[ks], kb[2], kb[3]);
            }
        }

        float mx0 = -1e30f, mx1 = -1e30f;
        #pragma unroll
        for (int ni = 0; ni < 8; ni++) {
            sacc[ni][0] *= sc; sacc[ni][1] *= sc;
            sacc[ni][2] *= sc; sacc[ni][3] *= sc;
            mx0 = fmaxf(mx0, fmaxf(sacc[ni][0], sacc[ni][1]));
            mx1 = fmaxf(mx1, fmaxf(sacc[ni][2], sacc[ni][3]));
        }
        mx0 = fmaxf(mx0, __shfl_xor_sync(0xffffffff, mx0, 1));
        mx0 = fmaxf(mx0, __shfl_xor_sync(0xffffffff, mx0, 2));
        mx1 = fmaxf(mx1, __shfl_xor_sync(0xffffffff, mx1, 1));
        mx1 = fmaxf(mx1, __shfl_xor_sync(0xffffffff, mx1, 2));

        float m0n = fmaxf(m0, mx0), m1n = fmaxf(m1, mx1);
        float c0 = ex2f(m0 - m0n), c1 = ex2f(m1 - m1n);
        float s0 = 0.f, s1 = 0.f;
        #pragma unroll
        for (int ni = 0; ni < 8; ni++) {
            float p0 = ex2f(sacc[ni][0] - m0n);
            float p1 = ex2f(sacc[ni][1] - m0n);
            float p2 = ex2f(sacc[ni][2] - m1n);
            float p3 = ex2f(sacc[ni][3] - m1n);
            sacc[ni][0] = p0; sacc[ni][1] = p1;
            sacc[ni][2] = p2; sacc[ni][3] = p3;
            s0 += p0 + p1; s1 += p2 + p3;
        }
        s0 += __shfl_xor_sync(0xffffffff, s0, 1);
        s0 += __shfl_xor_sync(0xffffffff, s0, 2);
        s1 += __shfl_xor_sync(0xffffffff, s1, 1);
        s1 += __shfl_xor_sync(0xffffffff, s1, 2);
        l0 = l0 * c0 + s0;
        l1 = l1 * c1 + s1;
        m0 = m0n; m1 = m1n;
        #pragma unroll
        for (int nj = 0; nj < 8; nj++) {
            oacc[nj][0] *= c0; oacc[nj][1] *= c0;
            oacc[nj][2] *= c1; oacc[nj][3] *= c1;
        }

        uint32_t aP[4][4];
        #pragma unroll
        for (int ks = 0; ks < 4; ks++) {
            aP[ks][0] = bf2pack(sacc[2*ks][0],     sacc[2*ks][1]);
            aP[ks][1] = bf2pack(sacc[2*ks][2],     sacc[2*ks][3]);
            aP[ks][2] = bf2pack(sacc[2*ks + 1][0], sacc[2*ks + 1][1]);
            aP[ks][3] = bf2pack(sacc[2*ks + 1][2], sacc[2*ks + 1][3]);
        }

        #pragma unroll
        for (int np = 0; np < 4; np++) {
            #pragma unroll
            for (int ks = 0; ks < 4; ks++) {
                uint32_t vb[4];
                uint32_t addr = vB +
                    ((ks * 16 + (lane & 7) + ((lane >> 3) & 1) * 8) * KSTR +
                     np * 16 + ((lane >> 4) & 1) * 8) * 2;
                asm volatile(
                    "ldmatrix.sync.aligned.m8n8.x4.trans.shared.b16 {%0,%1,%2,%3}, [%4];"
                    : "=r"(vb[0]), "=r"(vb[1]), "=r"(vb[2]), "=r"(vb[3]) : "r"(addr));
                MMA_BF16(oacc[np * 2],     aP[ks], vb[0], vb[1]);
                MMA_BF16(oacc[np * 2 + 1], aP[ks], vb[2], vb[3]);
            }
        }
    }

    float i0 = 1.f / l0, i1 = 1.f / l1;
    uint16_t* o0 = (uint16_t*)out + (size_t)(b * TT + qb + w * 16 + gid) * D + h * DH;
    uint16_t* o1 = o0 + (size_t)8 * D;
    #pragma unroll
    for (int nj = 0; nj < 8; nj++) {
        *(uint32_t*)(o0 + nj * 8 + tq * 2) = bf2pack(oacc[nj][0] * i0, oacc[nj][1] * i0);
        *(uint32_t*)(o1 + nj * 8 + tq * 2) = bf2pack(oacc[nj][2] * i1, oacc[nj][3] * i1);
    }
}

// ---------------------------------------------------------------------------
// launch
// ---------------------------------------------------------------------------
extern "C" void kernel_launch(void* const* d_in, const int* in_sizes, int n_in,
                              void* d_out, int out_size)
{
    (void)in_sizes; (void)n_in; (void)out_size;

    const float* in_x     = (const float*)d_in[0];
    const float* in_init0 = (const float*)d_in[1];
    const float* in_init1 = (const float*)d_in[2];
    // d_in[3] = mask: constant all-True -> unused
    const float* ln1_g = (const float*)d_in[4];
    const float* ln1_b = (const float*)d_in[5];
    const float* qkv_W = (const float*)d_in[6];
    const float* out_W = (const float*)d_in[7];
    const float* out_b = (const float*)d_in[8];
    const float* ln2_g = (const float*)d_in[9];
    const float* ln2_b = (const float*)d_in[10];
    const float* ff_W1 = (const float*)d_in[11];
    const float* ff_b1 = (const float*)d_in[12];
    const float* ff_W2 = (const float*)d_in[13];
    const float* ff_b2 = (const float*)d_in[14];
    const float* ln3_g = (const float*)d_in[15];
    const float* ln3_b = (const float*)d_in[16];
    const float* r0_W1 = (const float*)d_in[17];
    const float* r0_b1 = (const float*)d_in[18];
    const float* r0_W2 = (const float*)d_in[19];
    const float* r0_b2 = (const float*)d_in[20];
    const float* ln4_g = (const float*)d_in[21];
    const float* ln4_b = (const float*)d_in[22];
    const float* r1_W1 = (const float*)d_in[23];
    const float* r1_b1 = (const float*)d_in[24];
    const float* r1_W2 = (const float*)d_in[25];
    const float* r1_b2 = (const float*)d_in[26];

    static bool attr_done = false;
    if (!attr_done) {
        cudaFuncSetAttribute(gemm_bf16_kernel,
                             cudaFuncAttributeMaxDynamicSharedMemorySize, GEMM_SMEM);
        attr_done = true;
    }

    float *px;
    __nv_bfloat16 *pqkv, *ph, *po, *pmid, *pcat;
    __nv_bfloat16 *wqkv, *wout, *wff1, *wff2, *wr01, *wr02, *wr11;
    cudaGetSymbolAddress((void**)&px,   g_x);
    cudaGetSymbolAddress((void**)&pqkv, gb_qkv);
    cudaGetSymbolAddress((void**)&ph,   gb_h);
    cudaGetSymbolAddress((void**)&po,   gb_o);
    cudaGetSymbolAddress((void**)&pmid, gb_mid);
    cudaGetSymbolAddress((void**)&pcat, gb_cat);
    cudaGetSymbolAddress((void**)&wqkv, gb_wqkv);
    cudaGetSymbolAddress((void**)&wout, gb_wout);
    cudaGetSymbolAddress((void**)&wff1, gb_wff1);
    cudaGetSymbolAddress((void**)&wff2, gb_wff2);
    cudaGetSymbolAddress((void**)&wr01, gb_wr01);
    cudaGetSymbolAddress((void**)&wr02, gb_wr02);
    cudaGetSymbolAddress((void**)&wr11, gb_wr11);

    float* y0 = (float*)d_out;                 // [ROWS, O0]
    float* y1 = (float*)d_out + ROWS * O0;     // [ROWS, O1]

    cudaMemcpyAsync(px, in_x,     (size_t)ROWS * D  * sizeof(float), cudaMemcpyDeviceToDevice, 0);
    cudaMemcpyAsync(y0, in_init0, (size_t)ROWS * O0 * sizeof(float), cudaMemcpyDeviceToDevice, 0);
    cudaMemcpyAsync(y1, in_init1, (size_t)ROWS * O1 * sizeof(float), cudaMemcpyDeviceToDevice, 0);

    // ---- weight conversion (fp32 -> padded bf16) ----
    wconv_kernel<<<1024, 256>>>(qkv_W, wqkv, LAYERS * D,   NQKV, NQKV);
    wconv_kernel<<<1024, 256>>>(out_W, wout, LAYERS * D,   D,    D);
    wconv_kernel<<<1024, 256>>>(ff_W1, wff1, LAYERS * D,   MFF,  MFF);
    wconv_kernel<<<1024, 256>>>(ff_W2, wff2, LAYERS * MFF, D,    D);
    wconv_kernel<<<1024, 256>>>(r0_W1, wr01, LAYERS * K0c, MFF,  MFF);
    wconv_kernel<<<1024, 256>>>(r0_W2, wr02, LAYERS * MFF, O0,   LDW02);
    wconv_kernel<<<1024, 256>>>(r1_W1, wr11, LAYERS * K1c, MFF,  MFF);

    for (int l = 0; l < LAYERS; l++) {
        // --- attention block ---
        ln_kernel<<<ROWS / 4, 128>>>(px, ln1_g + l * D, ln1_b + l * D, ph, D);
        gemm_bf16_kernel<<<dim3(NQKV / BN, ROWS / BM), 256, GEMM_SMEM>>>(
            ph, wqkv + (size_t)l * D * NQKV, nullptr, nullptr, nullptr, pqkv,
            ROWS, NQKV, D, D, NQKV, NQKV, 0);
        attn_kernel<<<dim3(TT / 128, BB * H), 256>>>(pqkv, po);
        gemm_bf16_kernel<<<dim3(D / BN, ROWS / BM), 256, GEMM_SMEM>>>(
            po, wout + (size_t)l * D * D, out_b + l * D, px, px, nullptr,
            ROWS, D, D, D, D, 0, 1 | 4);

        // --- FFN block ---
        ln_kernel<<<ROWS / 4, 128>>>(px, ln2_g + l * D, ln2_b + l * D, ph, D);
        gemm_bf16_kernel<<<dim3(MFF / BN, ROWS / BM), 256, GEMM_SMEM>>>(
            ph, wff1 + (size_t)l * D * MFF, ff_b1 + l * MFF, nullptr, nullptr, pmid,
            ROWS, MFF, D, D, MFF, MFF, 1 | 2);
        gemm_bf16_kernel<<<dim3(D / BN, ROWS / BM), 256, GEMM_SMEM>>>(
            pmid, wff2 + (size_t)l * MFF * D, ff_b2 + l * D, px, px, nullptr,
            ROWS, D, MFF, MFF, D, 0, 1 | 4);

        // --- regressor 0 (LN writes directly into cat buffer) ---
        ln_kernel<<<ROWS / 4, 128>>>(px, ln3_g + l * D, ln3_b + l * D, pcat, LDC0);
        concat_y_kernel<<<1024, 256>>>(pcat, y0, O0, ROWS, LDC0);
        gemm_bf16_kernel<<<dim3(MFF / BN, ROWS / BM), 256, GEMM_SMEM>>>(
            pcat, wr01 + (size_t)l * K0c * MFF, r0_b1 + l * MFF, nullptr, nullptr, pmid,
            ROWS, MFF, K0c, LDC0, MFF, MFF, 1 | 2);
        gemm_bf16_kernel<<<dim3((O0 + BN - 1) / BN, ROWS / BM), 256, GEMM_SMEM>>>(
            pmid, wr02 + (size_t)l * MFF * LDW02, r0_b2 + l * O0, y0, y0, nullptr,
            ROWS, O0, MFF, MFF, LDW02, 0, 1 | 4);

        // --- regressor 1 ---
        ln_kernel<<<ROWS / 4, 128>>>(px, ln4_g + l * D, ln4_b + l * D, pcat, LDC1);
        concat_y_kernel<<<1024, 256>>>(pcat, y1, O1, ROWS, LDC1);
        gemm_bf16_kernel<<<dim3(MFF / BN, ROWS / BM), 256, GEMM_SMEM>>>(
            pcat, wr11 + (size_t)l * K1c * MFF, r1_b1 + l * MFF, nullptr, nullptr, pmid,
            ROWS, MFF, K1c, LDC1, MFF, MFF, 1 | 2);
        rowdot3_kernel<<<128, 256>>>(pmid, r1_W2 + (size_t)l * MFF * O1,
                                     r1_b2 + l * O1, y1);
    }
}

// round 15
// speedup vs baseline: 8.1140x; 1.1341x over previous
#include <cuda_runtime.h>
#include <cuda_bf16.h>
#include <math.h>
#include <stdint.h>

// Problem constants
#define LAYERS 2
#define D 512
#define H 8
#define DH 64
#define MFF 2048
#define O0 132
#define O1 3
#define BB 2
#define TT 2048
#define ROWS (BB*TT)          // 4096
#define EPS 1e-5f

#define NQKV 1536
#define K0c 644               // D+O0
#define K1c 515               // D+O1
#define LDC0 648              // cat0 stride (mod 8 == 0)
#define LDC1 520              // cat1 stride (mod 8 == 0)
#define LDW02 136             // r0_W2 padded N stride

// ---------------------------------------------------------------------------
// Scratch (device globals; no runtime allocation allowed)
// ---------------------------------------------------------------------------
__device__ float g_x  [ROWS * D];          // residual stream (fp32)

__device__ __nv_bfloat16 gb_qkv [ROWS * NQKV];
__device__ __nv_bfloat16 gb_h   [ROWS * D];
__device__ __nv_bfloat16 gb_o   [ROWS * D];
__device__ __nv_bfloat16 gb_mid [ROWS * MFF];   // FFN hidden (main stream)
__device__ __nv_bfloat16 gb_mid0[ROWS * MFF];   // reg0 hidden (stream s0)
__device__ __nv_bfloat16 gb_mid1[ROWS * MFF];   // reg1 hidden (stream s1)
__device__ __nv_bfloat16 gb_cat0[ROWS * LDC0];
__device__ __nv_bfloat16 gb_cat1[ROWS * LDC1];

__device__ __nv_bfloat16 gb_wqkv[LAYERS * D * NQKV];
__device__ __nv_bfloat16 gb_wout[LAYERS * D * D];
__device__ __nv_bfloat16 gb_wff1[LAYERS * D * MFF];
__device__ __nv_bfloat16 gb_wff2[LAYERS * MFF * D];
__device__ __nv_bfloat16 gb_wr01[LAYERS * K0c * MFF];
__device__ __nv_bfloat16 gb_wr02[LAYERS * MFF * LDW02];
__device__ __nv_bfloat16 gb_wr11[LAYERS * K1c * MFF];

__device__ __forceinline__ uint32_t bf2pack(float lo, float hi) {
    __nv_bfloat162 h = __floats2bfloat162_rn(lo, hi);
    return *reinterpret_cast<uint32_t*>(&h);
}

__device__ __forceinline__ float2 bfunpack(uint32_t u) {
    __nv_bfloat162 h = *reinterpret_cast<__nv_bfloat162*>(&u);
    return __bfloat1622float2(h);
}

__device__ __forceinline__ float ex2f(float x) {
    float y;
    asm("ex2.approx.f32 %0, %1;" : "=f"(y) : "f"(x));
    return y;
}

#define MMA_BF16(acc, a, b0v, b1v)                                          \
    asm volatile(                                                           \
        "mma.sync.aligned.m16n8k16.row.col.f32.bf16.bf16.f32 "              \
        "{%0,%1,%2,%3}, {%4,%5,%6,%7}, {%8,%9}, {%0,%1,%2,%3};"             \
        : "+f"((acc)[0]), "+f"((acc)[1]), "+f"((acc)[2]), "+f"((acc)[3])    \
        : "r"((a)[0]), "r"((a)[1]), "r"((a)[2]), "r"((a)[3]),               \
          "r"(b0v), "r"(b1v))

// ---------------------------------------------------------------------------
// Weight fp32 -> bf16 with padded/zeroed N stride (fast path when no pad)
// ---------------------------------------------------------------------------
__global__ void wconv_kernel(const float* __restrict__ src,
                             __nv_bfloat16* __restrict__ dst,
                             int rows, int N, int ldb)
{
    if (N == ldb && (N & 7) == 0) {
        int total8 = rows * (N >> 3);
        for (int idx = blockIdx.x * blockDim.x + threadIdx.x; idx < total8;
             idx += gridDim.x * blockDim.x) {
            const float4* s = (const float4*)(src + (size_t)idx * 8);
            float4 a = s[0], b2 = s[1];
            uint4 u;
            u.x = bf2pack(a.x, a.y);   u.y = bf2pack(a.z, a.w);
            u.z = bf2pack(b2.x, b2.y); u.w = bf2pack(b2.z, b2.w);
            reinterpret_cast<uint4*>(dst)[idx] = u;
        }
        return;
    }
    int half = ldb >> 1;
    int total = rows * half;
    for (int idx = blockIdx.x * blockDim.x + threadIdx.x; idx < total;
         idx += gridDim.x * blockDim.x) {
        int r = idx / half;
        int c = (idx - r * half) * 2;
        float v0 = (c     < N) ? src[(size_t)r * N + c]     : 0.f;
        float v1 = (c + 1 < N) ? src[(size_t)r * N + c + 1] : 0.f;
        reinterpret_cast<uint32_t*>(dst)[(size_t)r * half + (c >> 1)] = bf2pack(v0, v1);
    }
}

// ---------------------------------------------------------------------------
// LayerNorm: warp per row (4 rows/block), D=512; bf16 output with stride ldo.
// ---------------------------------------------------------------------------
__global__ __launch_bounds__(128) void ln_kernel(const float* __restrict__ x,
                                                 const float* __restrict__ g,
                                                 const float* __restrict__ b,
                                                 __nv_bfloat16* __restrict__ out,
                                                 int ldo)
{
    const int row  = blockIdx.x * 4 + (threadIdx.x >> 5);
    const int lane = threadIdx.x & 31;
    const float4* xr = (const float4*)(x + (size_t)row * D);

    float4 v[4];
    float s = 0.f;
    #pragma unroll
    for (int i = 0; i < 4; i++) {
        v[i] = xr[lane + 32 * i];
        s += v[i].x + v[i].y + v[i].z + v[i].w;
    }
    #pragma unroll
    for (int off = 16; off > 0; off >>= 1)
        s += __shfl_xor_sync(0xffffffff, s, off);
    float mu = s * (1.f / D);

    float var = 0.f;
    #pragma unroll
    for (int i = 0; i < 4; i++) {
        v[i].x -= mu; v[i].y -= mu; v[i].z -= mu; v[i].w -= mu;
        var += v[i].x*v[i].x + v[i].y*v[i].y + v[i].z*v[i].z + v[i].w*v[i].w;
    }
    #pragma unroll
    for (int off = 16; off > 0; off >>= 1)
        var += __shfl_xor_sync(0xffffffff, var, off);
    float inv = rsqrtf(var * (1.f / D) + EPS);

    uint16_t* orow = (uint16_t*)out + (size_t)row * ldo;
    #pragma unroll
    for (int i = 0; i < 4; i++) {
        int e = (lane + 32 * i) * 4;
        const float4 g4 = *(const float4*)(g + e);
        const float4 b4 = *(const float4*)(b + e);
        float o0 = v[i].x * inv * g4.x + b4.x;
        float o1 = v[i].y * inv * g4.y + b4.y;
        float o2 = v[i].z * inv * g4.z + b4.z;
        float o3 = v[i].w * inv * g4.w + b4.w;
        uint2 u; u.x = bf2pack(o0, o1); u.y = bf2pack(o2, o3);
        *(uint2*)(orow + e) = u;
    }
}

// ---------------------------------------------------------------------------
// concat_y: fill columns [D, dstr) of dst with (bf16)y[:, 0:nb] then zero pad
// ---------------------------------------------------------------------------
__global__ void concat_y_kernel(__nv_bfloat16* __restrict__ dst,
                                const float* __restrict__ y, int nb, int rows,
                                int dstr)
{
    int w = dstr - D;
    int total = rows * w;
    for (int idx = blockIdx.x * blockDim.x + threadIdx.x; idx < total;
         idx += gridDim.x * blockDim.x) {
        int r = idx / w, c = idx - r * w;
        dst[(size_t)r * dstr + D + c] =
            (c < nb) ? __float2bfloat16(y[(size_t)r * nb + c])
                     : __float2bfloat16(0.f);
    }
}

// ---------------------------------------------------------------------------
// BF16 tensor-core GEMM, 4-stage cp.async pipeline, 2 CTAs/SM. (verified R13)
// ---------------------------------------------------------------------------
#define BM 128
#define BN 128
#define BKT 32
#define ASTR 40
#define BSTR 136
#define STAGE_BYTES (BM*ASTR*2 + BKT*BSTR*2)
#define A_PART (BM*ASTR*2)
#define NSTAGE 4
#define GEMM_SMEM (NSTAGE*STAGE_BYTES)

__global__ __launch_bounds__(256, 2) void gemm_bf16_kernel(
    const __nv_bfloat16* __restrict__ A, const __nv_bfloat16* __restrict__ B,
    const float* __restrict__ bias, const float* __restrict__ res,
    float* __restrict__ Cf, __nv_bfloat16* __restrict__ Cb,
    int M, int N, int K, int lda, int ldb, int ldcb, int flags)
{
    extern __shared__ __align__(16) uint16_t smem_dyn[];
    const uint32_t sBase = (uint32_t)__cvta_generic_to_shared(smem_dyn);

    const int tid  = threadIdx.x;
    const int lane = tid & 31;
    const int wid  = tid >> 5;
    const int wm   = wid >> 2;
    const int wn   = wid & 3;
    const int lr   = lane >> 2;
    const int lc   = lane & 3;

    const int m0 = blockIdx.y * BM;
    const int n0 = blockIdx.x * BN;

    const int a_r  = (lane & 7) + ((lane >> 3) & 1) * 8;
    const int a_kc = (lane >> 4) * 8;
    const int b_kr = (lane & 7) + ((lane >> 3) & 1) * 8;
    const int b_nc = (lane >> 4) * 8;

    float acc[4][4][4];
    #pragma unroll
    for (int i = 0; i < 4; i++)
        #pragma unroll
        for (int j = 0; j < 4; j++)
            #pragma unroll
            for (int r = 0; r < 4; r++) acc[i][j][r] = 0.f;

    const int nkt = (K + BKT - 1) / BKT;

    auto load_tile = [&](int t, int stage) {
        const int k0 = t * BKT;
        const uint32_t sA = sBase + stage * STAGE_BYTES;
        const uint32_t sB = sA + A_PART;
        #pragma unroll
        for (int i = 0; i < 2; i++) {
            int c   = tid + i * 256;
            int row = c >> 2;
            int col = (c & 3) * 8;
            int gk  = k0 + col;
            int avail = lda - gk;
            int bytes = (avail <= 0) ? 0 : (avail >= 8 ? 16 : avail * 2);
            const __nv_bfloat16* src = bytes ? (A + (size_t)(m0 + row) * lda + gk) : A;
            uint32_t dst = sA + (row * ASTR + col) * 2;
            asm volatile("cp.async.cg.shared.global [%0], [%1], 16, %2;"
                         :: "r"(dst), "l"(src), "r"(bytes));
        }
        #pragma unroll
        for (int i = 0; i < 2; i++) {
            int c   = tid + i * 256;
            int row = c >> 4;
            int col = (c & 15) * 8;
            int gk  = k0 + row;
            int gn  = n0 + col;
            int bytes = (gk < K && gn + 8 <= ldb) ? 16 : 0;
            const __nv_bfloat16* src = bytes ? (B + (size_t)gk * ldb + gn) : B;
            uint32_t dst = sB + (row * BSTR + col) * 2;
            asm volatile("cp.async.cg.shared.global [%0], [%1], 16, %2;"
                         :: "r"(dst), "l"(src), "r"(bytes));
        }
        asm volatile("cp.async.commit_group;");
    };

    #pragma unroll
    for (int s = 0; s < NSTAGE - 1; s++) {
        if (s < nkt) load_tile(s, s);
        else asm volatile("cp.async.commit_group;");
    }

    for (int t = 0; t < nkt; t++) {
        asm volatile("cp.async.wait_group %0;" :: "n"(NSTAGE - 2));
        __syncthreads();
        if (t + NSTAGE - 1 < nkt) load_tile(t + NSTAGE - 1, (t + NSTAGE - 1) & (NSTAGE - 1));
        else asm volatile("cp.async.commit_group;");

        const uint32_t aB = sBase + (t & (NSTAGE - 1)) * STAGE_BYTES;
        const uint32_t bB = aB + A_PART;

        #pragma unroll
        for (int kk = 0; kk < BKT; kk += 16) {
            uint32_t af[4][4];
            #pragma unroll
            for (int mi = 0; mi < 4; mi++) {
                uint32_t addr = aB + ((wm * 64 + mi * 16 + a_r) * ASTR + kk + a_kc) * 2;
                asm volatile(
                    "ldmatrix.sync.aligned.m8n8.x4.shared.b16 {%0,%1,%2,%3}, [%4];"
                    : "=r"(af[mi][0]), "=r"(af[mi][1]),
                      "=r"(af[mi][2]), "=r"(af[mi][3]) : "r"(addr));
            }
            uint32_t bfp[2][4];
            #pragma unroll
            for (int pr = 0; pr < 2; pr++) {
                uint32_t addr = bB + ((kk + b_kr) * BSTR + wn * 32 + pr * 16 + b_nc) * 2;
                asm volatile(
                    "ldmatrix.sync.aligned.m8n8.x4.trans.shared.b16 {%0,%1,%2,%3}, [%4];"
                    : "=r"(bfp[pr][0]), "=r"(bfp[pr][1]),
                      "=r"(bfp[pr][2]), "=r"(bfp[pr][3]) : "r"(addr));
            }
            #pragma unroll
            for (int mi = 0; mi < 4; mi++)
                #pragma unroll
                for (int ni = 0; ni < 4; ni++) {
                    uint32_t b0 = bfp[ni >> 1][(ni & 1) * 2];
                    uint32_t b1 = bfp[ni >> 1][(ni & 1) * 2 + 1];
                    MMA_BF16(acc[mi][ni], af[mi], b0, b1);
                }
        }
        __syncthreads();
    }

    #pragma unroll
    for (int mi = 0; mi < 4; mi++) {
        #pragma unroll
        for (int ni = 0; ni < 4; ni++) {
            int row = m0 + wm * 64 + mi * 16 + lr;
            int col = n0 + wn * 32 + ni * 8 + lc * 2;
            float v[4];
            #pragma unroll
            for (int r = 0; r < 4; r++) {
                int rr = row + (r >> 1) * 8;
                int cc = col + (r & 1);
                float x = acc[mi][ni][r];
                if (cc < N) {
                    if (flags & 1) x += bias[cc];
                    if (flags & 2) x = 0.5f * x * (1.f + erff(x * 0.70710678118654752f));
                    if (flags & 4) x += res[(size_t)rr * N + cc];
                    if (Cf) Cf[(size_t)rr * N + cc] = x;
                }
                v[r] = x;
            }
            if (Cb && col + 2 <= N) {
                reinterpret_cast<uint32_t*>(Cb)[((size_t)row * ldcb + col) >> 1]       = bf2pack(v[0], v[1]);
                reinterpret_cast<uint32_t*>(Cb)[((size_t)(row + 8) * ldcb + col) >> 1] = bf2pack(v[2], v[3]);
            }
        }
    }
}

// ---------------------------------------------------------------------------
// rowdot3: y[r,0..2] += A[r,:] @ W[:,0..2] + bias   (N=3, K=2048)
// ---------------------------------------------------------------------------
__global__ __launch_bounds__(256) void rowdot3_kernel(
    const __nv_bfloat16* __restrict__ A, const float* __restrict__ W,
    const float* __restrict__ bias, float* __restrict__ y)
{
    __shared__ uint16_t Ws[3][MFF];
    const int tid  = threadIdx.x;
    const int lane = tid & 31;
    const int w    = tid >> 5;

    for (int i = tid; i < 3 * MFF; i += 256) {
        int c = i / MFF, k = i - c * MFF;
        __nv_bfloat16 hv = __float2bfloat16(W[(size_t)k * O1 + c]);
        Ws[c][k] = *reinterpret_cast<const uint16_t*>(&hv);
    }
    __syncthreads();

    const float b0 = bias[0], b1 = bias[1], b2 = bias[2];
    #pragma unroll
    for (int r = 0; r < 4; r++) {
        int row = blockIdx.x * 32 + w * 4 + r;
        const uint4* arow = (const uint4*)(A + (size_t)row * MFF);
        float a0 = 0.f, a1 = 0.f, a2 = 0.f;
        #pragma unroll
        for (int i = 0; i < MFF / 8 / 32; i++) {
            int idx = lane + i * 32;
            uint4 av = arow[idx];
            uint4 w0 = ((const uint4*)Ws[0])[idx];
            uint4 w1 = ((const uint4*)Ws[1])[idx];
            uint4 w2 = ((const uint4*)Ws[2])[idx];
            const uint32_t* ap = (const uint32_t*)&av;
            const uint32_t* p0 = (const uint32_t*)&w0;
            const uint32_t* p1 = (const uint32_t*)&w1;
            const uint32_t* p2 = (const uint32_t*)&w2;
            #pragma unroll
            for (int j = 0; j < 4; j++) {
                float2 a = bfunpack(ap[j]);
                float2 f0 = bfunpack(p0[j]);
                float2 f1 = bfunpack(p1[j]);
                float2 f2 = bfunpack(p2[j]);
                a0 = fmaf(a.x, f0.x, fmaf(a.y, f0.y, a0));
                a1 = fmaf(a.x, f1.x, fmaf(a.y, f1.y, a1));
                a2 = fmaf(a.x, f2.x, fmaf(a.y, f2.y, a2));
            }
        }
        #pragma unroll
        for (int off = 16; off > 0; off >>= 1) {
            a0 += __shfl_xor_sync(0xffffffff, a0, off);
            a1 += __shfl_xor_sync(0xffffffff, a1, off);
            a2 += __shfl_xor_sync(0xffffffff, a2, off);
        }
        if (lane == 0) {
            float* yr = y + (size_t)row * O1;
            yr[0] += a0 + b0;
            yr[1] += a1 + b1;
            yr[2] += a2 + b2;
        }
    }
}

// ---------------------------------------------------------------------------
// Tensor-core flash attention (verified Round 9)
// ---------------------------------------------------------------------------
#define KSTR 72
#define KV_ST_BYTES (64*KSTR*2)

__global__ __launch_bounds__(256) void attn_kernel(
    const __nv_bfloat16* __restrict__ qkv, __nv_bfloat16* __restrict__ out)
{
    __shared__ __align__(16) uint16_t Ks[2][64][KSTR];
    __shared__ __align__(16) uint16_t Vs[2][64][KSTR];

    const int tid  = threadIdx.x;
    const int lane = tid & 31;
    const int w    = tid >> 5;
    const int gid  = lane >> 2;
    const int tq   = lane & 3;
    const int qb   = blockIdx.x * 128;
    const int b    = blockIdx.y >> 3;
    const int h    = blockIdx.y & 7;

    uint32_t qf[4][4];
    {
        const uint16_t* q0 = (const uint16_t*)qkv +
            (size_t)(b * TT + qb + w * 16 + gid) * NQKV + h * DH;
        const uint16_t* q1 = q0 + (size_t)8 * NQKV;
        #pragma unroll
        for (int ks = 0; ks < 4; ks++) {
            qf[ks][0] = *(const uint32_t*)(q0 + ks * 16 + tq * 2);
            qf[ks][1] = *(const uint32_t*)(q1 + ks * 16 + tq * 2);
            qf[ks][2] = *(const uint32_t*)(q0 + ks * 16 + 8 + tq * 2);
            qf[ks][3] = *(const uint32_t*)(q1 + ks * 16 + 8 + tq * 2);
        }
    }

    const uint32_t kBase = (uint32_t)__cvta_generic_to_shared(&Ks[0][0][0]);
    const uint32_t vBase = (uint32_t)__cvta_generic_to_shared(&Vs[0][0][0]);

    float oacc[8][4];
    #pragma unroll
    for (int i = 0; i < 8; i++)
        #pragma unroll
        for (int j = 0; j < 4; j++) oacc[i][j] = 0.f;
    float m0 = -1e30f, m1 = -1e30f, l0 = 0.f, l1 = 0.f;

    auto load_kv = [&](int t, int buf) {
        #pragma unroll
        for (int i = 0; i < 2; i++) {
            int idx = tid + i * 256;
            int row = idx >> 3;
            int ch  = (idx & 7) * 8;
            const uint16_t* src = (const uint16_t*)qkv +
                (size_t)(b * TT + t * 64 + row) * NQKV + h * DH + ch;
            uint32_t kd = kBase + buf * KV_ST_BYTES + (row * KSTR + ch) * 2;
            uint32_t vd = vBase + buf * KV_ST_BYTES + (row * KSTR + ch) * 2;
            asm volatile("cp.async.cg.shared.global [%0], [%1], 16;"
                         :: "r"(kd), "l"(src + 512) : "memory");
            asm volatile("cp.async.cg.shared.global [%0], [%1], 16;"
                         :: "r"(vd), "l"(src + 1024) : "memory");
        }
        asm volatile("cp.async.commit_group;");
    };

    load_kv(0, 0);

    const float sc = 0.125f * 1.4426950408889634f;

    for (int t = 0; t < TT / 64; t++) {
        asm volatile("cp.async.wait_group 0;");
        __syncthreads();
        if (t + 1 < TT / 64) load_kv(t + 1, (t + 1) & 1);

        const uint32_t kB = kBase + (t & 1) * KV_ST_BYTES;
        const uint32_t vB = vBase + (t & 1) * KV_ST_BYTES;

        float sacc[8][4];
        #pragma unroll
        for (int i = 0; i < 8; i++)
            #pragma unroll
            for (int j = 0; j < 4; j++) sacc[i][j] = 0.f;

        #pragma unroll
        for (int np = 0; np < 4; np++) {
            #pragma unroll
            for (int ks = 0; ks < 4; ks++) {
                uint32_t kb[4];
                uint32_t addr = kB +
                    ((np * 16 + (lane & 7) + ((lane >> 4) & 1) * 8) * KSTR +
                     ks * 16 + ((lane >> 3) & 1) * 8) * 2;
                asm volatile(
                    "ldmatrix.sync.aligned.m8n8.x4.shared.b16 {%0,%1,%2,%3}, [%4];"
                    : "=r"(kb[0]), "=r"(kb[1]), "=r"(kb[2]), "=r"(kb[3]) : "r"(addr));
                MMA_BF16(sacc[np * 2],     qf[ks], kb[0], kb[1]);
                MMA_BF16(sacc[np * 2 + 1], qf[ks], kb[2], kb[3]);
            }
        }

        float mx0 = -1e30f, mx1 = -1e30f;
        #pragma unroll
        for (int ni = 0; ni < 8; ni++) {
            sacc[ni][0] *= sc; sacc[ni][1] *= sc;
            sacc[ni][2] *= sc; sacc[ni][3] *= sc;
            mx0 = fmaxf(mx0, fmaxf(sacc[ni][0], sacc[ni][1]));
            mx1 = fmaxf(mx1, fmaxf(sacc[ni][2], sacc[ni][3]));
        }
        mx0 = fmaxf(mx0, __shfl_xor_sync(0xffffffff, mx0, 1));
        mx0 = fmaxf(mx0, __shfl_xor_sync(0xffffffff, mx0, 2));
        mx1 = fmaxf(mx1, __shfl_xor_sync(0xffffffff, mx1, 1));
        mx1 = fmaxf(mx1, __shfl_xor_sync(0xffffffff, mx1, 2));

        float m0n = fmaxf(m0, mx0), m1n = fmaxf(m1, mx1);
        float c0 = ex2f(m0 - m0n), c1 = ex2f(m1 - m1n);
        float s0 = 0.f, s1 = 0.f;
        #pragma unroll
        for (int ni = 0; ni < 8; ni++) {
            float p0 = ex2f(sacc[ni][0] - m0n);
            float p1 = ex2f(sacc[ni][1] - m0n);
            float p2 = ex2f(sacc[ni][2] - m1n);
            float p3 = ex2f(sacc[ni][3] - m1n);
            sacc[ni][0] = p0; sacc[ni][1] = p1;
            sacc[ni][2] = p2; sacc[ni][3] = p3;
            s0 += p0 + p1; s1 += p2 + p3;
        }
        s0 += __shfl_xor_sync(0xffffffff, s0, 1);
        s0 += __shfl_xor_sync(0xffffffff, s0, 2);
        s1 += __shfl_xor_sync(0xffffffff, s1, 1);
        s1 += __shfl_xor_sync(0xffffffff, s1, 2);
        l0 = l0 * c0 + s0;
        l1 = l1 * c1 + s1;
        m0 = m0n; m1 = m1n;
        #pragma unroll
        for (int nj = 0; nj < 8; nj++) {
            oacc[nj][0] *= c0; oacc[nj][1] *= c0;
            oacc[nj][2] *= c1; oacc[nj][3] *= c1;
        }

        uint32_t aP[4][4];
        #pragma unroll
        for (int ks = 0; ks < 4; ks++) {
            aP[ks][0] = bf2pack(sacc[2*ks][0],     sacc[2*ks][1]);
            aP[ks][1] = bf2pack(sacc[2*ks][2],     sacc[2*ks][3]);
            aP[ks][2] = bf2pack(sacc[2*ks + 1][0], sacc[2*ks + 1][1]);
            aP[ks][3] = bf2pack(sacc[2*ks + 1][2], sacc[2*ks + 1][3]);
        }

        #pragma unroll
        for (int np = 0; np < 4; np++) {
            #pragma unroll
            for (int ks = 0; ks < 4; ks++) {
                uint32_t vb[4];
                uint32_t addr = vB +
                    ((ks * 16 + (lane & 7) + ((lane >> 3) & 1) * 8) * KSTR +
                     np * 16 + ((lane >> 4) & 1) * 8) * 2;
                asm volatile(
                    "ldmatrix.sync.aligned.m8n8.x4.trans.shared.b16 {%0,%1,%2,%3}, [%4];"
                    : "=r"(vb[0]), "=r"(vb[1]), "=r"(vb[2]), "=r"(vb[3]) : "r"(addr));
                MMA_BF16(oacc[np * 2],     aP[ks], vb[0], vb[1]);
                MMA_BF16(oacc[np * 2 + 1], aP[ks], vb[2], vb[3]);
            }
        }
    }

    float i0 = 1.f / l0, i1 = 1.f / l1;
    uint16_t* o0 = (uint16_t*)out + (size_t)(b * TT + qb + w * 16 + gid) * D + h * DH;
    uint16_t* o1 = o0 + (size_t)8 * D;
    #pragma unroll
    for (int nj = 0; nj < 8; nj++) {
        *(uint32_t*)(o0 + nj * 8 + tq * 2) = bf2pack(oacc[nj][0] * i0, oacc[nj][1] * i0);
        *(uint32_t*)(o1 + nj * 8 + tq * 2) = bf2pack(oacc[nj][2] * i1, oacc[nj][3] * i1);
    }
}

// ---------------------------------------------------------------------------
// launch — main stream runs attn+FFN; streams s0/s1 run the two regressor
// chains overlapped (they only read x; events enforce the x WAR hazard).
// ---------------------------------------------------------------------------
extern "C" void kernel_launch(void* const* d_in, const int* in_sizes, int n_in,
                              void* d_out, int out_size)
{
    (void)in_sizes; (void)n_in; (void)out_size;

    const float* in_x     = (const float*)d_in[0];
    const float* in_init0 = (const float*)d_in[1];
    const float* in_init1 = (const float*)d_in[2];
    // d_in[3] = mask: constant all-True -> unused
    const float* ln1_g = (const float*)d_in[4];
    const float* ln1_b = (const float*)d_in[5];
    const float* qkv_W = (const float*)d_in[6];
    const float* out_W = (const float*)d_in[7];
    const float* out_b = (const float*)d_in[8];
    const float* ln2_g = (const float*)d_in[9];
    const float* ln2_b = (const float*)d_in[10];
    const float* ff_W1 = (const float*)d_in[11];
    const float* ff_b1 = (const float*)d_in[12];
    const float* ff_W2 = (const float*)d_in[13];
    const float* ff_b2 = (const float*)d_in[14];
    const float* ln3_g = (const float*)d_in[15];
    const float* ln3_b = (const float*)d_in[16];
    const float* r0_W1 = (const float*)d_in[17];
    const float* r0_b1 = (const float*)d_in[18];
    const float* r0_W2 = (const float*)d_in[19];
    const float* r0_b2 = (const float*)d_in[20];
    const float* ln4_g = (const float*)d_in[21];
    const float* ln4_b = (const float*)d_in[22];
    const float* r1_W1 = (const float*)d_in[23];
    const float* r1_b1 = (const float*)d_in[24];
    const float* r1_W2 = (const float*)d_in[25];
    const float* r1_b2 = (const float*)d_in[26];

    static bool init_done = false;
    static cudaStream_t st0, st1;
    static cudaEvent_t e_x[LAYERS], e_ln3[LAYERS], e_ln4[LAYERS], e_r0, e_r1;
    if (!init_done) {
        cudaFuncSetAttribute(gemm_bf16_kernel,
                             cudaFuncAttributeMaxDynamicSharedMemorySize, GEMM_SMEM);
        cudaStreamCreateWithFlags(&st0, cudaStreamNonBlocking);
        cudaStreamCreateWithFlags(&st1, cudaStreamNonBlocking);
        for (int l = 0; l < LAYERS; l++) {
            cudaEventCreateWithFlags(&e_x[l],   cudaEventDisableTiming);
            cudaEventCreateWithFlags(&e_ln3[l], cudaEventDisableTiming);
            cudaEventCreateWithFlags(&e_ln4[l], cudaEventDisableTiming);
        }
        cudaEventCreateWithFlags(&e_r0, cudaEventDisableTiming);
        cudaEventCreateWithFlags(&e_r1, cudaEventDisableTiming);
        init_done = true;
    }

    float *px;
    __nv_bfloat16 *pqkv, *ph, *po, *pmid, *pmid0, *pmid1, *pcat0, *pcat1;
    __nv_bfloat16 *wqkv, *wout, *wff1, *wff2, *wr01, *wr02, *wr11;
    cudaGetSymbolAddress((void**)&px,    g_x);
    cudaGetSymbolAddress((void**)&pqkv,  gb_qkv);
    cudaGetSymbolAddress((void**)&ph,    gb_h);
    cudaGetSymbolAddress((void**)&po,    gb_o);
    cudaGetSymbolAddress((void**)&pmid,  gb_mid);
    cudaGetSymbolAddress((void**)&pmid0, gb_mid0);
    cudaGetSymbolAddress((void**)&pmid1, gb_mid1);
    cudaGetSymbolAddress((void**)&pcat0, gb_cat0);
    cudaGetSymbolAddress((void**)&pcat1, gb_cat1);
    cudaGetSymbolAddress((void**)&wqkv,  gb_wqkv);
    cudaGetSymbolAddress((void**)&wout,  gb_wout);
    cudaGetSymbolAddress((void**)&wff1,  gb_wff1);
    cudaGetSymbolAddress((void**)&wff2,  gb_wff2);
    cudaGetSymbolAddress((void**)&wr01,  gb_wr01);
    cudaGetSymbolAddress((void**)&wr02,  gb_wr02);
    cudaGetSymbolAddress((void**)&wr11,  gb_wr11);

    float* y0 = (float*)d_out;                 // [ROWS, O0]
    float* y1 = (float*)d_out + ROWS * O0;     // [ROWS, O1]

    cudaMemcpyAsync(px, in_x,     (size_t)ROWS * D  * sizeof(float), cudaMemcpyDeviceToDevice, 0);
    cudaMemcpyAsync(y0, in_init0, (size_t)ROWS * O0 * sizeof(float), cudaMemcpyDeviceToDevice, 0);
    cudaMemcpyAsync(y1, in_init1, (size_t)ROWS * O1 * sizeof(float), cudaMemcpyDeviceToDevice, 0);

    // ---- weight conversion (fp32 -> padded bf16), main stream ----
    wconv_kernel<<<1024, 256>>>(qkv_W, wqkv, LAYERS * D,   NQKV, NQKV);
    wconv_kernel<<<1024, 256>>>(out_W, wout, LAYERS * D,   D,    D);
    wconv_kernel<<<1024, 256>>>(ff_W1, wff1, LAYERS * D,   MFF,  MFF);
    wconv_kernel<<<1024, 256>>>(ff_W2, wff2, LAYERS * MFF, D,    D);
    wconv_kernel<<<1024, 256>>>(r0_W1, wr01, LAYERS * K0c, MFF,  MFF);
    wconv_kernel<<<1024, 256>>>(r0_W2, wr02, LAYERS * MFF, O0,   LDW02);
    wconv_kernel<<<1024, 256>>>(r1_W1, wr11, LAYERS * K1c, MFF,  MFF);

    for (int l = 0; l < LAYERS; l++) {
        // --- main stream: attention block ---
        ln_kernel<<<ROWS / 4, 128>>>(px, ln1_g + l * D, ln1_b + l * D, ph, D);
        gemm_bf16_kernel<<<dim3(NQKV / BN, ROWS / BM), 256, GEMM_SMEM>>>(
            ph, wqkv + (size_t)l * D * NQKV, nullptr, nullptr, nullptr, pqkv,
            ROWS, NQKV, D, D, NQKV, NQKV, 0);
        attn_kernel<<<dim3(TT / 128, BB * H), 256>>>(pqkv, po);
        if (l > 0) {   // out-proj writes x: wait for last readers (ln3/ln4 of l-1)
            cudaStreamWaitEvent(0, e_ln3[l - 1], 0);
            cudaStreamWaitEvent(0, e_ln4[l - 1], 0);
        }
        gemm_bf16_kernel<<<dim3(D / BN, ROWS / BM), 256, GEMM_SMEM>>>(
            po, wout + (size_t)l * D * D, out_b + l * D, px, px, nullptr,
            ROWS, D, D, D, D, 0, 1 | 4);

        // --- main stream: FFN block ---
        ln_kernel<<<ROWS / 4, 128>>>(px, ln2_g + l * D, ln2_b + l * D, ph, D);
        gemm_bf16_kernel<<<dim3(MFF / BN, ROWS / BM), 256, GEMM_SMEM>>>(
            ph, wff1 + (size_t)l * D * MFF, ff_b1 + l * MFF, nullptr, nullptr, pmid,
            ROWS, MFF, D, D, MFF, MFF, 1 | 2);
        gemm_bf16_kernel<<<dim3(D / BN, ROWS / BM), 256, GEMM_SMEM>>>(
            pmid, wff2 + (size_t)l * MFF * D, ff_b2 + l * D, px, px, nullptr,
            ROWS, D, MFF, MFF, D, 0, 1 | 4);
        cudaEventRecord(e_x[l], 0);

        // --- stream s0: regressor 0 ---
        cudaStreamWaitEvent(st0, e_x[l], 0);
        ln_kernel<<<ROWS / 4, 128, 0, st0>>>(px, ln3_g + l * D, ln3_b + l * D, pcat0, LDC0);
        cudaEventRecord(e_ln3[l], st0);
        concat_y_kernel<<<1024, 256, 0, st0>>>(pcat0, y0, O0, ROWS, LDC0);
        gemm_bf16_kernel<<<dim3(MFF / BN, ROWS / BM), 256, GEMM_SMEM, st0>>>(
            pcat0, wr01 + (size_t)l * K0c * MFF, r0_b1 + l * MFF, nullptr, nullptr, pmid0,
            ROWS, MFF, K0c, LDC0, MFF, MFF, 1 | 2);
        gemm_bf16_kernel<<<dim3((O0 + BN - 1) / BN, ROWS / BM), 256, GEMM_SMEM, st0>>>(
            pmid0, wr02 + (size_t)l * MFF * LDW02, r0_b2 + l * O0, y0, y0, nullptr,
            ROWS, O0, MFF, MFF, LDW02, 0, 1 | 4);
        if (l == LAYERS - 1) cudaEventRecord(e_r0, st0);

        // --- stream s1: regressor 1 ---
        cudaStreamWaitEvent(st1, e_x[l], 0);
        ln_kernel<<<ROWS / 4, 128, 0, st1>>>(px, ln4_g + l * D, ln4_b + l * D, pcat1, LDC1);
        cudaEventRecord(e_ln4[l], st1);
        concat_y_kernel<<<1024, 256, 0, st1>>>(pcat1, y1, O1, ROWS, LDC1);
        gemm_bf16_kernel<<<dim3(MFF / BN, ROWS / BM), 256, GEMM_SMEM, st1>>>(
            pcat1, wr11 + (size_t)l * K1c * MFF, r1_b1 + l * MFF, nullptr, nullptr, pmid1,
            ROWS, MFF, K1c, LDC1, MFF, MFF, 1 | 2);
        rowdot3_kernel<<<128, 256, 0, st1>>>(pmid1, r1_W2 + (size_t)l * MFF * O1,
                                             r1_b2 + l * O1, y1);
        if (l == LAYERS - 1) cudaEventRecord(e_r1, st1);
    }

    // join forked streams back into the capture/origin stream
    cudaStreamWaitEvent(0, e_r0, 0);
    cudaStreamWaitEvent(0, e_r1, 0);
}

// round 17
// speedup vs baseline: 8.3965x; 1.0348x over previous
#include <cuda_runtime.h>
#include <cuda_bf16.h>
#include <math.h>
#include <stdint.h>

// Problem constants
#define LAYERS 2
#define D 512
#define H 8
#define DH 64
#define MFF 2048
#define O0 132
#define O1 3
#define BB 2
#define TT 2048
#define ROWS (BB*TT)          // 4096
#define EPS 1e-5f

#define NQKV 1536
#define K0c 644               // D+O0
#define K1c 515               // D+O1
#define LDC0 648              // cat0 stride (mod 8 == 0)
#define LDC1 520              // cat1 stride (mod 8 == 0)
#define LDW02 136             // r0_W2 padded N stride

// ---------------------------------------------------------------------------
// Scratch (device globals; no runtime allocation allowed)
// ---------------------------------------------------------------------------
__device__ float g_x  [ROWS * D];          // residual stream (fp32)

__device__ __nv_bfloat16 gb_qkv [ROWS * NQKV];
__device__ __nv_bfloat16 gb_h   [ROWS * D];
__device__ __nv_bfloat16 gb_o   [ROWS * D];
__device__ __nv_bfloat16 gb_mid [ROWS * MFF];   // FFN hidden (main stream)
__device__ __nv_bfloat16 gb_mid0[ROWS * MFF];   // reg0 hidden (stream s0)
__device__ __nv_bfloat16 gb_mid1[ROWS * MFF];   // reg1 hidden (stream s1)
__device__ __nv_bfloat16 gb_cat0[ROWS * LDC0];
__device__ __nv_bfloat16 gb_cat1[ROWS * LDC1];

__device__ __nv_bfloat16 gb_wqkv[LAYERS * D * NQKV];
__device__ __nv_bfloat16 gb_wout[LAYERS * D * D];
__device__ __nv_bfloat16 gb_wff1[LAYERS * D * MFF];
__device__ __nv_bfloat16 gb_wff2[LAYERS * MFF * D];
__device__ __nv_bfloat16 gb_wr01[LAYERS * K0c * MFF];
__device__ __nv_bfloat16 gb_wr02[LAYERS * MFF * LDW02];
__device__ __nv_bfloat16 gb_wr11[LAYERS * K1c * MFF];

__device__ __forceinline__ uint32_t bf2pack(float lo, float hi) {
    __nv_bfloat162 h = __floats2bfloat162_rn(lo, hi);
    return *reinterpret_cast<uint32_t*>(&h);
}

__device__ __forceinline__ float2 bfunpack(uint32_t u) {
    __nv_bfloat162 h = *reinterpret_cast<__nv_bfloat162*>(&u);
    return __bfloat1622float2(h);
}

__device__ __forceinline__ float ex2f(float x) {
    float y;
    asm("ex2.approx.f32 %0, %1;" : "=f"(y) : "f"(x));
    return y;
}

#define MMA_BF16(acc, a, b0v, b1v)                                          \
    asm volatile(                                                           \
        "mma.sync.aligned.m16n8k16.row.col.f32.bf16.bf16.f32 "              \
        "{%0,%1,%2,%3}, {%4,%5,%6,%7}, {%8,%9}, {%0,%1,%2,%3};"             \
        : "+f"((acc)[0]), "+f"((acc)[1]), "+f"((acc)[2]), "+f"((acc)[3])    \
        : "r"((a)[0]), "r"((a)[1]), "r"((a)[2]), "r"((a)[3]),               \
          "r"(b0v), "r"(b1v))

// ---------------------------------------------------------------------------
// Weight fp32 -> bf16 with padded/zeroed N stride (fast path when no pad)
// ---------------------------------------------------------------------------
__global__ void wconv_kernel(const float* __restrict__ src,
                             __nv_bfloat16* __restrict__ dst,
                             int rows, int N, int ldb)
{
    if (N == ldb && (N & 7) == 0) {
        int total8 = rows * (N >> 3);
        for (int idx = blockIdx.x * blockDim.x + threadIdx.x; idx < total8;
             idx += gridDim.x * blockDim.x) {
            const float4* s = (const float4*)(src + (size_t)idx * 8);
            float4 a = s[0], b2 = s[1];
            uint4 u;
            u.x = bf2pack(a.x, a.y);   u.y = bf2pack(a.z, a.w);
            u.z = bf2pack(b2.x, b2.y); u.w = bf2pack(b2.z, b2.w);
            reinterpret_cast<uint4*>(dst)[idx] = u;
        }
        return;
    }
    int half = ldb >> 1;
    int total = rows * half;
    for (int idx = blockIdx.x * blockDim.x + threadIdx.x; idx < total;
         idx += gridDim.x * blockDim.x) {
        int r = idx / half;
        int c = (idx - r * half) * 2;
        float v0 = (c     < N) ? src[(size_t)r * N + c]     : 0.f;
        float v1 = (c + 1 < N) ? src[(size_t)r * N + c + 1] : 0.f;
        reinterpret_cast<uint32_t*>(dst)[(size_t)r * half + (c >> 1)] = bf2pack(v0, v1);
    }
}

// ---------------------------------------------------------------------------
// LayerNorm: warp per row (4 rows/block), D=512; bf16 output with stride ldo.
// ---------------------------------------------------------------------------
__global__ __launch_bounds__(128) void ln_kernel(const float* __restrict__ x,
                                                 const float* __restrict__ g,
                                                 const float* __restrict__ b,
                                                 __nv_bfloat16* __restrict__ out,
                                                 int ldo)
{
    const int row  = blockIdx.x * 4 + (threadIdx.x >> 5);
    const int lane = threadIdx.x & 31;
    const float4* xr = (const float4*)(x + (size_t)row * D);

    float4 v[4];
    float s = 0.f;
    #pragma unroll
    for (int i = 0; i < 4; i++) {
        v[i] = xr[lane + 32 * i];
        s += v[i].x + v[i].y + v[i].z + v[i].w;
    }
    #pragma unroll
    for (int off = 16; off > 0; off >>= 1)
        s += __shfl_xor_sync(0xffffffff, s, off);
    float mu = s * (1.f / D);

    float var = 0.f;
    #pragma unroll
    for (int i = 0; i < 4; i++) {
        v[i].x -= mu; v[i].y -= mu; v[i].z -= mu; v[i].w -= mu;
        var += v[i].x*v[i].x + v[i].y*v[i].y + v[i].z*v[i].z + v[i].w*v[i].w;
    }
    #pragma unroll
    for (int off = 16; off > 0; off >>= 1)
        var += __shfl_xor_sync(0xffffffff, var, off);
    float inv = rsqrtf(var * (1.f / D) + EPS);

    uint16_t* orow = (uint16_t*)out + (size_t)row * ldo;
    #pragma unroll
    for (int i = 0; i < 4; i++) {
        int e = (lane + 32 * i) * 4;
        const float4 g4 = *(const float4*)(g + e);
        const float4 b4 = *(const float4*)(b + e);
        float o0 = v[i].x * inv * g4.x + b4.x;
        float o1 = v[i].y * inv * g4.y + b4.y;
        float o2 = v[i].z * inv * g4.z + b4.z;
        float o3 = v[i].w * inv * g4.w + b4.w;
        uint2 u; u.x = bf2pack(o0, o1); u.y = bf2pack(o2, o3);
        *(uint2*)(orow + e) = u;
    }
}

// ---------------------------------------------------------------------------
// concat_y: fill columns [D, dstr) of dst with (bf16)y[:, 0:nb] then zero pad
// ---------------------------------------------------------------------------
__global__ void concat_y_kernel(__nv_bfloat16* __restrict__ dst,
                                const float* __restrict__ y, int nb, int rows,
                                int dstr)
{
    int w = dstr - D;
    int total = rows * w;
    for (int idx = blockIdx.x * blockDim.x + threadIdx.x; idx < total;
         idx += gridDim.x * blockDim.x) {
        int r = idx / w, c = idx - r * w;
        dst[(size_t)r * dstr + D + c] =
            (c < nb) ? __float2bfloat16(y[(size_t)r * nb + c])
                     : __float2bfloat16(0.f);
    }
}

// ---------------------------------------------------------------------------
// BF16 tensor-core GEMM, 4-stage cp.async pipeline, 2 CTAs/SM. (verified R13)
// ---------------------------------------------------------------------------
#define BM 128
#define BN 128
#define BKT 32
#define ASTR 40
#define BSTR 136
#define STAGE_BYTES (BM*ASTR*2 + BKT*BSTR*2)
#define A_PART (BM*ASTR*2)
#define NSTAGE 4
#define GEMM_SMEM (NSTAGE*STAGE_BYTES)

__global__ __launch_bounds__(256, 2) void gemm_bf16_kernel(
    const __nv_bfloat16* __restrict__ A, const __nv_bfloat16* __restrict__ B,
    const float* __restrict__ bias, const float* __restrict__ res,
    float* __restrict__ Cf, __nv_bfloat16* __restrict__ Cb,
    int M, int N, int K, int lda, int ldb, int ldcb, int flags)
{
    extern __shared__ __align__(16) uint16_t smem_dyn[];
    const uint32_t sBase = (uint32_t)__cvta_generic_to_shared(smem_dyn);

    const int tid  = threadIdx.x;
    const int lane = tid & 31;
    const int wid  = tid >> 5;
    const int wm   = wid >> 2;
    const int wn   = wid & 3;
    const int lr   = lane >> 2;
    const int lc   = lane & 3;

    const int m0 = blockIdx.y * BM;
    const int n0 = blockIdx.x * BN;

    const int a_r  = (lane & 7) + ((lane >> 3) & 1) * 8;
    const int a_kc = (lane >> 4) * 8;
    const int b_kr = (lane & 7) + ((lane >> 3) & 1) * 8;
    const int b_nc = (lane >> 4) * 8;

    float acc[4][4][4];
    #pragma unroll
    for (int i = 0; i < 4; i++)
        #pragma unroll
        for (int j = 0; j < 4; j++)
            #pragma unroll
            for (int r = 0; r < 4; r++) acc[i][j][r] = 0.f;

    const int nkt = (K + BKT - 1) / BKT;

    auto load_tile = [&](int t, int stage) {
        const int k0 = t * BKT;
        const uint32_t sA = sBase + stage * STAGE_BYTES;
        const uint32_t sB = sA + A_PART;
        #pragma unroll
        for (int i = 0; i < 2; i++) {
            int c   = tid + i * 256;
            int row = c >> 2;
            int col = (c & 3) * 8;
            int gk  = k0 + col;
            int avail = lda - gk;
            int bytes = (avail <= 0) ? 0 : (avail >= 8 ? 16 : avail * 2);
            const __nv_bfloat16* src = bytes ? (A + (size_t)(m0 + row) * lda + gk) : A;
            uint32_t dst = sA + (row * ASTR + col) * 2;
            asm volatile("cp.async.cg.shared.global [%0], [%1], 16, %2;"
                         :: "r"(dst), "l"(src), "r"(bytes));
        }
        #pragma unroll
        for (int i = 0; i < 2; i++) {
            int c   = tid + i * 256;
            int row = c >> 4;
            int col = (c & 15) * 8;
            int gk  = k0 + row;
            int gn  = n0 + col;
            int bytes = (gk < K && gn + 8 <= ldb) ? 16 : 0;
            const __nv_bfloat16* src = bytes ? (B + (size_t)gk * ldb + gn) : B;
            uint32_t dst = sB + (row * BSTR + col) * 2;
            asm volatile("cp.async.cg.shared.global [%0], [%1], 16, %2;"
                         :: "r"(dst), "l"(src), "r"(bytes));
        }
        asm volatile("cp.async.commit_group;");
    };

    #pragma unroll
    for (int s = 0; s < NSTAGE - 1; s++) {
        if (s < nkt) load_tile(s, s);
        else asm volatile("cp.async.commit_group;");
    }

    for (int t = 0; t < nkt; t++) {
        asm volatile("cp.async.wait_group %0;" :: "n"(NSTAGE - 2));
        __syncthreads();
        if (t + NSTAGE - 1 < nkt) load_tile(t + NSTAGE - 1, (t + NSTAGE - 1) & (NSTAGE - 1));
        else asm volatile("cp.async.commit_group;");

        const uint32_t aB = sBase + (t & (NSTAGE - 1)) * STAGE_BYTES;
        const uint32_t bB = aB + A_PART;

        #pragma unroll
        for (int kk = 0; kk < BKT; kk += 16) {
            uint32_t af[4][4];
            #pragma unroll
            for (int mi = 0; mi < 4; mi++) {
                uint32_t addr = aB + ((wm * 64 + mi * 16 + a_r) * ASTR + kk + a_kc) * 2;
                asm volatile(
                    "ldmatrix.sync.aligned.m8n8.x4.shared.b16 {%0,%1,%2,%3}, [%4];"
                    : "=r"(af[mi][0]), "=r"(af[mi][1]),
                      "=r"(af[mi][2]), "=r"(af[mi][3]) : "r"(addr));
            }
            uint32_t bfp[2][4];
            #pragma unroll
            for (int pr = 0; pr < 2; pr++) {
                uint32_t addr = bB + ((kk + b_kr) * BSTR + wn * 32 + pr * 16 + b_nc) * 2;
                asm volatile(
                    "ldmatrix.sync.aligned.m8n8.x4.trans.shared.b16 {%0,%1,%2,%3}, [%4];"
                    : "=r"(bfp[pr][0]), "=r"(bfp[pr][1]),
                      "=r"(bfp[pr][2]), "=r"(bfp[pr][3]) : "r"(addr));
            }
            #pragma unroll
            for (int mi = 0; mi < 4; mi++)
                #pragma unroll
                for (int ni = 0; ni < 4; ni++) {
                    uint32_t b0 = bfp[ni >> 1][(ni & 1) * 2];
                    uint32_t b1 = bfp[ni >> 1][(ni & 1) * 2 + 1];
                    MMA_BF16(acc[mi][ni], af[mi], b0, b1);
                }
        }
        __syncthreads();
    }

    #pragma unroll
    for (int mi = 0; mi < 4; mi++) {
        #pragma unroll
        for (int ni = 0; ni < 4; ni++) {
            int row = m0 + wm * 64 + mi * 16 + lr;
            int col = n0 + wn * 32 + ni * 8 + lc * 2;
            float v[4];
            #pragma unroll
            for (int r = 0; r < 4; r++) {
                int rr = row + (r >> 1) * 8;
                int cc = col + (r & 1);
                float x = acc[mi][ni][r];
                if (cc < N) {
                    if (flags & 1) x += bias[cc];
                    if (flags & 2) x = 0.5f * x * (1.f + erff(x * 0.70710678118654752f));
                    if (flags & 4) x += res[(size_t)rr * N + cc];
                    if (Cf) Cf[(size_t)rr * N + cc] = x;
                }
                v[r] = x;
            }
            if (Cb && col + 2 <= N) {
                reinterpret_cast<uint32_t*>(Cb)[((size_t)row * ldcb + col) >> 1]       = bf2pack(v[0], v[1]);
                reinterpret_cast<uint32_t*>(Cb)[((size_t)(row + 8) * ldcb + col) >> 1] = bf2pack(v[2], v[3]);
            }
        }
    }
}

// ---------------------------------------------------------------------------
// rowdot3: y[r,0..2] += A[r,:] @ W[:,0..2] + bias   (N=3, K=2048)
// ---------------------------------------------------------------------------
__global__ __launch_bounds__(256) void rowdot3_kernel(
    const __nv_bfloat16* __restrict__ A, const float* __restrict__ W,
    const float* __restrict__ bias, float* __restrict__ y)
{
    __shared__ uint16_t Ws[3][MFF];
    const int tid  = threadIdx.x;
    const int lane = tid & 31;
    const int w    = tid >> 5;

    for (int i = tid; i < 3 * MFF; i += 256) {
        int c = i / MFF, k = i - c * MFF;
        __nv_bfloat16 hv = __float2bfloat16(W[(size_t)k * O1 + c]);
        Ws[c][k] = *reinterpret_cast<const uint16_t*>(&hv);
    }
    __syncthreads();

    const float b0 = bias[0], b1 = bias[1], b2 = bias[2];
    #pragma unroll
    for (int r = 0; r < 4; r++) {
        int row = blockIdx.x * 32 + w * 4 + r;
        const uint4* arow = (const uint4*)(A + (size_t)row * MFF);
        float a0 = 0.f, a1 = 0.f, a2 = 0.f;
        #pragma unroll
        for (int i = 0; i < MFF / 8 / 32; i++) {
            int idx = lane + i * 32;
            uint4 av = arow[idx];
            uint4 w0 = ((const uint4*)Ws[0])[idx];
            uint4 w1 = ((const uint4*)Ws[1])[idx];
            uint4 w2 = ((const uint4*)Ws[2])[idx];
            const uint32_t* ap = (const uint32_t*)&av;
            const uint32_t* p0 = (const uint32_t*)&w0;
            const uint32_t* p1 = (const uint32_t*)&w1;
            const uint32_t* p2 = (const uint32_t*)&w2;
            #pragma unroll
            for (int j = 0; j < 4; j++) {
                float2 a = bfunpack(ap[j]);
                float2 f0 = bfunpack(p0[j]);
                float2 f1 = bfunpack(p1[j]);
                float2 f2 = bfunpack(p2[j]);
                a0 = fmaf(a.x, f0.x, fmaf(a.y, f0.y, a0));
                a1 = fmaf(a.x, f1.x, fmaf(a.y, f1.y, a1));
                a2 = fmaf(a.x, f2.x, fmaf(a.y, f2.y, a2));
            }
        }
        #pragma unroll
        for (int off = 16; off > 0; off >>= 1) {
            a0 += __shfl_xor_sync(0xffffffff, a0, off);
            a1 += __shfl_xor_sync(0xffffffff, a1, off);
            a2 += __shfl_xor_sync(0xffffffff, a2, off);
        }
        if (lane == 0) {
            float* yr = y + (size_t)row * O1;
            yr[0] += a0 + b0;
            yr[1] += a1 + b1;
            yr[2] += a2 + b2;
        }
    }
}

// ---------------------------------------------------------------------------
// Tensor-core flash attention (verified Round 9)
// ---------------------------------------------------------------------------
#define KSTR 72
#define KV_ST_BYTES (64*KSTR*2)

__global__ __launch_bounds__(256) void attn_kernel(
    const __nv_bfloat16* __restrict__ qkv, __nv_bfloat16* __restrict__ out)
{
    __shared__ __align__(16) uint16_t Ks[2][64][KSTR];
    __shared__ __align__(16) uint16_t Vs[2][64][KSTR];

    const int tid  = threadIdx.x;
    const int lane = tid & 31;
    const int w    = tid >> 5;
    const int gid  = lane >> 2;
    const int tq   = lane & 3;
    const int qb   = blockIdx.x * 128;
    const int b    = blockIdx.y >> 3;
    const int h    = blockIdx.y & 7;

    uint32_t qf[4][4];
    {
        const uint16_t* q0 = (const uint16_t*)qkv +
            (size_t)(b * TT + qb + w * 16 + gid) * NQKV + h * DH;
        const uint16_t* q1 = q0 + (size_t)8 * NQKV;
        #pragma unroll
        for (int ks = 0; ks < 4; ks++) {
            qf[ks][0] = *(const uint32_t*)(q0 + ks * 16 + tq * 2);
            qf[ks][1] = *(const uint32_t*)(q1 + ks * 16 + tq * 2);
            qf[ks][2] = *(const uint32_t*)(q0 + ks * 16 + 8 + tq * 2);
            qf[ks][3] = *(const uint32_t*)(q1 + ks * 16 + 8 + tq * 2);
        }
    }

    const uint32_t kBase = (uint32_t)__cvta_generic_to_shared(&Ks[0][0][0]);
    const uint32_t vBase = (uint32_t)__cvta_generic_to_shared(&Vs[0][0][0]);

    float oacc[8][4];
    #pragma unroll
    for (int i = 0; i < 8; i++)
        #pragma unroll
        for (int j = 0; j < 4; j++) oacc[i][j] = 0.f;
    float m0 = -1e30f, m1 = -1e30f, l0 = 0.f, l1 = 0.f;

    auto load_kv = [&](int t, int buf) {
        #pragma unroll
        for (int i = 0; i < 2; i++) {
            int idx = tid + i * 256;
            int row = idx >> 3;
            int ch  = (idx & 7) * 8;
            const uint16_t* src = (const uint16_t*)qkv +
                (size_t)(b * TT + t * 64 + row) * NQKV + h * DH + ch;
            uint32_t kd = kBase + buf * KV_ST_BYTES + (row * KSTR + ch) * 2;
            uint32_t vd = vBase + buf * KV_ST_BYTES + (row * KSTR + ch) * 2;
            asm volatile("cp.async.cg.shared.global [%0], [%1], 16;"
                         :: "r"(kd), "l"(src + 512) : "memory");
            asm volatile("cp.async.cg.shared.global [%0], [%1], 16;"
                         :: "r"(vd), "l"(src + 1024) : "memory");
        }
        asm volatile("cp.async.commit_group;");
    };

    load_kv(0, 0);

    const float sc = 0.125f * 1.4426950408889634f;

    for (int t = 0; t < TT / 64; t++) {
        asm volatile("cp.async.wait_group 0;");
        __syncthreads();
        if (t + 1 < TT / 64) load_kv(t + 1, (t + 1) & 1);

        const uint32_t kB = kBase + (t & 1) * KV_ST_BYTES;
        const uint32_t vB = vBase + (t & 1) * KV_ST_BYTES;

        float sacc[8][4];
        #pragma unroll
        for (int i = 0; i < 8; i++)
            #pragma unroll
            for (int j = 0; j < 4; j++) sacc[i][j] = 0.f;

        #pragma unroll
        for (int np = 0; np < 4; np++) {
            #pragma unroll
            for (int ks = 0; ks < 4; ks++) {
                uint32_t kb[4];
                uint32_t addr = kB +
                    ((np * 16 + (lane & 7) + ((lane >> 4) & 1) * 8) * KSTR +
                     ks * 16 + ((lane >> 3) & 1) * 8) * 2;
                asm volatile(
                    "ldmatrix.sync.aligned.m8n8.x4.shared.b16 {%0,%1,%2,%3}, [%4];"
                    : "=r"(kb[0]), "=r"(kb[1]), "=r"(kb[2]), "=r"(kb[3]) : "r"(addr));
                MMA_BF16(sacc[np * 2],     qf[ks], kb[0], kb[1]);
                MMA_BF16(sacc[np * 2 + 1], qf[ks], kb[2], kb[3]);
            }
        }

        float mx0 = -1e30f, mx1 = -1e30f;
        #pragma unroll
        for (int ni = 0; ni < 8; ni++) {
            sacc[ni][0] *= sc; sacc[ni][1] *= sc;
            sacc[ni][2] *= sc; sacc[ni][3] *= sc;
            mx0 = fmaxf(mx0, fmaxf(sacc[ni][0], sacc[ni][1]));
            mx1 = fmaxf(mx1, fmaxf(sacc[ni][2], sacc[ni][3]));
        }
        mx0 = fmaxf(mx0, __shfl_xor_sync(0xffffffff, mx0, 1));
        mx0 = fmaxf(mx0, __shfl_xor_sync(0xffffffff, mx0, 2));
        mx1 = fmaxf(mx1, __shfl_xor_sync(0xffffffff, mx1, 1));
        mx1 = fmaxf(mx1, __shfl_xor_sync(0xffffffff, mx1, 2));

        float m0n = fmaxf(m0, mx0), m1n = fmaxf(m1, mx1);
        float c0 = ex2f(m0 - m0n), c1 = ex2f(m1 - m1n);
        float s0 = 0.f, s1 = 0.f;
        #pragma unroll
        for (int ni = 0; ni < 8; ni++) {
            float p0 = ex2f(sacc[ni][0] - m0n);
            float p1 = ex2f(sacc[ni][1] - m0n);
            float p2 = ex2f(sacc[ni][2] - m1n);
            float p3 = ex2f(sacc[ni][3] - m1n);
            sacc[ni][0] = p0; sacc[ni][1] = p1;
            sacc[ni][2] = p2; sacc[ni][3] = p3;
            s0 += p0 + p1; s1 += p2 + p3;
        }
        s0 += __shfl_xor_sync(0xffffffff, s0, 1);
        s0 += __shfl_xor_sync(0xffffffff, s0, 2);
        s1 += __shfl_xor_sync(0xffffffff, s1, 1);
        s1 += __shfl_xor_sync(0xffffffff, s1, 2);
        l0 = l0 * c0 + s0;
        l1 = l1 * c1 + s1;
        m0 = m0n; m1 = m1n;
        #pragma unroll
        for (int nj = 0; nj < 8; nj++) {
            oacc[nj][0] *= c0; oacc[nj][1] *= c0;
            oacc[nj][2] *= c1; oacc[nj][3] *= c1;
        }

        uint32_t aP[4][4];
        #pragma unroll
        for (int ks = 0; ks < 4; ks++) {
            aP[ks][0] = bf2pack(sacc[2*ks][0],     sacc[2*ks][1]);
            aP[ks][1] = bf2pack(sacc[2*ks][2],     sacc[2*ks][3]);
            aP[ks][2] = bf2pack(sacc[2*ks + 1][0], sacc[2*ks + 1][1]);
            aP[ks][3] = bf2pack(sacc[2*ks + 1][2], sacc[2*ks + 1][3]);
        }

        #pragma unroll
        for (int np = 0; np < 4; np++) {
            #pragma unroll
            for (int ks = 0; ks < 4; ks++) {
                uint32_t vb[4];
                uint32_t addr = vB +
                    ((ks * 16 + (lane & 7) + ((lane >> 3) & 1) * 8) * KSTR +
                     np * 16 + ((lane >> 4) & 1) * 8) * 2;
                asm volatile(
                    "ldmatrix.sync.aligned.m8n8.x4.trans.shared.b16 {%0,%1,%2,%3}, [%4];"
                    : "=r"(vb[0]), "=r"(vb[1]), "=r"(vb[2]), "=r"(vb[3]) : "r"(addr));
                MMA_BF16(oacc[np * 2],     aP[ks], vb[0], vb[1]);
                MMA_BF16(oacc[np * 2 + 1], aP[ks], vb[2], vb[3]);
            }
        }
    }

    float i0 = 1.f / l0, i1 = 1.f / l1;
    uint16_t* o0 = (uint16_t*)out + (size_t)(b * TT + qb + w * 16 + gid) * D + h * DH;
    uint16_t* o1 = o0 + (size_t)8 * D;
    #pragma unroll
    for (int nj = 0; nj < 8; nj++) {
        *(uint32_t*)(o0 + nj * 8 + tq * 2) = bf2pack(oacc[nj][0] * i0, oacc[nj][1] * i0);
        *(uint32_t*)(o1 + nj * 8 + tq * 2) = bf2pack(oacc[nj][2] * i1, oacc[nj][3] * i1);
    }
}

// ---------------------------------------------------------------------------
// launch — main stream: attn+FFN chain; st0/st1 (forked via e_fork): regressor
// chains + deferred weight conversion, overlapped behind layer-0 qkv+attention.
// ---------------------------------------------------------------------------
extern "C" void kernel_launch(void* const* d_in, const int* in_sizes, int n_in,
                              void* d_out, int out_size)
{
    (void)in_sizes; (void)n_in; (void)out_size;

    const float* in_x     = (const float*)d_in[0];
    const float* in_init0 = (const float*)d_in[1];
    const float* in_init1 = (const float*)d_in[2];
    // d_in[3] = mask: constant all-True -> unused
    const float* ln1_g = (const float*)d_in[4];
    const float* ln1_b = (const float*)d_in[5];
    const float* qkv_W = (const float*)d_in[6];
    const float* out_W = (const float*)d_in[7];
    const float* out_b = (const float*)d_in[8];
    const float* ln2_g = (const float*)d_in[9];
    const float* ln2_b = (const float*)d_in[10];
    const float* ff_W1 = (const float*)d_in[11];
    const float* ff_b1 = (const float*)d_in[12];
    const float* ff_W2 = (const float*)d_in[13];
    const float* ff_b2 = (const float*)d_in[14];
    const float* ln3_g = (const float*)d_in[15];
    const float* ln3_b = (const float*)d_in[16];
    const float* r0_W1 = (const float*)d_in[17];
    const float* r0_b1 = (const float*)d_in[18];
    const float* r0_W2 = (const float*)d_in[19];
    const float* r0_b2 = (const float*)d_in[20];
    const float* ln4_g = (const float*)d_in[21];
    const float* ln4_b = (const float*)d_in[22];
    const float* r1_W1 = (const float*)d_in[23];
    const float* r1_b1 = (const float*)d_in[24];
    const float* r1_W2 = (const float*)d_in[25];
    const float* r1_b2 = (const float*)d_in[26];

    static bool init_done = false;
    static cudaStream_t st0, st1;
    static cudaEvent_t e_fork, e_wc, e_x[LAYERS], e_ln3[LAYERS], e_ln4[LAYERS], e_r0, e_r1;
    if (!init_done) {
        cudaFuncSetAttribute(gemm_bf16_kernel,
                             cudaFuncAttributeMaxDynamicSharedMemorySize, GEMM_SMEM);
        cudaStreamCreateWithFlags(&st0, cudaStreamNonBlocking);
        cudaStreamCreateWithFlags(&st1, cudaStreamNonBlocking);
        cudaEventCreateWithFlags(&e_fork, cudaEventDisableTiming);
        cudaEventCreateWithFlags(&e_wc,   cudaEventDisableTiming);
        for (int l = 0; l < LAYERS; l++) {
            cudaEventCreateWithFlags(&e_x[l],   cudaEventDisableTiming);
            cudaEventCreateWithFlags(&e_ln3[l], cudaEventDisableTiming);
            cudaEventCreateWithFlags(&e_ln4[l], cudaEventDisableTiming);
        }
        cudaEventCreateWithFlags(&e_r0, cudaEventDisableTiming);
        cudaEventCreateWithFlags(&e_r1, cudaEventDisableTiming);
        init_done = true;
    }

    float *px;
    __nv_bfloat16 *pqkv, *ph, *po, *pmid, *pmid0, *pmid1, *pcat0, *pcat1;
    __nv_bfloat16 *wqkv, *wout, *wff1, *wff2, *wr01, *wr02, *wr11;
    cudaGetSymbolAddress((void**)&px,    g_x);
    cudaGetSymbolAddress((void**)&pqkv,  gb_qkv);
    cudaGetSymbolAddress((void**)&ph,    gb_h);
    cudaGetSymbolAddress((void**)&po,    gb_o);
    cudaGetSymbolAddress((void**)&pmid,  gb_mid);
    cudaGetSymbolAddress((void**)&pmid0, gb_mid0);
    cudaGetSymbolAddress((void**)&pmid1, gb_mid1);
    cudaGetSymbolAddress((void**)&pcat0, gb_cat0);
    cudaGetSymbolAddress((void**)&pcat1, gb_cat1);
    cudaGetSymbolAddress((void**)&wqkv,  gb_wqkv);
    cudaGetSymbolAddress((void**)&wout,  gb_wout);
    cudaGetSymbolAddress((void**)&wff1,  gb_wff1);
    cudaGetSymbolAddress((void**)&wff2,  gb_wff2);
    cudaGetSymbolAddress((void**)&wr01,  gb_wr01);
    cudaGetSymbolAddress((void**)&wr02,  gb_wr02);
    cudaGetSymbolAddress((void**)&wr11,  gb_wr11);

    float* y0 = (float*)d_out;                 // [ROWS, O0]
    float* y1 = (float*)d_out + ROWS * O0;     // [ROWS, O1]

    // main stream: x copy + the one weight needed immediately (qkv).
    // Record the fork event FIRST so side streams join the capture legally.
    cudaMemcpyAsync(px, in_x, (size_t)ROWS * D * sizeof(float),
                    cudaMemcpyDeviceToDevice, 0);
    cudaEventRecord(e_fork, 0);
    wconv_kernel<<<1024, 256>>>(qkv_W, wqkv, LAYERS * D, NQKV, NQKV);

    // st0 (forked): remaining weight conversions + y0 init
    cudaStreamWaitEvent(st0, e_fork, 0);
    wconv_kernel<<<512, 256, 0, st0>>>(out_W, wout, LAYERS * D,   D,    D);
    wconv_kernel<<<512, 256, 0, st0>>>(ff_W1, wff1, LAYERS * D,   MFF,  MFF);
    wconv_kernel<<<512, 256, 0, st0>>>(ff_W2, wff2, LAYERS * MFF, D,    D);
    wconv_kernel<<<512, 256, 0, st0>>>(r0_W1, wr01, LAYERS * K0c, MFF,  MFF);
    wconv_kernel<<<512, 256, 0, st0>>>(r0_W2, wr02, LAYERS * MFF, O0,   LDW02);
    wconv_kernel<<<512, 256, 0, st0>>>(r1_W1, wr11, LAYERS * K1c, MFF,  MFF);
    cudaEventRecord(e_wc, st0);
    cudaMemcpyAsync(y0, in_init0, (size_t)ROWS * O0 * sizeof(float),
                    cudaMemcpyDeviceToDevice, st0);
    // st1 (forked): y1 init; wait for weights it will use later
    cudaStreamWaitEvent(st1, e_fork, 0);
    cudaMemcpyAsync(y1, in_init1, (size_t)ROWS * O1 * sizeof(float),
                    cudaMemcpyDeviceToDevice, st1);
    cudaStreamWaitEvent(st1, e_wc, 0);

    for (int l = 0; l < LAYERS; l++) {
        // --- main stream: attention block ---
        ln_kernel<<<ROWS / 4, 128>>>(px, ln1_g + l * D, ln1_b + l * D, ph, D);
        gemm_bf16_kernel<<<dim3(NQKV / BN, ROWS / BM), 256, GEMM_SMEM>>>(
            ph, wqkv + (size_t)l * D * NQKV, nullptr, nullptr, nullptr, pqkv,
            ROWS, NQKV, D, D, NQKV, NQKV, 0);
        attn_kernel<<<dim3(TT / 128, BB * H), 256>>>(pqkv, po);
        if (l == 0) {
            cudaStreamWaitEvent(0, e_wc, 0);   // wout (and later weights) ready
        } else {                               // out-proj writes x: wait last readers
            cudaStreamWaitEvent(0, e_ln3[l - 1], 0);
            cudaStreamWaitEvent(0, e_ln4[l - 1], 0);
        }
        gemm_bf16_kernel<<<dim3(D / BN, ROWS / BM), 256, GEMM_SMEM>>>(
            po, wout + (size_t)l * D * D, out_b + l * D, px, px, nullptr,
            ROWS, D, D, D, D, 0, 1 | 4);

        // --- main stream: FFN block ---
        ln_kernel<<<ROWS / 4, 128>>>(px, ln2_g + l * D, ln2_b + l * D, ph, D);
        gemm_bf16_kernel<<<dim3(MFF / BN, ROWS / BM), 256, GEMM_SMEM>>>(
            ph, wff1 + (size_t)l * D * MFF, ff_b1 + l * MFF, nullptr, nullptr, pmid,
            ROWS, MFF, D, D, MFF, MFF, 1 | 2);
        gemm_bf16_kernel<<<dim3(D / BN, ROWS / BM), 256, GEMM_SMEM>>>(
            pmid, wff2 + (size_t)l * MFF * D, ff_b2 + l * D, px, px, nullptr,
            ROWS, D, MFF, MFF, D, 0, 1 | 4);
        cudaEventRecord(e_x[l], 0);

        // --- stream s0: regressor 0 ---
        cudaStreamWaitEvent(st0, e_x[l], 0);
        ln_kernel<<<ROWS / 4, 128, 0, st0>>>(px, ln3_g + l * D, ln3_b + l * D, pcat0, LDC0);
        cudaEventRecord(e_ln3[l], st0);
        concat_y_kernel<<<1024, 256, 0, st0>>>(pcat0, y0, O0, ROWS, LDC0);
        gemm_bf16_kernel<<<dim3(MFF / BN, ROWS / BM), 256, GEMM_SMEM, st0>>>(
            pcat0, wr01 + (size_t)l * K0c * MFF, r0_b1 + l * MFF, nullptr, nullptr, pmid0,
            ROWS, MFF, K0c, LDC0, MFF, MFF, 1 | 2);
        gemm_bf16_kernel<<<dim3((O0 + BN - 1) / BN, ROWS / BM), 256, GEMM_SMEM, st0>>>(
            pmid0, wr02 + (size_t)l * MFF * LDW02, r0_b2 + l * O0, y0, y0, nullptr,
            ROWS, O0, MFF, MFF, LDW02, 0, 1 | 4);
        if (l == LAYERS - 1) cudaEventRecord(e_r0, st0);

        // --- stream s1: regressor 1 ---
        cudaStreamWaitEvent(st1, e_x[l], 0);
        ln_kernel<<<ROWS / 4, 128, 0, st1>>>(px, ln4_g + l * D, ln4_b + l * D, pcat1, LDC1);
        cudaEventRecord(e_ln4[l], st1);
        concat_y_kernel<<<1024, 256, 0, st1>>>(pcat1, y1, O1, ROWS, LDC1);
        gemm_bf16_kernel<<<dim3(MFF / BN, ROWS / BM), 256, GEMM_SMEM, st1>>>(
            pcat1, wr11 + (size_t)l * K1c * MFF, r1_b1 + l * MFF, nullptr, nullptr, pmid1,
            ROWS, MFF, K1c, LDC1, MFF, MFF, 1 | 2);
        rowdot3_kernel<<<128, 256, 0, st1>>>(pmid1, r1_W2 + (size_t)l * MFF * O1,
                                             r1_b2 + l * O1, y1);
        if (l == LAYERS - 1) cudaEventRecord(e_r1, st1);
    }

    // join forked streams back into the capture/origin stream
    cudaStreamWaitEvent(0, e_r0, 0);
    cudaStreamWaitEvent(0, e_r1, 0);
}